// round 8
// baseline (speedup 1.0000x reference)
#include <cuda_runtime.h>
#include <cuda_bf16.h>
#include <cstdint>

#define B_   32
#define D_   128
#define LC_  2048
#define LQ_  512

typedef unsigned int u32;

// ---------------- scratch planes (bf16 hi/lo stored as u32 pairs) ----------
__device__ u32 g_Ehi[(size_t)B_ * LC_ * LQ_ / 2];
__device__ u32 g_Elo[(size_t)B_ * LC_ * LQ_ / 2];
__device__ u32 g_Cwhi[(size_t)B_ * D_ * LC_ / 2];
__device__ u32 g_Cwlo[(size_t)B_ * D_ * LC_ / 2];
__device__ u32 g_Cmhi[(size_t)B_ * D_ * LC_ / 2];
__device__ u32 g_Cmlo[(size_t)B_ * D_ * LC_ / 2];
__device__ u32 g_Qhi[(size_t)B_ * D_ * LQ_ / 2];
__device__ u32 g_Qlo[(size_t)B_ * D_ * LQ_ / 2];
__device__ u32 g_Thi[(size_t)B_ * LQ_ * D_ / 2];
__device__ u32 g_Tlo[(size_t)B_ * LQ_ * D_ / 2];
__device__ float g_s0[B_ * LC_];
__device__ float g_s1[B_ * LQ_];
__device__ float g_Z1p[B_ * LC_ * 4];
__device__ float g_Z2p[B_ * LQ_ * 16];

// ---------------- helpers ----------------
__device__ __forceinline__ u32 s2u(const void* p) {
    u32 a; asm("{ .reg .u64 t; cvta.to.shared.u64 t, %1; cvt.u32.u64 %0, t; }" : "=r"(a) : "l"(p));
    return a;
}
#define SWZ(x) ((u32)(x) ^ ((((u32)(x)) >> 3) & 0x70))

__device__ __forceinline__ void cpa16(u32 dst, const void* src) {
    asm volatile("cp.async.cg.shared.global [%0], [%1], 16;" :: "r"(dst), "l"(src));
}
#define CP_COMMIT() asm volatile("cp.async.commit_group;")
#define CP_WAIT0()  asm volatile("cp.async.wait_group 0;")
#define CP_WAIT1()  asm volatile("cp.async.wait_group 1;")

__device__ __forceinline__ void splt(float v, u32 &hi, u32 &lo) {
    __nv_bfloat16 h = __float2bfloat16(v);
    float hf = __bfloat162float(h);
    __nv_bfloat16 l = __float2bfloat16(v - hf);
    hi = (u32)__bfloat16_as_ushort(h);
    lo = (u32)__bfloat16_as_ushort(l);
}

__device__ __forceinline__ void ldsm4(u32 addr, u32 r[4]) {
    asm volatile("ldmatrix.sync.aligned.m8n8.x4.shared.b16 {%0,%1,%2,%3}, [%4];"
                 : "=r"(r[0]), "=r"(r[1]), "=r"(r[2]), "=r"(r[3]) : "r"(addr));
}
__device__ __forceinline__ void ldsm4t(u32 addr, u32 r[4]) {
    asm volatile("ldmatrix.sync.aligned.m8n8.x4.trans.shared.b16 {%0,%1,%2,%3}, [%4];"
                 : "=r"(r[0]), "=r"(r[1]), "=r"(r[2]), "=r"(r[3]) : "r"(addr));
}
__device__ __forceinline__ void hmma(float d[4], const u32 a[4], u32 b0, u32 b1) {
    asm volatile("mma.sync.aligned.m16n8k16.row.col.f32.bf16.bf16.f32 "
                 "{%0,%1,%2,%3}, {%4,%5,%6,%7}, {%8,%9}, {%0,%1,%2,%3};"
                 : "+f"(d[0]), "+f"(d[1]), "+f"(d[2]), "+f"(d[3])
                 : "r"(a[0]), "r"(a[1]), "r"(a[2]), "r"(a[3]), "r"(b0), "r"(b1));
}
__device__ __forceinline__ uint4 lds128(u32 a) {
    uint4 v;
    asm volatile("ld.shared.v4.b32 {%0,%1,%2,%3}, [%4];"
                 : "=r"(v.x), "=r"(v.y), "=r"(v.z), "=r"(v.w) : "r"(a));
    return v;
}
__device__ __forceinline__ void sts32(u32 a, u32 v) { asm volatile("st.shared.b32 [%0], %1;" :: "r"(a), "r"(v)); }

// ---------------- chunk copy (pure cp.async, 64KB per chunk) --------------
__device__ __forceinline__ void cpyR64(u32 dstBase, const __nv_bfloat16* srcHi,
                                       const __nv_bfloat16* srcLo, size_t rowStride, int tid) {
    #pragma unroll
    for (int t = 0; t < 8; t++) {
        int u = tid + t * 256;
        int limb = u >> 10, rem = u & 1023;
        int row = rem >> 4, ucol = rem & 15;
        const __nv_bfloat16* src = (limb ? srcLo : srcHi) + (size_t)row * rowStride + ucol * 8;
        u32 dst = dstBase + limb * 16384 + (ucol >> 3) * 8192 + SWZ(row * 128 + (ucol & 7) * 16);
        cpa16(dst, src);
    }
}
__device__ __forceinline__ void cpyR128(u32 dstBase, const __nv_bfloat16* srcHi,
                                        const __nv_bfloat16* srcLo, size_t rowStride, int tid) {
    #pragma unroll
    for (int t = 0; t < 8; t++) {
        int u = tid + t * 256;
        int limb = u >> 10, rem = u & 1023;
        int row = rem >> 3, ucol = rem & 7;
        const __nv_bfloat16* src = (limb ? srcLo : srcHi) + (size_t)row * rowStride + ucol * 8;
        u32 dst = dstBase + limb * 16384 + SWZ(row * 128 + ucol * 16);
        cpa16(dst, src);
    }
}

// ---------------- warp MMA over one k=64 chunk (3-limb) -------------------
template<int AT, int BT>
__device__ __forceinline__ void mma_chunk(float acc[4][4][4], u32 Ab, u32 Bb,
                                          int m0w, int n0w, int lane) {
    #pragma unroll
    for (int ks = 0; ks < 4; ks++) {
        int k0 = ks * 16;
        u32 ah[4][4], al[4][4];
        #pragma unroll
        for (int mi = 0; mi < 4; mi++) {
            int m0 = m0w + mi * 16;
            u32 ad;
            if (AT) {
                int r = k0 + (lane & 7) + ((lane & 16) ? 8 : 0);
                int c = m0 + ((lane & 8) ? 8 : 0);
                ad = Ab + ((u32)(c >> 6)) * 8192 + SWZ(r * 128 + (c & 63) * 2);
                ldsm4t(ad, ah[mi]); ldsm4t(ad + 16384, al[mi]);
            } else {
                int r = m0 + (lane & 15);
                int c = k0 + ((lane >> 4) << 3);
                ad = Ab + SWZ(r * 128 + c * 2);
                ldsm4(ad, ah[mi]); ldsm4(ad + 16384, al[mi]);
            }
        }
        u32 bh[4][2], bl[4][2];
        #pragma unroll
        for (int nj2 = 0; nj2 < 2; nj2++) {
            int n0 = n0w + nj2 * 16;
            u32 bd;
            u32 t[4], tl[4];
            if (BT) {
                int r = k0 + (lane & 7) + ((lane & 8) ? 8 : 0);
                int c = n0 + ((lane & 16) ? 8 : 0);
                bd = Bb + ((u32)(c >> 6)) * 8192 + SWZ(r * 128 + (c & 63) * 2);
                ldsm4t(bd, t); ldsm4t(bd + 16384, tl);
            } else {
                int r = n0 + (lane & 7) + ((lane & 16) ? 8 : 0);
                int c = k0 + ((lane & 8) ? 8 : 0);
                bd = Bb + SWZ(r * 128 + c * 2);
                ldsm4(bd, t); ldsm4(bd + 16384, tl);
            }
            bh[nj2 * 2][0] = t[0];  bh[nj2 * 2][1] = t[1];
            bh[nj2 * 2 + 1][0] = t[2]; bh[nj2 * 2 + 1][1] = t[3];
            bl[nj2 * 2][0] = tl[0]; bl[nj2 * 2][1] = tl[1];
            bl[nj2 * 2 + 1][0] = tl[2]; bl[nj2 * 2 + 1][1] = tl[3];
        }
        #pragma unroll
        for (int mi = 0; mi < 4; mi++)
            #pragma unroll
            for (int nj = 0; nj < 4; nj++) {
                hmma(acc[mi][nj], ah[mi], bh[nj][0], bh[nj][1]);
                hmma(acc[mi][nj], ah[mi], bl[nj][0], bl[nj][1]);
                hmma(acc[mi][nj], al[mi], bh[nj][0], bh[nj][1]);
            }
    }
}

// =====================================================================
// k_cvtC / k_cvtQ / k_vec: preprocessing
// =====================================================================
__global__ void k_cvtC(const float* __restrict__ C, const int* __restrict__ Cmask,
                       const float* __restrict__ w_mul) {
    size_t idx = (size_t)blockIdx.x * 256 + threadIdx.x;
    size_t g4 = idx * 4;
    int c = (int)(g4 & (LC_ - 1));
    int d = (int)((g4 >> 11) & (D_ - 1));
    int b = (int)(g4 >> 18);
    float4 v = *(const float4*)(C + g4);
    int4 m = *(const int4*)(Cmask + b * LC_ + c);
    float w = w_mul[d];
    u32 h[4], l[4];
    splt(v.x * w, h[0], l[0]); splt(v.y * w, h[1], l[1]);
    splt(v.z * w, h[2], l[2]); splt(v.w * w, h[3], l[3]);
    ((uint2*)g_Cwhi)[idx] = make_uint2(h[0] | (h[1] << 16), h[2] | (h[3] << 16));
    ((uint2*)g_Cwlo)[idx] = make_uint2(l[0] | (l[1] << 16), l[2] | (l[3] << 16));
    splt(m.x ? v.x : 0.f, h[0], l[0]); splt(m.y ? v.y : 0.f, h[1], l[1]);
    splt(m.z ? v.z : 0.f, h[2], l[2]); splt(m.w ? v.w : 0.f, h[3], l[3]);
    ((uint2*)g_Cmhi)[idx] = make_uint2(h[0] | (h[1] << 16), h[2] | (h[3] << 16));
    ((uint2*)g_Cmlo)[idx] = make_uint2(l[0] | (l[1] << 16), l[2] | (l[3] << 16));
}

__global__ void k_cvtQ(const float* __restrict__ Q) {
    size_t idx = (size_t)blockIdx.x * 256 + threadIdx.x;
    float4 v = *(const float4*)(Q + idx * 4);
    u32 h[4], l[4];
    splt(v.x, h[0], l[0]); splt(v.y, h[1], l[1]);
    splt(v.z, h[2], l[2]); splt(v.w, h[3], l[3]);
    ((uint2*)g_Qhi)[idx] = make_uint2(h[0] | (h[1] << 16), h[2] | (h[3] << 16));
    ((uint2*)g_Qlo)[idx] = make_uint2(l[0] | (l[1] << 16), l[2] | (l[3] << 16));
}

__global__ void k_vec(const float* __restrict__ C, const float* __restrict__ Q,
                      const float* __restrict__ w_c, const float* __restrict__ w_q,
                      const float* __restrict__ bias) {
    __shared__ float w[128];
    int t = threadIdx.x;
    bool isQ = blockIdx.x >= 256;
    const float* W = isQ ? w_q : w_c;
    if (t < 128) w[t] = W[t];
    __syncthreads();
    if (!isQ) {
        int idx = blockIdx.x * 256 + t;
        int b = idx >> 11, c = idx & (LC_ - 1);
        const float* base = C + (size_t)b * D_ * LC_ + c;
        float acc = bias[0];
        #pragma unroll 8
        for (int dd = 0; dd < 128; dd++) acc += base[dd * LC_] * w[dd];
        g_s0[idx] = acc;
    } else {
        int idx = (blockIdx.x - 256) * 256 + t;
        int b = idx >> 9, q = idx & (LQ_ - 1);
        const float* base = Q + (size_t)b * D_ * LQ_ + q;
        float acc = 0.f;
        #pragma unroll 8
        for (int dd = 0; dd < 128; dd++) acc += base[dd * LQ_] * w[dd];
        g_s1[idx] = acc;
    }
}

// =====================================================================
// k_S: E = qmask*exp(Cw@Qt^T + s0 + s1); Z1/Z2 partials; smem-staged E store
// =====================================================================
#define KS_S0 0
#define KS_S1 512
#define KS_QM 1024
#define KS_CM 1536
#define KS_ZS 2048
#define KS_ZC 4096
#define KS_BUF 8192
#define KS_DYN 139264

__global__ void __launch_bounds__(256, 1) k_S(const int* __restrict__ Qmask,
                                              const int* __restrict__ Cmask) {
    extern __shared__ char sm[];
    u32 sb = s2u(sm);
    int tid = threadIdx.x, lane = tid & 31, wid = tid >> 5;
    int b = blockIdx.z, cB = blockIdx.y * 128, qB = blockIdx.x * 128, qt = blockIdx.x;
    float* s0f = (float*)(sm + KS_S0);
    float* s1f = (float*)(sm + KS_S1);
    int*   qmi = (int*)(sm + KS_QM);
    float* cmk = (float*)(sm + KS_CM);
    float* zs  = (float*)(sm + KS_ZS);
    float* zc  = (float*)(sm + KS_ZC);
    if (tid < 128) {
        s0f[tid] = g_s0[b * LC_ + cB + tid];
        s1f[tid] = g_s1[b * LQ_ + qB + tid];
        qmi[tid] = Qmask[b * LQ_ + qB + tid];
        cmk[tid] = (float)Cmask[b * LC_ + cB + tid];
    }

    const __nv_bfloat16* CwH = (const __nv_bfloat16*)g_Cwhi;
    const __nv_bfloat16* CwL = (const __nv_bfloat16*)g_Cwlo;
    const __nv_bfloat16* QH  = (const __nv_bfloat16*)g_Qhi;
    const __nv_bfloat16* QL  = (const __nv_bfloat16*)g_Qlo;

    u32 buf0 = sb + KS_BUF, buf1 = sb + KS_BUF + 65536;
    cpyR64(buf0,         CwH + (size_t)(b * D_) * LC_ + cB, CwL + (size_t)(b * D_) * LC_ + cB, LC_, tid);
    cpyR64(buf0 + 32768, QH  + (size_t)(b * D_) * LQ_ + qB, QL  + (size_t)(b * D_) * LQ_ + qB, LQ_, tid);
    CP_COMMIT();

    int wm = wid >> 2, wn = wid & 3;
    int m0w = wm * 64, n0w = wn * 32;
    float acc[4][4][4] = {};
    #pragma unroll
    for (int ci = 0; ci < 2; ci++) {
        if (ci == 0) {
            cpyR64(buf1,         CwH + (size_t)(b * D_ + 64) * LC_ + cB, CwL + (size_t)(b * D_ + 64) * LC_ + cB, LC_, tid);
            cpyR64(buf1 + 32768, QH  + (size_t)(b * D_ + 64) * LQ_ + qB, QL  + (size_t)(b * D_ + 64) * LQ_ + qB, LQ_, tid);
            CP_COMMIT();
            CP_WAIT1();
        } else CP_WAIT0();
        __syncthreads();
        u32 bb = ci ? buf1 : buf0;
        mma_chunk<1, 1>(acc, bb, bb + 32768, m0w, n0w, lane);
        __syncthreads();
    }

    // epilogue: exp + split + smem staging (reuses MMA buffers)
    int r = lane >> 2, cp = (lane & 3) * 2;
    float zrow[8] = {}, zcol[8] = {};
    u32 stg = sb + KS_BUF;   // hi plane 128*272; lo at +34816
    #pragma unroll
    for (int mi = 0; mi < 4; mi++) {
        int m0 = m0w + mi * 16 + r;
        float s0a = s0f[m0], s0b = s0f[m0 + 8];
        float cma = cmk[m0], cmb = cmk[m0 + 8];
        #pragma unroll
        for (int nj = 0; nj < 4; nj++) {
            int q0 = n0w + nj * 8 + cp;
            float s1a = s1f[q0], s1b = s1f[q0 + 1];
            int qa = qmi[q0], qb = qmi[q0 + 1];
            float e00 = qa ? __expf(acc[mi][nj][0] + s0a + s1a) : 0.f;
            float e01 = qb ? __expf(acc[mi][nj][1] + s0a + s1b) : 0.f;
            float e10 = qa ? __expf(acc[mi][nj][2] + s0b + s1a) : 0.f;
            float e11 = qb ? __expf(acc[mi][nj][3] + s0b + s1b) : 0.f;
            zrow[mi * 2]     += e00 + e01;
            zrow[mi * 2 + 1] += e10 + e11;
            zcol[nj * 2]     += cma * e00 + cmb * e10;
            zcol[nj * 2 + 1] += cma * e01 + cmb * e11;
            u32 h00, l00, h01, l01, h10, l10, h11, l11;
            splt(e00, h00, l00); splt(e01, h01, l01);
            splt(e10, h10, l10); splt(e11, h11, l11);
            sts32(stg + m0 * 272 + q0 * 2,               h00 | (h01 << 16));
            sts32(stg + 34816 + m0 * 272 + q0 * 2,       l00 | (l01 << 16));
            sts32(stg + (m0 + 8) * 272 + q0 * 2,         h10 | (h11 << 16));
            sts32(stg + 34816 + (m0 + 8) * 272 + q0 * 2, l10 | (l11 << 16));
        }
    }
    #pragma unroll
    for (int h = 0; h < 8; h++) {
        float v = zrow[h];
        v += __shfl_xor_sync(0xffffffffu, v, 1);
        v += __shfl_xor_sync(0xffffffffu, v, 2);
        if ((lane & 3) == 0) {
            int m = m0w + (h >> 1) * 16 + ((h & 1) ? 8 : 0) + r;
            zs[m * 4 + wn] = v;
        }
    }
    #pragma unroll
    for (int j = 0; j < 8; j++) {
        float v = zcol[j];
        v += __shfl_xor_sync(0xffffffffu, v, 4);
        v += __shfl_xor_sync(0xffffffffu, v, 8);
        v += __shfl_xor_sync(0xffffffffu, v, 16);
        zcol[j] = v;
    }
    if (lane < 4) {
        #pragma unroll
        for (int nj = 0; nj < 4; nj++) {
            zc[wm * 128 + n0w + nj * 8 + lane * 2]     = zcol[nj * 2];
            zc[wm * 128 + n0w + nj * 8 + lane * 2 + 1] = zcol[nj * 2 + 1];
        }
    }
    __syncthreads();
    // coalesced copy stage -> global (4096 16B chunks; warp writes 2x256B rows)
    #pragma unroll
    for (int it = 0; it < 16; it++) {
        int idx = tid + it * 256;
        int chunk = idx & 15, c = (idx >> 4) & 127, plane = idx >> 11;
        uint4 v = lds128(stg + plane * 34816 + c * 272 + chunk * 16);
        uint4* dst = plane ? (uint4*)g_Elo : (uint4*)g_Ehi;
        dst[((((size_t)(b * LC_ + cB + c)) * LQ_ + qB) >> 3) + chunk] = v;
    }
    if (tid < 128) {
        g_Z1p[((size_t)b * LC_ + cB + tid) * 4 + qt] =
            zs[tid * 4] + zs[tid * 4 + 1] + zs[tid * 4 + 2] + zs[tid * 4 + 3];
        g_Z2p[((size_t)b * LQ_ + qB + tid) * 16 + blockIdx.y] = zc[tid] + zc[128 + tid];
    }
}

// =====================================================================
// k_T: T[q][d] = rZ2[q] * sum_c E[c,q]*Cm[d,c].  M=q128, N=d128, K=c2048.
// =====================================================================
#define KT_RZ 0
#define KT_BUF 1024
#define KT_DYN 132096

__global__ void __launch_bounds__(256, 1) k_T() {
    extern __shared__ char sm[];
    u32 sb = s2u(sm);
    int tid = threadIdx.x, lane = tid & 31, wid = tid >> 5;
    int b = blockIdx.y, qB = blockIdx.x * 128;
    float* rzs = (float*)(sm + KT_RZ);
    if (tid < 128) {
        const float* p = &g_Z2p[((size_t)b * LQ_ + qB + tid) * 16];
        float s = 0.f;
        #pragma unroll
        for (int t = 0; t < 16; t++) s += p[t];
        rzs[tid] = 1.f / fmaxf(s, 1e-30f);
    }
    const __nv_bfloat16* EH = (const __nv_bfloat16*)g_Ehi;
    const __nv_bfloat16* EL = (const __nv_bfloat16*)g_Elo;
    const __nv_bfloat16* CH = (const __nv_bfloat16*)g_Cmhi;
    const __nv_bfloat16* CL = (const __nv_bfloat16*)g_Cmlo;
    size_t Eoff = (size_t)(b * LC_) * LQ_ + qB;
    size_t Coff = (size_t)(b * D_) * LC_;
    u32 buf[2] = {sb + KT_BUF, sb + KT_BUF + 65536};

    cpyR64 (buf[0],         EH + Eoff, EL + Eoff, LQ_, tid);
    cpyR128(buf[0] + 32768, CH + Coff, CL + Coff, LC_, tid);
    CP_COMMIT();

    int wm = wid >> 2, wn = wid & 3;
    int m0w = wm * 64, n0w = wn * 32;
    float acc[4][4][4] = {};
    for (int ci = 0; ci < 32; ci++) {
        if (ci + 1 < 32) {
            int c0 = (ci + 1) * 64;
            u32 bb = buf[(ci + 1) & 1];
            cpyR64 (bb,         EH + Eoff + (size_t)c0 * LQ_, EL + Eoff + (size_t)c0 * LQ_, LQ_, tid);
            cpyR128(bb + 32768, CH + Coff + c0,               CL + Coff + c0,               LC_, tid);
            CP_COMMIT();
            CP_WAIT1();
        } else CP_WAIT0();
        __syncthreads();
        u32 bb = buf[ci & 1];
        mma_chunk<1, 0>(acc, bb, bb + 32768, m0w, n0w, lane);
        __syncthreads();
    }

    int r = lane >> 2, cp = (lane & 3) * 2;
    #pragma unroll
    for (int mi = 0; mi < 4; mi++) {
        int q0 = m0w + mi * 16 + r;
        float rza = rzs[q0], rzb = rzs[q0 + 8];
        #pragma unroll
        for (int nj = 0; nj < 4; nj++) {
            int d0 = n0w + nj * 8 + cp;
            u32 h0, l0, h1, l1;
            size_t i0 = ((size_t)(b * LQ_ + qB + q0) * D_ + d0) >> 1;
            size_t i1 = ((size_t)(b * LQ_ + qB + q0 + 8) * D_ + d0) >> 1;
            splt(acc[mi][nj][0] * rza, h0, l0); splt(acc[mi][nj][1] * rza, h1, l1);
            g_Thi[i0] = h0 | (h1 << 16); g_Tlo[i0] = l0 | (l1 << 16);
            splt(acc[mi][nj][2] * rzb, h0, l0); splt(acc[mi][nj][3] * rzb, h1, l1);
            g_Thi[i1] = h0 | (h1 << 16); g_Tlo[i1] = l0 | (l1 << 16);
        }
    }
}

// =====================================================================
// k_AB (fused): pass0 D=E@Qt -> sections 0,1,2; pass1 D=E@T -> section 3.
//   E re-read in pass1 hits L2 (same 0.5MB slice, same block).
// =====================================================================
#define KA_RZ 0
#define KA_BUF 1024
#define KA_DYN 132096

__global__ void __launch_bounds__(256, 1) k_AB(const float* __restrict__ C,
                                               float* __restrict__ out) {
    extern __shared__ char sm[];
    u32 sb = s2u(sm);
    int tid = threadIdx.x, lane = tid & 31, wid = tid >> 5;
    int b = blockIdx.y, cB = blockIdx.x * 128;
    float* rzs = (float*)(sm + KA_RZ);
    if (tid < 128) {
        const float* p = &g_Z1p[((size_t)b * LC_ + cB + tid) * 4];
        rzs[tid] = 1.f / (p[0] + p[1] + p[2] + p[3]);
    }
    const __nv_bfloat16* EH = (const __nv_bfloat16*)g_Ehi;
    const __nv_bfloat16* EL = (const __nv_bfloat16*)g_Elo;
    const __nv_bfloat16* QH = (const __nv_bfloat16*)g_Qhi;
    const __nv_bfloat16* QL = (const __nv_bfloat16*)g_Qlo;
    const __nv_bfloat16* TH = (const __nv_bfloat16*)g_Thi;
    const __nv_bfloat16* TL = (const __nv_bfloat16*)g_Tlo;
    size_t Eoff = ((size_t)b * LC_ + cB) * LQ_;
    size_t Qoff = (size_t)(b * D_) * LQ_;
    size_t Toff = (size_t)(b * LQ_) * D_;
    u32 buf[2] = {sb + KA_BUF, sb + KA_BUF + 65536};
    const float* Cb = C + (size_t)b * D_ * LC_ + cB;
    float* ob = out + (size_t)b * 4 * D_ * LC_ + cB;
    float* stg = (float*)(sm + KA_BUF);
    int wm = wid >> 2, wn = wid & 3;
    int m0w = wm * 64, n0w = wn * 32;
    int r = lane >> 2, cp = (lane & 3) * 2;

    #pragma unroll 1
    for (int pass = 0; pass < 2; pass++) {
        // prologue chunk 0
        cpyR128(buf[0], EH + Eoff, EL + Eoff, LQ_, tid);
        if (pass == 0) cpyR128(buf[0] + 32768, QH + Qoff, QL + Qoff, LQ_, tid);
        else           cpyR64 (buf[0] + 32768, TH + Toff, TL + Toff, D_, tid);
        CP_COMMIT();

        float acc[4][4][4] = {};
        for (int ci = 0; ci < 8; ci++) {
            if (ci + 1 < 8) {
                int q0 = (ci + 1) * 64;
                u32 bb = buf[(ci + 1) & 1];
                cpyR128(bb, EH + Eoff + q0, EL + Eoff + q0, LQ_, tid);
                if (pass == 0) cpyR128(bb + 32768, QH + Qoff + q0, QL + Qoff + q0, LQ_, tid);
                else           cpyR64 (bb + 32768, TH + Toff + (size_t)q0 * D_, TL + Toff + (size_t)q0 * D_, D_, tid);
                CP_COMMIT();
                CP_WAIT1();
            } else CP_WAIT0();
            __syncthreads();
            u32 bb = buf[ci & 1];
            if (pass == 0) mma_chunk<0, 0>(acc, bb, bb + 32768, m0w, n0w, lane);
            else           mma_chunk<0, 1>(acc, bb, bb + 32768, m0w, n0w, lane);
            __syncthreads();
        }

        // stage [d][c] (pitch 132) with rZ1
        #pragma unroll
        for (int mi = 0; mi < 4; mi++) {
            int m0 = m0w + mi * 16 + r;
            float rza = rzs[m0], rzb = rzs[m0 + 8];
            #pragma unroll
            for (int nj = 0; nj < 4; nj++) {
                int n0 = n0w + nj * 8 + cp;
                stg[n0 * 132 + m0]           = acc[mi][nj][0] * rza;
                stg[(n0 + 1) * 132 + m0]     = acc[mi][nj][1] * rza;
                stg[n0 * 132 + m0 + 8]       = acc[mi][nj][2] * rzb;
                stg[(n0 + 1) * 132 + m0 + 8] = acc[mi][nj][3] * rzb;
            }
        }
        __syncthreads();
        if (pass == 0) {
            for (int idx = tid; idx < 128 * 128; idx += 256) {
                int dd = idx >> 7, c = idx & 127;
                float a = stg[dd * 132 + c];
                float cv = Cb[(size_t)dd * LC_ + c];
                ob[(size_t)dd * LC_ + c]         = cv;
                ob[(size_t)(128 + dd) * LC_ + c] = a;
                ob[(size_t)(256 + dd) * LC_ + c] = cv * a;
            }
        } else {
            for (int idx = tid; idx < 128 * 128; idx += 256) {
                int dd = idx >> 7, c = idx & 127;
                float bm = stg[dd * 132 + c];
                float cv = Cb[(size_t)dd * LC_ + c];
                ob[(size_t)(384 + dd) * LC_ + c] = cv * bm;
            }
        }
        __syncthreads();
    }
}

// =====================================================================
extern "C" void kernel_launch(void* const* d_in, const int* in_sizes, int n_in,
                              void* d_out, int out_size) {
    const float* C     = (const float*)d_in[0];
    const float* Q     = (const float*)d_in[1];
    const int*   Cmask = (const int*)  d_in[2];
    const int*   Qmask = (const int*)  d_in[3];
    const float* w_c   = (const float*)d_in[4];
    const float* w_q   = (const float*)d_in[5];
    const float* w_mul = (const float*)d_in[6];
    const float* bias  = (const float*)d_in[7];
    float* out = (float*)d_out;

    cudaFuncSetAttribute(k_S,  cudaFuncAttributeMaxDynamicSharedMemorySize, KS_DYN);
    cudaFuncSetAttribute(k_T,  cudaFuncAttributeMaxDynamicSharedMemorySize, KT_DYN);
    cudaFuncSetAttribute(k_AB, cudaFuncAttributeMaxDynamicSharedMemorySize, KA_DYN);

    k_cvtC<<<(B_ * D_ * LC_ / 4) / 256, 256>>>(C, Cmask, w_mul);
    k_cvtQ<<<(B_ * D_ * LQ_ / 4) / 256, 256>>>(Q);
    k_vec<<<320, 256>>>(C, Q, w_c, w_q, bias);
    k_S<<<dim3(4, 16, 32), 256, KS_DYN>>>(Qmask, Cmask);
    k_T<<<dim3(4, 32), 256, KT_DYN>>>();
    k_AB<<<dim3(16, 32), 256, KA_DYN>>>(C, out);
}

// round 9
// speedup vs baseline: 1.0563x; 1.0563x over previous
#include <cuda_runtime.h>
#include <cuda_bf16.h>
#include <cstdint>

#define B_   32
#define D_   128
#define LC_  2048
#define LQ_  512

typedef unsigned int u32;

// ---------------- scratch planes (bf16 hi/lo stored as u32 pairs) ----------
__device__ u32 g_Ehi[(size_t)B_ * LC_ * LQ_ / 2];
__device__ u32 g_Elo[(size_t)B_ * LC_ * LQ_ / 2];
__device__ u32 g_Cwhi[(size_t)B_ * D_ * LC_ / 2];
__device__ u32 g_Cwlo[(size_t)B_ * D_ * LC_ / 2];
__device__ u32 g_Cmhi[(size_t)B_ * D_ * LC_ / 2];
__device__ u32 g_Cmlo[(size_t)B_ * D_ * LC_ / 2];
__device__ u32 g_Qhi[(size_t)B_ * D_ * LQ_ / 2];
__device__ u32 g_Qlo[(size_t)B_ * D_ * LQ_ / 2];
__device__ u32 g_Thi[(size_t)B_ * LQ_ * D_ / 2];
__device__ u32 g_Tlo[(size_t)B_ * LQ_ * D_ / 2];
__device__ float g_s0[B_ * LC_];
__device__ float g_s1[B_ * LQ_];
__device__ float g_Z1p[B_ * LC_ * 4];
__device__ float g_Z2p[B_ * LQ_ * 16];

// ---------------- helpers ----------------
__device__ __forceinline__ u32 s2u(const void* p) {
    u32 a; asm("{ .reg .u64 t; cvta.to.shared.u64 t, %1; cvt.u32.u64 %0, t; }" : "=r"(a) : "l"(p));
    return a;
}
#define SWZ(x) ((u32)(x) ^ ((((u32)(x)) >> 3) & 0x70))

__device__ __forceinline__ void cpa16(u32 dst, const void* src) {
    asm volatile("cp.async.cg.shared.global [%0], [%1], 16;" :: "r"(dst), "l"(src));
}
#define CP_COMMIT() asm volatile("cp.async.commit_group;")
#define CP_WAIT0()  asm volatile("cp.async.wait_group 0;")
#define CP_WAIT1()  asm volatile("cp.async.wait_group 1;")

__device__ __forceinline__ void splt(float v, u32 &hi, u32 &lo) {
    __nv_bfloat16 h = __float2bfloat16(v);
    float hf = __bfloat162float(h);
    __nv_bfloat16 l = __float2bfloat16(v - hf);
    hi = (u32)__bfloat16_as_ushort(h);
    lo = (u32)__bfloat16_as_ushort(l);
}

__device__ __forceinline__ void ldsm4(u32 addr, u32 r[4]) {
    asm volatile("ldmatrix.sync.aligned.m8n8.x4.shared.b16 {%0,%1,%2,%3}, [%4];"
                 : "=r"(r[0]), "=r"(r[1]), "=r"(r[2]), "=r"(r[3]) : "r"(addr));
}
__device__ __forceinline__ void ldsm4t(u32 addr, u32 r[4]) {
    asm volatile("ldmatrix.sync.aligned.m8n8.x4.trans.shared.b16 {%0,%1,%2,%3}, [%4];"
                 : "=r"(r[0]), "=r"(r[1]), "=r"(r[2]), "=r"(r[3]) : "r"(addr));
}
__device__ __forceinline__ void hmma(float d[4], const u32 a[4], u32 b0, u32 b1) {
    asm volatile("mma.sync.aligned.m16n8k16.row.col.f32.bf16.bf16.f32 "
                 "{%0,%1,%2,%3}, {%4,%5,%6,%7}, {%8,%9}, {%0,%1,%2,%3};"
                 : "+f"(d[0]), "+f"(d[1]), "+f"(d[2]), "+f"(d[3])
                 : "r"(a[0]), "r"(a[1]), "r"(a[2]), "r"(a[3]), "r"(b0), "r"(b1));
}
__device__ __forceinline__ uint4 lds128(u32 a) {
    uint4 v;
    asm volatile("ld.shared.v4.b32 {%0,%1,%2,%3}, [%4];"
                 : "=r"(v.x), "=r"(v.y), "=r"(v.z), "=r"(v.w) : "r"(a));
    return v;
}
__device__ __forceinline__ void sts32(u32 a, u32 v) { asm volatile("st.shared.b32 [%0], %1;" :: "r"(a), "r"(v)); }

// ---------------- chunk copy (pure cp.async, 64KB per chunk; NT threads) ---
template<int NT>
__device__ __forceinline__ void cpyR64(u32 dstBase, const __nv_bfloat16* srcHi,
                                       const __nv_bfloat16* srcLo, size_t rowStride, int tid) {
    #pragma unroll
    for (int t = 0; t < 2048 / NT; t++) {
        int u = tid + t * NT;
        int limb = u >> 10, rem = u & 1023;
        int row = rem >> 4, ucol = rem & 15;
        const __nv_bfloat16* src = (limb ? srcLo : srcHi) + (size_t)row * rowStride + ucol * 8;
        u32 dst = dstBase + limb * 16384 + (ucol >> 3) * 8192 + SWZ(row * 128 + (ucol & 7) * 16);
        cpa16(dst, src);
    }
}
template<int NT>
__device__ __forceinline__ void cpyR128(u32 dstBase, const __nv_bfloat16* srcHi,
                                        const __nv_bfloat16* srcLo, size_t rowStride, int tid) {
    #pragma unroll
    for (int t = 0; t < 2048 / NT; t++) {
        int u = tid + t * NT;
        int limb = u >> 10, rem = u & 1023;
        int row = rem >> 3, ucol = rem & 7;
        const __nv_bfloat16* src = (limb ? srcLo : srcHi) + (size_t)row * rowStride + ucol * 8;
        u32 dst = dstBase + limb * 16384 + SWZ(row * 128 + ucol * 16);
        cpa16(dst, src);
    }
}

// ---------------- warp MMA over one k=64 chunk (3-limb, MI m16-tiles) ------
template<int MI, int AT, int BT>
__device__ __forceinline__ void mma_chunk(float acc[MI][4][4], u32 Ab, u32 Bb,
                                          int m0w, int n0w, int lane) {
    #pragma unroll
    for (int ks = 0; ks < 4; ks++) {
        int k0 = ks * 16;
        u32 ah[MI][4], al[MI][4];
        #pragma unroll
        for (int mi = 0; mi < MI; mi++) {
            int m0 = m0w + mi * 16;
            u32 ad;
            if (AT) {
                int r = k0 + (lane & 7) + ((lane & 16) ? 8 : 0);
                int c = m0 + ((lane & 8) ? 8 : 0);
                ad = Ab + ((u32)(c >> 6)) * 8192 + SWZ(r * 128 + (c & 63) * 2);
                ldsm4t(ad, ah[mi]); ldsm4t(ad + 16384, al[mi]);
            } else {
                int r = m0 + (lane & 15);
                int c = k0 + ((lane >> 4) << 3);
                ad = Ab + SWZ(r * 128 + c * 2);
                ldsm4(ad, ah[mi]); ldsm4(ad + 16384, al[mi]);
            }
        }
        u32 bh[4][2], bl[4][2];
        #pragma unroll
        for (int nj2 = 0; nj2 < 2; nj2++) {
            int n0 = n0w + nj2 * 16;
            u32 bd;
            u32 t[4], tl[4];
            if (BT) {
                int r = k0 + (lane & 7) + ((lane & 8) ? 8 : 0);
                int c = n0 + ((lane & 16) ? 8 : 0);
                bd = Bb + ((u32)(c >> 6)) * 8192 + SWZ(r * 128 + (c & 63) * 2);
                ldsm4t(bd, t); ldsm4t(bd + 16384, tl);
            } else {
                int r = n0 + (lane & 7) + ((lane & 16) ? 8 : 0);
                int c = k0 + ((lane & 8) ? 8 : 0);
                bd = Bb + SWZ(r * 128 + c * 2);
                ldsm4(bd, t); ldsm4(bd + 16384, tl);
            }
            bh[nj2 * 2][0] = t[0];  bh[nj2 * 2][1] = t[1];
            bh[nj2 * 2 + 1][0] = t[2]; bh[nj2 * 2 + 1][1] = t[3];
            bl[nj2 * 2][0] = tl[0]; bl[nj2 * 2][1] = tl[1];
            bl[nj2 * 2 + 1][0] = tl[2]; bl[nj2 * 2 + 1][1] = tl[3];
        }
        #pragma unroll
        for (int mi = 0; mi < MI; mi++)
            #pragma unroll
            for (int nj = 0; nj < 4; nj++) {
                hmma(acc[mi][nj], ah[mi], bh[nj][0], bh[nj][1]);
                hmma(acc[mi][nj], ah[mi], bl[nj][0], bl[nj][1]);
                hmma(acc[mi][nj], al[mi], bh[nj][0], bh[nj][1]);
            }
    }
}

// =====================================================================
// preprocessing
// =====================================================================
__global__ void k_cvtC(const float* __restrict__ C, const int* __restrict__ Cmask,
                       const float* __restrict__ w_mul) {
    size_t idx = (size_t)blockIdx.x * 256 + threadIdx.x;
    size_t g4 = idx * 4;
    int c = (int)(g4 & (LC_ - 1));
    int d = (int)((g4 >> 11) & (D_ - 1));
    int b = (int)(g4 >> 18);
    float4 v = *(const float4*)(C + g4);
    int4 m = *(const int4*)(Cmask + b * LC_ + c);
    float w = w_mul[d];
    u32 h[4], l[4];
    splt(v.x * w, h[0], l[0]); splt(v.y * w, h[1], l[1]);
    splt(v.z * w, h[2], l[2]); splt(v.w * w, h[3], l[3]);
    ((uint2*)g_Cwhi)[idx] = make_uint2(h[0] | (h[1] << 16), h[2] | (h[3] << 16));
    ((uint2*)g_Cwlo)[idx] = make_uint2(l[0] | (l[1] << 16), l[2] | (l[3] << 16));
    splt(m.x ? v.x : 0.f, h[0], l[0]); splt(m.y ? v.y : 0.f, h[1], l[1]);
    splt(m.z ? v.z : 0.f, h[2], l[2]); splt(m.w ? v.w : 0.f, h[3], l[3]);
    ((uint2*)g_Cmhi)[idx] = make_uint2(h[0] | (h[1] << 16), h[2] | (h[3] << 16));
    ((uint2*)g_Cmlo)[idx] = make_uint2(l[0] | (l[1] << 16), l[2] | (l[3] << 16));
}

__global__ void k_cvtQ(const float* __restrict__ Q) {
    size_t idx = (size_t)blockIdx.x * 256 + threadIdx.x;
    float4 v = *(const float4*)(Q + idx * 4);
    u32 h[4], l[4];
    splt(v.x, h[0], l[0]); splt(v.y, h[1], l[1]);
    splt(v.z, h[2], l[2]); splt(v.w, h[3], l[3]);
    ((uint2*)g_Qhi)[idx] = make_uint2(h[0] | (h[1] << 16), h[2] | (h[3] << 16));
    ((uint2*)g_Qlo)[idx] = make_uint2(l[0] | (l[1] << 16), l[2] | (l[3] << 16));
}

__global__ void k_vec(const float* __restrict__ C, const float* __restrict__ Q,
                      const float* __restrict__ w_c, const float* __restrict__ w_q,
                      const float* __restrict__ bias) {
    __shared__ float w[128];
    int t = threadIdx.x;
    bool isQ = blockIdx.x >= 256;
    const float* W = isQ ? w_q : w_c;
    if (t < 128) w[t] = W[t];
    __syncthreads();
    if (!isQ) {
        int idx = blockIdx.x * 256 + t;
        int b = idx >> 11, c = idx & (LC_ - 1);
        const float* base = C + (size_t)b * D_ * LC_ + c;
        float acc = bias[0];
        #pragma unroll 8
        for (int dd = 0; dd < 128; dd++) acc += base[dd * LC_] * w[dd];
        g_s0[idx] = acc;
    } else {
        int idx = (blockIdx.x - 256) * 256 + t;
        int b = idx >> 9, q = idx & (LQ_ - 1);
        const float* base = Q + (size_t)b * D_ * LQ_ + q;
        float acc = 0.f;
        #pragma unroll 8
        for (int dd = 0; dd < 128; dd++) acc += base[dd * LQ_] * w[dd];
        g_s1[idx] = acc;
    }
}

// =====================================================================
// k_S: E = qmask*exp(Cw@Qt^T + s0 + s1); 512 threads, warp tile m32n32
// =====================================================================
#define KS_S0 0
#define KS_S1 512
#define KS_QM 1024
#define KS_CM 1536
#define KS_ZS 2048      // 512 f
#define KS_ZC 4096      // 512 f -> 6144
#define KS_BUF 8192
#define KS_DYN 139264

__global__ void __launch_bounds__(512, 1) k_S(const int* __restrict__ Qmask,
                                              const int* __restrict__ Cmask) {
    extern __shared__ char sm[];
    u32 sb = s2u(sm);
    int tid = threadIdx.x, lane = tid & 31, wid = tid >> 5;
    int b = blockIdx.z, cB = blockIdx.y * 128, qB = blockIdx.x * 128, qt = blockIdx.x;
    float* s0f = (float*)(sm + KS_S0);
    float* s1f = (float*)(sm + KS_S1);
    int*   qmi = (int*)(sm + KS_QM);
    float* cmk = (float*)(sm + KS_CM);
    float* zs  = (float*)(sm + KS_ZS);
    float* zc  = (float*)(sm + KS_ZC);
    if (tid < 128) {
        s0f[tid] = g_s0[b * LC_ + cB + tid];
        s1f[tid] = g_s1[b * LQ_ + qB + tid];
        qmi[tid] = Qmask[b * LQ_ + qB + tid];
        cmk[tid] = (float)Cmask[b * LC_ + cB + tid];
    }

    const __nv_bfloat16* CwH = (const __nv_bfloat16*)g_Cwhi;
    const __nv_bfloat16* CwL = (const __nv_bfloat16*)g_Cwlo;
    const __nv_bfloat16* QH  = (const __nv_bfloat16*)g_Qhi;
    const __nv_bfloat16* QL  = (const __nv_bfloat16*)g_Qlo;

    u32 buf0 = sb + KS_BUF, buf1 = sb + KS_BUF + 65536;
    cpyR64<512>(buf0,         CwH + (size_t)(b * D_) * LC_ + cB, CwL + (size_t)(b * D_) * LC_ + cB, LC_, tid);
    cpyR64<512>(buf0 + 32768, QH  + (size_t)(b * D_) * LQ_ + qB, QL  + (size_t)(b * D_) * LQ_ + qB, LQ_, tid);
    CP_COMMIT();

    int wm = wid >> 2, wn = wid & 3;
    int m0w = wm * 32, n0w = wn * 32;
    float acc[2][4][4] = {};
    #pragma unroll
    for (int ci = 0; ci < 2; ci++) {
        if (ci == 0) {
            cpyR64<512>(buf1,         CwH + (size_t)(b * D_ + 64) * LC_ + cB, CwL + (size_t)(b * D_ + 64) * LC_ + cB, LC_, tid);
            cpyR64<512>(buf1 + 32768, QH  + (size_t)(b * D_ + 64) * LQ_ + qB, QL  + (size_t)(b * D_ + 64) * LQ_ + qB, LQ_, tid);
            CP_COMMIT();
            CP_WAIT1();
        } else CP_WAIT0();
        __syncthreads();
        u32 bb = ci ? buf1 : buf0;
        mma_chunk<2, 1, 1>(acc, bb, bb + 32768, m0w, n0w, lane);
        __syncthreads();
    }

    // epilogue: exp + split + smem staging (reuses MMA buffers)
    int r = lane >> 2, cp = (lane & 3) * 2;
    float zrow[4] = {}, zcol[8] = {};
    u32 stg = sb + KS_BUF;   // hi plane 128*272; lo at +34816
    #pragma unroll
    for (int mi = 0; mi < 2; mi++) {
        int m0 = m0w + mi * 16 + r;
        float s0a = s0f[m0], s0b = s0f[m0 + 8];
        float cma = cmk[m0], cmb = cmk[m0 + 8];
        #pragma unroll
        for (int nj = 0; nj < 4; nj++) {
            int q0 = n0w + nj * 8 + cp;
            float s1a = s1f[q0], s1b = s1f[q0 + 1];
            int qa = qmi[q0], qb = qmi[q0 + 1];
            float e00 = qa ? __expf(acc[mi][nj][0] + s0a + s1a) : 0.f;
            float e01 = qb ? __expf(acc[mi][nj][1] + s0a + s1b) : 0.f;
            float e10 = qa ? __expf(acc[mi][nj][2] + s0b + s1a) : 0.f;
            float e11 = qb ? __expf(acc[mi][nj][3] + s0b + s1b) : 0.f;
            zrow[mi * 2]     += e00 + e01;
            zrow[mi * 2 + 1] += e10 + e11;
            zcol[nj * 2]     += cma * e00 + cmb * e10;
            zcol[nj * 2 + 1] += cma * e01 + cmb * e11;
            u32 h00, l00, h01, l01, h10, l10, h11, l11;
            splt(e00, h00, l00); splt(e01, h01, l01);
            splt(e10, h10, l10); splt(e11, h11, l11);
            sts32(stg + m0 * 272 + q0 * 2,               h00 | (h01 << 16));
            sts32(stg + 34816 + m0 * 272 + q0 * 2,       l00 | (l01 << 16));
            sts32(stg + (m0 + 8) * 272 + q0 * 2,         h10 | (h11 << 16));
            sts32(stg + 34816 + (m0 + 8) * 272 + q0 * 2, l10 | (l11 << 16));
        }
    }
    #pragma unroll
    for (int h = 0; h < 4; h++) {
        float v = zrow[h];
        v += __shfl_xor_sync(0xffffffffu, v, 1);
        v += __shfl_xor_sync(0xffffffffu, v, 2);
        if ((lane & 3) == 0) {
            int m = m0w + (h >> 1) * 16 + ((h & 1) ? 8 : 0) + r;
            zs[m * 4 + wn] = v;
        }
    }
    #pragma unroll
    for (int j = 0; j < 8; j++) {
        float v = zcol[j];
        v += __shfl_xor_sync(0xffffffffu, v, 4);
        v += __shfl_xor_sync(0xffffffffu, v, 8);
        v += __shfl_xor_sync(0xffffffffu, v, 16);
        zcol[j] = v;
    }
    if (lane < 4) {
        #pragma unroll
        for (int nj = 0; nj < 4; nj++) {
            zc[wm * 128 + n0w + nj * 8 + lane * 2]     = zcol[nj * 2];
            zc[wm * 128 + n0w + nj * 8 + lane * 2 + 1] = zcol[nj * 2 + 1];
        }
    }
    __syncthreads();
    // coalesced copy stage -> global
    #pragma unroll
    for (int it = 0; it < 8; it++) {
        int idx = tid + it * 512;
        int chunk = idx & 15, c = (idx >> 4) & 127, plane = idx >> 11;
        uint4 v = lds128(stg + plane * 34816 + c * 272 + chunk * 16);
        uint4* dst = plane ? (uint4*)g_Elo : (uint4*)g_Ehi;
        dst[((((size_t)(b * LC_ + cB + c)) * LQ_ + qB) >> 3) + chunk] = v;
    }
    if (tid < 128) {
        g_Z1p[((size_t)b * LC_ + cB + tid) * 4 + qt] =
            zs[tid * 4] + zs[tid * 4 + 1] + zs[tid * 4 + 2] + zs[tid * 4 + 3];
        g_Z2p[((size_t)b * LQ_ + qB + tid) * 16 + blockIdx.y] =
            zc[tid] + zc[128 + tid] + zc[256 + tid] + zc[384 + tid];
    }
}

// =====================================================================
// k_T: T[q][d] = rZ2[q] * sum_c E[c,q]*Cm[d,c]. 512 threads.
// =====================================================================
#define KT_RZ 0
#define KT_BUF 1024
#define KT_DYN 132096

__global__ void __launch_bounds__(512, 1) k_T() {
    extern __shared__ char sm[];
    u32 sb = s2u(sm);
    int tid = threadIdx.x, lane = tid & 31, wid = tid >> 5;
    int b = blockIdx.y, qB = blockIdx.x * 128;
    float* rzs = (float*)(sm + KT_RZ);
    if (tid < 128) {
        const float* p = &g_Z2p[((size_t)b * LQ_ + qB + tid) * 16];
        float s = 0.f;
        #pragma unroll
        for (int t = 0; t < 16; t++) s += p[t];
        rzs[tid] = 1.f / fmaxf(s, 1e-30f);
    }
    const __nv_bfloat16* EH = (const __nv_bfloat16*)g_Ehi;
    const __nv_bfloat16* EL = (const __nv_bfloat16*)g_Elo;
    const __nv_bfloat16* CH = (const __nv_bfloat16*)g_Cmhi;
    const __nv_bfloat16* CL = (const __nv_bfloat16*)g_Cmlo;
    size_t Eoff = (size_t)(b * LC_) * LQ_ + qB;
    size_t Coff = (size_t)(b * D_) * LC_;
    u32 buf[2] = {sb + KT_BUF, sb + KT_BUF + 65536};

    cpyR64<512> (buf[0],         EH + Eoff, EL + Eoff, LQ_, tid);
    cpyR128<512>(buf[0] + 32768, CH + Coff, CL + Coff, LC_, tid);
    CP_COMMIT();

    int wm = wid >> 2, wn = wid & 3;
    int m0w = wm * 32, n0w = wn * 32;
    float acc[2][4][4] = {};
    for (int ci = 0; ci < 32; ci++) {
        if (ci + 1 < 32) {
            int c0 = (ci + 1) * 64;
            u32 bb = buf[(ci + 1) & 1];
            cpyR64<512> (bb,         EH + Eoff + (size_t)c0 * LQ_, EL + Eoff + (size_t)c0 * LQ_, LQ_, tid);
            cpyR128<512>(bb + 32768, CH + Coff + c0,               CL + Coff + c0,               LC_, tid);
            CP_COMMIT();
            CP_WAIT1();
        } else CP_WAIT0();
        __syncthreads();
        u32 bb = buf[ci & 1];
        mma_chunk<2, 1, 0>(acc, bb, bb + 32768, m0w, n0w, lane);
        __syncthreads();
    }

    int r = lane >> 2, cp = (lane & 3) * 2;
    #pragma unroll
    for (int mi = 0; mi < 2; mi++) {
        int q0 = m0w + mi * 16 + r;
        float rza = rzs[q0], rzb = rzs[q0 + 8];
        #pragma unroll
        for (int nj = 0; nj < 4; nj++) {
            int d0 = n0w + nj * 8 + cp;
            u32 h0, l0, h1, l1;
            size_t i0 = ((size_t)(b * LQ_ + qB + q0) * D_ + d0) >> 1;
            size_t i1 = ((size_t)(b * LQ_ + qB + q0 + 8) * D_ + d0) >> 1;
            splt(acc[mi][nj][0] * rza, h0, l0); splt(acc[mi][nj][1] * rza, h1, l1);
            g_Thi[i0] = h0 | (h1 << 16); g_Tlo[i0] = l0 | (l1 << 16);
            splt(acc[mi][nj][2] * rzb, h0, l0); splt(acc[mi][nj][3] * rzb, h1, l1);
            g_Thi[i1] = h0 | (h1 << 16); g_Tlo[i1] = l0 | (l1 << 16);
        }
    }
}

// =====================================================================
// k_AB (fused): pass0 D=E@Qt -> sections 0,1,2; pass1 D=E@T -> section 3.
// =====================================================================
#define KA_RZ 0
#define KA_BUF 1024
#define KA_DYN 132096

__global__ void __launch_bounds__(512, 1) k_AB(const float* __restrict__ C,
                                               float* __restrict__ out) {
    extern __shared__ char sm[];
    u32 sb = s2u(sm);
    int tid = threadIdx.x, lane = tid & 31, wid = tid >> 5;
    int b = blockIdx.y, cB = blockIdx.x * 128;
    float* rzs = (float*)(sm + KA_RZ);
    if (tid < 128) {
        const float* p = &g_Z1p[((size_t)b * LC_ + cB + tid) * 4];
        rzs[tid] = 1.f / (p[0] + p[1] + p[2] + p[3]);
    }
    const __nv_bfloat16* EH = (const __nv_bfloat16*)g_Ehi;
    const __nv_bfloat16* EL = (const __nv_bfloat16*)g_Elo;
    const __nv_bfloat16* QH = (const __nv_bfloat16*)g_Qhi;
    const __nv_bfloat16* QL = (const __nv_bfloat16*)g_Qlo;
    const __nv_bfloat16* TH = (const __nv_bfloat16*)g_Thi;
    const __nv_bfloat16* TL = (const __nv_bfloat16*)g_Tlo;
    size_t Eoff = ((size_t)b * LC_ + cB) * LQ_;
    size_t Qoff = (size_t)(b * D_) * LQ_;
    size_t Toff = (size_t)(b * LQ_) * D_;
    u32 buf[2] = {sb + KA_BUF, sb + KA_BUF + 65536};
    const float* Cb = C + (size_t)b * D_ * LC_ + cB;
    float* ob = out + (size_t)b * 4 * D_ * LC_ + cB;
    float* stg = (float*)(sm + KA_BUF);
    int wm = wid >> 2, wn = wid & 3;
    int m0w = wm * 32, n0w = wn * 32;
    int r = lane >> 2, cp = (lane & 3) * 2;

    #pragma unroll 1
    for (int pass = 0; pass < 2; pass++) {
        cpyR128<512>(buf[0], EH + Eoff, EL + Eoff, LQ_, tid);
        if (pass == 0) cpyR128<512>(buf[0] + 32768, QH + Qoff, QL + Qoff, LQ_, tid);
        else           cpyR64<512> (buf[0] + 32768, TH + Toff, TL + Toff, D_, tid);
        CP_COMMIT();

        float acc[2][4][4] = {};
        for (int ci = 0; ci < 8; ci++) {
            if (ci + 1 < 8) {
                int q0 = (ci + 1) * 64;
                u32 bb = buf[(ci + 1) & 1];
                cpyR128<512>(bb, EH + Eoff + q0, EL + Eoff + q0, LQ_, tid);
                if (pass == 0) cpyR128<512>(bb + 32768, QH + Qoff + q0, QL + Qoff + q0, LQ_, tid);
                else           cpyR64<512> (bb + 32768, TH + Toff + (size_t)q0 * D_, TL + Toff + (size_t)q0 * D_, D_, tid);
                CP_COMMIT();
                CP_WAIT1();
            } else CP_WAIT0();
            __syncthreads();
            u32 bb = buf[ci & 1];
            if (pass == 0) mma_chunk<2, 0, 0>(acc, bb, bb + 32768, m0w, n0w, lane);
            else           mma_chunk<2, 0, 1>(acc, bb, bb + 32768, m0w, n0w, lane);
            __syncthreads();
        }

        // stage [d][c] (pitch 132) with rZ1
        #pragma unroll
        for (int mi = 0; mi < 2; mi++) {
            int m0 = m0w + mi * 16 + r;
            float rza = rzs[m0], rzb = rzs[m0 + 8];
            #pragma unroll
            for (int nj = 0; nj < 4; nj++) {
                int n0 = n0w + nj * 8 + cp;
                stg[n0 * 132 + m0]           = acc[mi][nj][0] * rza;
                stg[(n0 + 1) * 132 + m0]     = acc[mi][nj][1] * rza;
                stg[n0 * 132 + m0 + 8]       = acc[mi][nj][2] * rzb;
                stg[(n0 + 1) * 132 + m0 + 8] = acc[mi][nj][3] * rzb;
            }
        }
        __syncthreads();
        if (pass == 0) {
            for (int idx = tid; idx < 128 * 128; idx += 512) {
                int dd = idx >> 7, c = idx & 127;
                float a = stg[dd * 132 + c];
                float cv = Cb[(size_t)dd * LC_ + c];
                ob[(size_t)dd * LC_ + c]         = cv;
                ob[(size_t)(128 + dd) * LC_ + c] = a;
                ob[(size_t)(256 + dd) * LC_ + c] = cv * a;
            }
        } else {
            for (int idx = tid; idx < 128 * 128; idx += 512) {
                int dd = idx >> 7, c = idx & 127;
                float bm = stg[dd * 132 + c];
                float cv = Cb[(size_t)dd * LC_ + c];
                ob[(size_t)(384 + dd) * LC_ + c] = cv * bm;
            }
        }
        __syncthreads();
    }
}

// =====================================================================
extern "C" void kernel_launch(void* const* d_in, const int* in_sizes, int n_in,
                              void* d_out, int out_size) {
    const float* C     = (const float*)d_in[0];
    const float* Q     = (const float*)d_in[1];
    const int*   Cmask = (const int*)  d_in[2];
    const int*   Qmask = (const int*)  d_in[3];
    const float* w_c   = (const float*)d_in[4];
    const float* w_q   = (const float*)d_in[5];
    const float* w_mul = (const float*)d_in[6];
    const float* bias  = (const float*)d_in[7];
    float* out = (float*)d_out;

    cudaFuncSetAttribute(k_S,  cudaFuncAttributeMaxDynamicSharedMemorySize, KS_DYN);
    cudaFuncSetAttribute(k_T,  cudaFuncAttributeMaxDynamicSharedMemorySize, KT_DYN);
    cudaFuncSetAttribute(k_AB, cudaFuncAttributeMaxDynamicSharedMemorySize, KA_DYN);

    k_cvtC<<<(B_ * D_ * LC_ / 4) / 256, 256>>>(C, Cmask, w_mul);
    k_cvtQ<<<(B_ * D_ * LQ_ / 4) / 256, 256>>>(Q);
    k_vec<<<320, 256>>>(C, Q, w_c, w_q, bias);
    k_S<<<dim3(4, 16, 32), 512, KS_DYN>>>(Qmask, Cmask);
    k_T<<<dim3(4, 32), 512, KT_DYN>>>();
    k_AB<<<dim3(16, 32), 512, KA_DYN>>>(C, out);
}

// round 10
// speedup vs baseline: 1.0759x; 1.0185x over previous
#include <cuda_runtime.h>
#include <cuda_bf16.h>
#include <cstdint>

#define B_   32
#define D_   128
#define LC_  2048
#define LQ_  512

typedef unsigned int u32;

// ---------------- scratch planes (bf16 hi/lo stored as u32 pairs) ----------
__device__ u32 g_Ehi[(size_t)B_ * LC_ * LQ_ / 2];
__device__ u32 g_Elo[(size_t)B_ * LC_ * LQ_ / 2];
__device__ u32 g_Cwhi[(size_t)B_ * D_ * LC_ / 2];
__device__ u32 g_Cwlo[(size_t)B_ * D_ * LC_ / 2];
__device__ u32 g_Cmhi[(size_t)B_ * D_ * LC_ / 2];
__device__ u32 g_Cmlo[(size_t)B_ * D_ * LC_ / 2];
__device__ u32 g_Qhi[(size_t)B_ * D_ * LQ_ / 2];
__device__ u32 g_Qlo[(size_t)B_ * D_ * LQ_ / 2];
__device__ u32 g_Thi[(size_t)B_ * LQ_ * D_ / 2];
__device__ u32 g_Tlo[(size_t)B_ * LQ_ * D_ / 2];
__device__ float g_s0[B_ * LC_];
__device__ float g_s1[B_ * LQ_];
__device__ float g_Z1p[B_ * LC_ * 4];
__device__ float g_Z2p[B_ * LQ_ * 16];

// ---------------- helpers ----------------
__device__ __forceinline__ u32 s2u(const void* p) {
    u32 a; asm("{ .reg .u64 t; cvta.to.shared.u64 t, %1; cvt.u32.u64 %0, t; }" : "=r"(a) : "l"(p));
    return a;
}
#define SWZ(x) ((u32)(x) ^ ((((u32)(x)) >> 3) & 0x70))

__device__ __forceinline__ void cpa16(u32 dst, const void* src) {
    asm volatile("cp.async.cg.shared.global [%0], [%1], 16;" :: "r"(dst), "l"(src));
}
#define CP_COMMIT() asm volatile("cp.async.commit_group;")
#define CP_WAIT0()  asm volatile("cp.async.wait_group 0;")
#define CP_WAIT1()  asm volatile("cp.async.wait_group 1;")

__device__ __forceinline__ void splt(float v, u32 &hi, u32 &lo) {
    __nv_bfloat16 h = __float2bfloat16(v);
    float hf = __bfloat162float(h);
    __nv_bfloat16 l = __float2bfloat16(v - hf);
    hi = (u32)__bfloat16_as_ushort(h);
    lo = (u32)__bfloat16_as_ushort(l);
}

__device__ __forceinline__ void ldsm4(u32 addr, u32 r[4]) {
    asm volatile("ldmatrix.sync.aligned.m8n8.x4.shared.b16 {%0,%1,%2,%3}, [%4];"
                 : "=r"(r[0]), "=r"(r[1]), "=r"(r[2]), "=r"(r[3]) : "r"(addr));
}
__device__ __forceinline__ void ldsm4t(u32 addr, u32 r[4]) {
    asm volatile("ldmatrix.sync.aligned.m8n8.x4.trans.shared.b16 {%0,%1,%2,%3}, [%4];"
                 : "=r"(r[0]), "=r"(r[1]), "=r"(r[2]), "=r"(r[3]) : "r"(addr));
}
__device__ __forceinline__ void hmma(float d[4], const u32 a[4], u32 b0, u32 b1) {
    asm volatile("mma.sync.aligned.m16n8k16.row.col.f32.bf16.bf16.f32 "
                 "{%0,%1,%2,%3}, {%4,%5,%6,%7}, {%8,%9}, {%0,%1,%2,%3};"
                 : "+f"(d[0]), "+f"(d[1]), "+f"(d[2]), "+f"(d[3])
                 : "r"(a[0]), "r"(a[1]), "r"(a[2]), "r"(a[3]), "r"(b0), "r"(b1));
}
__device__ __forceinline__ uint4 lds128(u32 a) {
    uint4 v;
    asm volatile("ld.shared.v4.b32 {%0,%1,%2,%3}, [%4];"
                 : "=r"(v.x), "=r"(v.y), "=r"(v.z), "=r"(v.w) : "r"(a));
    return v;
}
__device__ __forceinline__ void sts32(u32 a, u32 v) { asm volatile("st.shared.b32 [%0], %1;" :: "r"(a), "r"(v)); }

// ---------------- chunk copies ----------------
// k-major panel, k=64 rows x 128 cols, 2 limbs (32KB). Sub-panels 8KB, SW128.
template<int NT>
__device__ __forceinline__ void cpyT64(u32 dstBase, const __nv_bfloat16* srcHi,
                                       const __nv_bfloat16* srcLo, size_t rowStride, int tid) {
    #pragma unroll
    for (int t = 0; t < 2048 / NT; t++) {
        int u = tid + t * NT;
        int limb = u >> 10, rem = u & 1023;
        int row = rem >> 4, ucol = rem & 15;
        const __nv_bfloat16* src = (limb ? srcLo : srcHi) + (size_t)row * rowStride + ucol * 8;
        u32 dst = dstBase + limb * 16384 + (ucol >> 3) * 8192 + SWZ(row * 128 + (ucol & 7) * 16);
        cpa16(dst, src);
    }
}
// k-major panel, k=32 rows x 128 cols, 2 limbs (16KB). Sub-panels 4KB, SW128.
template<int NT>
__device__ __forceinline__ void cpyT32(u32 dstBase, const __nv_bfloat16* srcHi,
                                       const __nv_bfloat16* srcLo, size_t rowStride, int tid) {
    #pragma unroll
    for (int t = 0; t < 1024 / NT; t++) {
        int u = tid + t * NT;
        int limb = u >> 9, rem = u & 511;
        int row = rem >> 4, ucol = rem & 15;
        const __nv_bfloat16* src = (limb ? srcLo : srcHi) + (size_t)row * rowStride + ucol * 8;
        u32 dst = dstBase + limb * 8192 + (ucol >> 3) * 4096 + SWZ(row * 128 + (ucol & 7) * 16);
        cpa16(dst, src);
    }
}
// row-major panel, 128 rows x k=64 cols, 2 limbs (32KB). 128B rows, SW128.
template<int NT>
__device__ __forceinline__ void cpyN128(u32 dstBase, const __nv_bfloat16* srcHi,
                                        const __nv_bfloat16* srcLo, size_t rowStride, int tid) {
    #pragma unroll
    for (int t = 0; t < 2048 / NT; t++) {
        int u = tid + t * NT;
        int limb = u >> 10, rem = u & 1023;
        int row = rem >> 3, ucol = rem & 7;
        const __nv_bfloat16* src = (limb ? srcLo : srcHi) + (size_t)row * rowStride + ucol * 8;
        u32 dst = dstBase + limb * 16384 + SWZ(row * 128 + ucol * 16);
        cpa16(dst, src);
    }
}

// ---------------- warp MMA over one chunk (3-limb) -------------------------
// SUB: k-major sub-panel bytes (8192 for k64, 4096 for k32); lo limb at +2*SUB.
template<int MI, int AT, int BT, int KSTEPS, int SUB>
__device__ __forceinline__ void mma_chunk(float acc[MI][4][4], u32 Ab, u32 Bb,
                                          int m0w, int n0w, int lane) {
    const int LO = 2 * SUB;
    #pragma unroll
    for (int ks = 0; ks < KSTEPS; ks++) {
        int k0 = ks * 16;
        u32 ah[MI][4], al[MI][4];
        #pragma unroll
        for (int mi = 0; mi < MI; mi++) {
            int m0 = m0w + mi * 16;
            u32 ad;
            if (AT) {
                int r = k0 + (lane & 7) + ((lane & 16) ? 8 : 0);
                int c = m0 + ((lane & 8) ? 8 : 0);
                ad = Ab + ((u32)(c >> 6)) * SUB + SWZ(r * 128 + (c & 63) * 2);
                ldsm4t(ad, ah[mi]); ldsm4t(ad + LO, al[mi]);
            } else {
                int r = m0 + (lane & 15);
                int c = k0 + ((lane >> 4) << 3);
                ad = Ab + SWZ(r * 128 + c * 2);
                ldsm4(ad, ah[mi]); ldsm4(ad + LO, al[mi]);
            }
        }
        u32 bh[4][2], bl[4][2];
        #pragma unroll
        for (int nj2 = 0; nj2 < 2; nj2++) {
            int n0 = n0w + nj2 * 16;
            u32 bd;
            u32 t[4], tl[4];
            if (BT) {
                int r = k0 + (lane & 7) + ((lane & 8) ? 8 : 0);
                int c = n0 + ((lane & 16) ? 8 : 0);
                bd = Bb + ((u32)(c >> 6)) * SUB + SWZ(r * 128 + (c & 63) * 2);
                ldsm4t(bd, t); ldsm4t(bd + LO, tl);
            } else {
                int r = n0 + (lane & 7) + ((lane & 16) ? 8 : 0);
                int c = k0 + ((lane & 8) ? 8 : 0);
                bd = Bb + SWZ(r * 128 + c * 2);
                ldsm4(bd, t); ldsm4(bd + LO, tl);
            }
            bh[nj2 * 2][0] = t[0];  bh[nj2 * 2][1] = t[1];
            bh[nj2 * 2 + 1][0] = t[2]; bh[nj2 * 2 + 1][1] = t[3];
            bl[nj2 * 2][0] = tl[0]; bl[nj2 * 2][1] = tl[1];
            bl[nj2 * 2 + 1][0] = tl[2]; bl[nj2 * 2 + 1][1] = tl[3];
        }
        #pragma unroll
        for (int mi = 0; mi < MI; mi++)
            #pragma unroll
            for (int nj = 0; nj < 4; nj++) {
                hmma(acc[mi][nj], ah[mi], bh[nj][0], bh[nj][1]);
                hmma(acc[mi][nj], ah[mi], bl[nj][0], bl[nj][1]);
                hmma(acc[mi][nj], al[mi], bh[nj][0], bh[nj][1]);
            }
    }
}

// =====================================================================
// preprocessing
// =====================================================================
__global__ void k_cvtC(const float* __restrict__ C, const int* __restrict__ Cmask,
                       const float* __restrict__ w_mul) {
    size_t idx = (size_t)blockIdx.x * 256 + threadIdx.x;
    size_t g4 = idx * 4;
    int c = (int)(g4 & (LC_ - 1));
    int d = (int)((g4 >> 11) & (D_ - 1));
    int b = (int)(g4 >> 18);
    float4 v = *(const float4*)(C + g4);
    int4 m = *(const int4*)(Cmask + b * LC_ + c);
    float w = w_mul[d];
    u32 h[4], l[4];
    splt(v.x * w, h[0], l[0]); splt(v.y * w, h[1], l[1]);
    splt(v.z * w, h[2], l[2]); splt(v.w * w, h[3], l[3]);
    ((uint2*)g_Cwhi)[idx] = make_uint2(h[0] | (h[1] << 16), h[2] | (h[3] << 16));
    ((uint2*)g_Cwlo)[idx] = make_uint2(l[0] | (l[1] << 16), l[2] | (l[3] << 16));
    splt(m.x ? v.x : 0.f, h[0], l[0]); splt(m.y ? v.y : 0.f, h[1], l[1]);
    splt(m.z ? v.z : 0.f, h[2], l[2]); splt(m.w ? v.w : 0.f, h[3], l[3]);
    ((uint2*)g_Cmhi)[idx] = make_uint2(h[0] | (h[1] << 16), h[2] | (h[3] << 16));
    ((uint2*)g_Cmlo)[idx] = make_uint2(l[0] | (l[1] << 16), l[2] | (l[3] << 16));
}

__global__ void k_cvtQ(const float* __restrict__ Q) {
    size_t idx = (size_t)blockIdx.x * 256 + threadIdx.x;
    float4 v = *(const float4*)(Q + idx * 4);
    u32 h[4], l[4];
    splt(v.x, h[0], l[0]); splt(v.y, h[1], l[1]);
    splt(v.z, h[2], l[2]); splt(v.w, h[3], l[3]);
    ((uint2*)g_Qhi)[idx] = make_uint2(h[0] | (h[1] << 16), h[2] | (h[3] << 16));
    ((uint2*)g_Qlo)[idx] = make_uint2(l[0] | (l[1] << 16), l[2] | (l[3] << 16));
}

__global__ void k_vec(const float* __restrict__ C, const float* __restrict__ Q,
                      const float* __restrict__ w_c, const float* __restrict__ w_q,
                      const float* __restrict__ bias) {
    __shared__ float w[128];
    int t = threadIdx.x;
    bool isQ = blockIdx.x >= 256;
    const float* W = isQ ? w_q : w_c;
    if (t < 128) w[t] = W[t];
    __syncthreads();
    if (!isQ) {
        int idx = blockIdx.x * 256 + t;
        int b = idx >> 11, c = idx & (LC_ - 1);
        const float* base = C + (size_t)b * D_ * LC_ + c;
        float acc = bias[0];
        #pragma unroll 8
        for (int dd = 0; dd < 128; dd++) acc += base[dd * LC_] * w[dd];
        g_s0[idx] = acc;
    } else {
        int idx = (blockIdx.x - 256) * 256 + t;
        int b = idx >> 9, q = idx & (LQ_ - 1);
        const float* base = Q + (size_t)b * D_ * LQ_ + q;
        float acc = 0.f;
        #pragma unroll 8
        for (int dd = 0; dd < 128; dd++) acc += base[dd * LQ_] * w[dd];
        g_s1[idx] = acc;
    }
}

// =====================================================================
// k_S: E = qmask*exp(Cw@Qt^T + s0 + s1). k32 chunks x4, 3-stage, 1 sync/chunk.
// =====================================================================
#define KS_S0 0
#define KS_S1 512
#define KS_QM 1024
#define KS_CM 1536
#define KS_ZS 2048      // 512 f
#define KS_ZC 4096      // 256 f
#define KS_BUF 8192     // 3 stages x 32KB (A 16KB + B 16KB)
#define KS_DYN (8192 + 3 * 32768)

__global__ void __launch_bounds__(512, 1) k_S(const int* __restrict__ Qmask,
                                              const int* __restrict__ Cmask) {
    extern __shared__ char sm[];
    u32 sb = s2u(sm);
    int tid = threadIdx.x, lane = tid & 31, wid = tid >> 5;
    int b = blockIdx.z, cB = blockIdx.y * 128, qB = blockIdx.x * 128, qt = blockIdx.x;
    float* s0f = (float*)(sm + KS_S0);
    float* s1f = (float*)(sm + KS_S1);
    int*   qmi = (int*)(sm + KS_QM);
    float* cmk = (float*)(sm + KS_CM);
    float* zs  = (float*)(sm + KS_ZS);
    float* zc  = (float*)(sm + KS_ZC);
    if (tid < 128) {
        s0f[tid] = g_s0[b * LC_ + cB + tid];
        s1f[tid] = g_s1[b * LQ_ + qB + tid];
        qmi[tid] = Qmask[b * LQ_ + qB + tid];
        cmk[tid] = (float)Cmask[b * LC_ + cB + tid];
    }

    const __nv_bfloat16* CwH = (const __nv_bfloat16*)g_Cwhi;
    const __nv_bfloat16* CwL = (const __nv_bfloat16*)g_Cwlo;
    const __nv_bfloat16* QH  = (const __nv_bfloat16*)g_Qhi;
    const __nv_bfloat16* QL  = (const __nv_bfloat16*)g_Qlo;
    size_t Ca = (size_t)(b * D_) * LC_ + cB;
    size_t Qa = (size_t)(b * D_) * LQ_ + qB;

    // prologue: chunks 0,1
    #pragma unroll
    for (int pc = 0; pc < 2; pc++) {
        u32 st = sb + KS_BUF + pc * 32768;
        cpyT32<512>(st,         CwH + Ca + (size_t)(pc * 32) * LC_, CwL + Ca + (size_t)(pc * 32) * LC_, LC_, tid);
        cpyT32<512>(st + 16384, QH  + Qa + (size_t)(pc * 32) * LQ_, QL  + Qa + (size_t)(pc * 32) * LQ_, LQ_, tid);
        CP_COMMIT();
    }

    int wm = wid >> 2, wn = wid & 3;
    int m0w = wm * 32, n0w = wn * 32;
    float acc[2][4][4] = {};
    #pragma unroll
    for (int ci = 0; ci < 4; ci++) {
        if (ci < 3) CP_WAIT1(); else CP_WAIT0();
        __syncthreads();
        if (ci < 2) {
            int k0 = (ci + 2) * 32;
            u32 st = sb + KS_BUF + ((ci + 2) % 3) * 32768;
            cpyT32<512>(st,         CwH + Ca + (size_t)k0 * LC_, CwL + Ca + (size_t)k0 * LC_, LC_, tid);
            cpyT32<512>(st + 16384, QH  + Qa + (size_t)k0 * LQ_, QL  + Qa + (size_t)k0 * LQ_, LQ_, tid);
            CP_COMMIT();
        }
        u32 bb = sb + KS_BUF + (ci % 3) * 32768;
        mma_chunk<2, 1, 1, 2, 4096>(acc, bb, bb + 16384, m0w, n0w, lane);
    }
    __syncthreads();   // all warps done with buffers before stage overwrite

    // epilogue: exp + split + smem staging (reuses MMA buffers)
    int r = lane >> 2, cp = (lane & 3) * 2;
    float zrow[4] = {}, zcol[8] = {};
    u32 stg = sb + KS_BUF;   // hi plane 128*272; lo at +34816
    #pragma unroll
    for (int mi = 0; mi < 2; mi++) {
        int m0 = m0w + mi * 16 + r;
        float s0a = s0f[m0], s0b = s0f[m0 + 8];
        float cma = cmk[m0], cmb = cmk[m0 + 8];
        #pragma unroll
        for (int nj = 0; nj < 4; nj++) {
            int q0 = n0w + nj * 8 + cp;
            float s1a = s1f[q0], s1b = s1f[q0 + 1];
            int qa = qmi[q0], qb = qmi[q0 + 1];
            float e00 = qa ? __expf(acc[mi][nj][0] + s0a + s1a) : 0.f;
            float e01 = qb ? __expf(acc[mi][nj][1] + s0a + s1b) : 0.f;
            float e10 = qa ? __expf(acc[mi][nj][2] + s0b + s1a) : 0.f;
            float e11 = qb ? __expf(acc[mi][nj][3] + s0b + s1b) : 0.f;
            zrow[mi * 2]     += e00 + e01;
            zrow[mi * 2 + 1] += e10 + e11;
            zcol[nj * 2]     += cma * e00 + cmb * e10;
            zcol[nj * 2 + 1] += cma * e01 + cmb * e11;
            u32 h00, l00, h01, l01, h10, l10, h11, l11;
            splt(e00, h00, l00); splt(e01, h01, l01);
            splt(e10, h10, l10); splt(e11, h11, l11);
            sts32(stg + m0 * 272 + q0 * 2,               h00 | (h01 << 16));
            sts32(stg + 34816 + m0 * 272 + q0 * 2,       l00 | (l01 << 16));
            sts32(stg + (m0 + 8) * 272 + q0 * 2,         h10 | (h11 << 16));
            sts32(stg + 34816 + (m0 + 8) * 272 + q0 * 2, l10 | (l11 << 16));
        }
    }
    #pragma unroll
    for (int h = 0; h < 4; h++) {
        float v = zrow[h];
        v += __shfl_xor_sync(0xffffffffu, v, 1);
        v += __shfl_xor_sync(0xffffffffu, v, 2);
        if ((lane & 3) == 0) {
            int m = m0w + (h >> 1) * 16 + ((h & 1) ? 8 : 0) + r;
            zs[m * 4 + wn] = v;
        }
    }
    #pragma unroll
    for (int j = 0; j < 8; j++) {
        float v = zcol[j];
        v += __shfl_xor_sync(0xffffffffu, v, 4);
        v += __shfl_xor_sync(0xffffffffu, v, 8);
        v += __shfl_xor_sync(0xffffffffu, v, 16);
        zcol[j] = v;
    }
    if (lane < 4) {
        #pragma unroll
        for (int nj = 0; nj < 4; nj++) {
            zc[wm * 128 + n0w + nj * 8 + lane * 2]     = zcol[nj * 2];
            zc[wm * 128 + n0w + nj * 8 + lane * 2 + 1] = zcol[nj * 2 + 1];
        }
    }
    __syncthreads();
    // coalesced copy stage -> global
    #pragma unroll
    for (int it = 0; it < 8; it++) {
        int idx = tid + it * 512;
        int chunk = idx & 15, c = (idx >> 4) & 127, plane = idx >> 11;
        uint4 v = lds128(stg + plane * 34816 + c * 272 + chunk * 16);
        uint4* dst = plane ? (uint4*)g_Elo : (uint4*)g_Ehi;
        dst[((((size_t)(b * LC_ + cB + c)) * LQ_ + qB) >> 3) + chunk] = v;
    }
    if (tid < 128) {
        g_Z1p[((size_t)b * LC_ + cB + tid) * 4 + qt] =
            zs[tid * 4] + zs[tid * 4 + 1] + zs[tid * 4 + 2] + zs[tid * 4 + 3];
        g_Z2p[((size_t)b * LQ_ + qB + tid) * 16 + blockIdx.y] =
            zc[tid] + zc[128 + tid] + zc[256 + tid] + zc[384 + tid];
    }
}

// =====================================================================
// k_T: T[q][d] = rZ2[q] * sum_c E[c,q]*Cm[d,c]. k64 x32, 3-stage, 1 sync.
// =====================================================================
#define KT_RZ 0
#define KT_BUF 1024
#define KT_DYN (1024 + 3 * 65536)

__global__ void __launch_bounds__(512, 1) k_T() {
    extern __shared__ char sm[];
    u32 sb = s2u(sm);
    int tid = threadIdx.x, lane = tid & 31, wid = tid >> 5;
    int b = blockIdx.y, qB = blockIdx.x * 128;
    float* rzs = (float*)(sm + KT_RZ);
    if (tid < 128) {
        const float* p = &g_Z2p[((size_t)b * LQ_ + qB + tid) * 16];
        float s = 0.f;
        #pragma unroll
        for (int t = 0; t < 16; t++) s += p[t];
        rzs[tid] = 1.f / fmaxf(s, 1e-30f);
    }
    const __nv_bfloat16* EH = (const __nv_bfloat16*)g_Ehi;
    const __nv_bfloat16* EL = (const __nv_bfloat16*)g_Elo;
    const __nv_bfloat16* CH = (const __nv_bfloat16*)g_Cmhi;
    const __nv_bfloat16* CL = (const __nv_bfloat16*)g_Cmlo;
    size_t Eoff = (size_t)(b * LC_) * LQ_ + qB;
    size_t Coff = (size_t)(b * D_) * LC_;

    #pragma unroll
    for (int pc = 0; pc < 2; pc++) {
        u32 st = sb + KT_BUF + pc * 65536;
        cpyT64<512> (st,         EH + Eoff + (size_t)(pc * 64) * LQ_, EL + Eoff + (size_t)(pc * 64) * LQ_, LQ_, tid);
        cpyN128<512>(st + 32768, CH + Coff + pc * 64,                 CL + Coff + pc * 64,                 LC_, tid);
        CP_COMMIT();
    }

    int wm = wid >> 2, wn = wid & 3;
    int m0w = wm * 32, n0w = wn * 32;
    float acc[2][4][4] = {};
    for (int ci = 0; ci < 32; ci++) {
        if (ci < 31) CP_WAIT1(); else CP_WAIT0();
        __syncthreads();
        if (ci < 30) {
            int c0 = (ci + 2) * 64;
            u32 st = sb + KT_BUF + ((ci + 2) % 3) * 65536;
            cpyT64<512> (st,         EH + Eoff + (size_t)c0 * LQ_, EL + Eoff + (size_t)c0 * LQ_, LQ_, tid);
            cpyN128<512>(st + 32768, CH + Coff + c0,               CL + Coff + c0,               LC_, tid);
            CP_COMMIT();
        }
        u32 bb = sb + KT_BUF + (ci % 3) * 65536;
        mma_chunk<2, 1, 0, 4, 8192>(acc, bb, bb + 32768, m0w, n0w, lane);
    }

    int r = lane >> 2, cp = (lane & 3) * 2;
    #pragma unroll
    for (int mi = 0; mi < 2; mi++) {
        int q0 = m0w + mi * 16 + r;
        float rza = rzs[q0], rzb = rzs[q0 + 8];
        #pragma unroll
        for (int nj = 0; nj < 4; nj++) {
            int d0 = n0w + nj * 8 + cp;
            u32 h0, l0, h1, l1;
            size_t i0 = ((size_t)(b * LQ_ + qB + q0) * D_ + d0) >> 1;
            size_t i1 = ((size_t)(b * LQ_ + qB + q0 + 8) * D_ + d0) >> 1;
            splt(acc[mi][nj][0] * rza, h0, l0); splt(acc[mi][nj][1] * rza, h1, l1);
            g_Thi[i0] = h0 | (h1 << 16); g_Tlo[i0] = l0 | (l1 << 16);
            splt(acc[mi][nj][2] * rzb, h0, l0); splt(acc[mi][nj][3] * rzb, h1, l1);
            g_Thi[i1] = h0 | (h1 << 16); g_Tlo[i1] = l0 | (l1 << 16);
        }
    }
}

// =====================================================================
// k_AB (fused): pass0 D=E@Qt -> sections 0,1,2; pass1 D=E@T -> section 3.
//   k64 x8 per pass, 3-stage, 1 sync per chunk.
// =====================================================================
#define KA_RZ 0
#define KA_BUF 1024
#define KA_DYN (1024 + 3 * 65536)

__global__ void __launch_bounds__(512, 1) k_AB(const float* __restrict__ C,
                                               float* __restrict__ out) {
    extern __shared__ char sm[];
    u32 sb = s2u(sm);
    int tid = threadIdx.x, lane = tid & 31, wid = tid >> 5;
    int b = blockIdx.y, cB = blockIdx.x * 128;
    float* rzs = (float*)(sm + KA_RZ);
    if (tid < 128) {
        const float* p = &g_Z1p[((size_t)b * LC_ + cB + tid) * 4];
        rzs[tid] = 1.f / (p[0] + p[1] + p[2] + p[3]);
    }
    const __nv_bfloat16* EH = (const __nv_bfloat16*)g_Ehi;
    const __nv_bfloat16* EL = (const __nv_bfloat16*)g_Elo;
    const __nv_bfloat16* QH = (const __nv_bfloat16*)g_Qhi;
    const __nv_bfloat16* QL = (const __nv_bfloat16*)g_Qlo;
    const __nv_bfloat16* TH = (const __nv_bfloat16*)g_Thi;
    const __nv_bfloat16* TL = (const __nv_bfloat16*)g_Tlo;
    size_t Eoff = ((size_t)b * LC_ + cB) * LQ_;
    size_t Qoff = (size_t)(b * D_) * LQ_;
    size_t Toff = (size_t)(b * LQ_) * D_;
    const float* Cb = C + (size_t)b * D_ * LC_ + cB;
    float* ob = out + (size_t)b * 4 * D_ * LC_ + cB;
    float* stg = (float*)(sm + KA_BUF);
    int wm = wid >> 2, wn = wid & 3;
    int m0w = wm * 32, n0w = wn * 32;
    int r = lane >> 2, cp = (lane & 3) * 2;

    #pragma unroll 1
    for (int pass = 0; pass < 2; pass++) {
        // prologue: chunks 0,1
        #pragma unroll
        for (int pc = 0; pc < 2; pc++) {
            u32 st = sb + KA_BUF + pc * 65536;
            int q0 = pc * 64;
            cpyN128<512>(st, EH + Eoff + q0, EL + Eoff + q0, LQ_, tid);
            if (pass == 0) cpyN128<512>(st + 32768, QH + Qoff + q0, QL + Qoff + q0, LQ_, tid);
            else           cpyT64<512> (st + 32768, TH + Toff + (size_t)q0 * D_, TL + Toff + (size_t)q0 * D_, D_, tid);
            CP_COMMIT();
        }

        float acc[2][4][4] = {};
        for (int ci = 0; ci < 8; ci++) {
            if (ci < 7) CP_WAIT1(); else CP_WAIT0();
            __syncthreads();
            if (ci < 6) {
                int q0 = (ci + 2) * 64;
                u32 st = sb + KA_BUF + ((ci + 2) % 3) * 65536;
                cpyN128<512>(st, EH + Eoff + q0, EL + Eoff + q0, LQ_, tid);
                if (pass == 0) cpyN128<512>(st + 32768, QH + Qoff + q0, QL + Qoff + q0, LQ_, tid);
                else           cpyT64<512> (st + 32768, TH + Toff + (size_t)q0 * D_, TL + Toff + (size_t)q0 * D_, D_, tid);
                CP_COMMIT();
            }
            u32 bb = sb + KA_BUF + (ci % 3) * 65536;
            if (pass == 0) mma_chunk<2, 0, 0, 4, 8192>(acc, bb, bb + 32768, m0w, n0w, lane);
            else           mma_chunk<2, 0, 1, 4, 8192>(acc, bb, bb + 32768, m0w, n0w, lane);
        }
        __syncthreads();   // buffers free before stage writes

        // stage [d][c] (pitch 132) with rZ1
        #pragma unroll
        for (int mi = 0; mi < 2; mi++) {
            int m0 = m0w + mi * 16 + r;
            float rza = rzs[m0], rzb = rzs[m0 + 8];
            #pragma unroll
            for (int nj = 0; nj < 4; nj++) {
                int n0 = n0w + nj * 8 + cp;
                stg[n0 * 132 + m0]           = acc[mi][nj][0] * rza;
                stg[(n0 + 1) * 132 + m0]     = acc[mi][nj][1] * rza;
                stg[n0 * 132 + m0 + 8]       = acc[mi][nj][2] * rzb;
                stg[(n0 + 1) * 132 + m0 + 8] = acc[mi][nj][3] * rzb;
            }
        }
        __syncthreads();
        if (pass == 0) {
            for (int idx = tid; idx < 128 * 128; idx += 512) {
                int dd = idx >> 7, c = idx & 127;
                float a = stg[dd * 132 + c];
                float cv = Cb[(size_t)dd * LC_ + c];
                ob[(size_t)dd * LC_ + c]         = cv;
                ob[(size_t)(128 + dd) * LC_ + c] = a;
                ob[(size_t)(256 + dd) * LC_ + c] = cv * a;
            }
        } else {
            for (int idx = tid; idx < 128 * 128; idx += 512) {
                int dd = idx >> 7, c = idx & 127;
                float bm = stg[dd * 132 + c];
                float cv = Cb[(size_t)dd * LC_ + c];
                ob[(size_t)(384 + dd) * LC_ + c] = cv * bm;
            }
        }
        __syncthreads();
    }
}

// =====================================================================
extern "C" void kernel_launch(void* const* d_in, const int* in_sizes, int n_in,
                              void* d_out, int out_size) {
    const float* C     = (const float*)d_in[0];
    const float* Q     = (const float*)d_in[1];
    const int*   Cmask = (const int*)  d_in[2];
    const int*   Qmask = (const int*)  d_in[3];
    const float* w_c   = (const float*)d_in[4];
    const float* w_q   = (const float*)d_in[5];
    const float* w_mul = (const float*)d_in[6];
    const float* bias  = (const float*)d_in[7];
    float* out = (float*)d_out;

    cudaFuncSetAttribute(k_S,  cudaFuncAttributeMaxDynamicSharedMemorySize, KS_DYN);
    cudaFuncSetAttribute(k_T,  cudaFuncAttributeMaxDynamicSharedMemorySize, KT_DYN);
    cudaFuncSetAttribute(k_AB, cudaFuncAttributeMaxDynamicSharedMemorySize, KA_DYN);

    k_cvtC<<<(B_ * D_ * LC_ / 4) / 256, 256>>>(C, Cmask, w_mul);
    k_cvtQ<<<(B_ * D_ * LQ_ / 4) / 256, 256>>>(Q);
    k_vec<<<320, 256>>>(C, Q, w_c, w_q, bias);
    k_S<<<dim3(4, 16, 32), 512, KS_DYN>>>(Qmask, Cmask);
    k_T<<<dim3(4, 32), 512, KT_DYN>>>();
    k_AB<<<dim3(16, 32), 512, KA_DYN>>>(C, out);
}

// round 11
// speedup vs baseline: 1.1591x; 1.0774x over previous
#include <cuda_runtime.h>
#include <cuda_bf16.h>
#include <cstdint>

#define B_   32
#define D_   128
#define LC_  2048
#define LQ_  512

typedef unsigned int u32;

// ---------------- scratch planes (bf16 hi/lo stored as u32 pairs) ----------
__device__ u32 g_Ehi[(size_t)B_ * LC_ * LQ_ / 2];
__device__ u32 g_Elo[(size_t)B_ * LC_ * LQ_ / 2];
__device__ u32 g_Cwhi[(size_t)B_ * D_ * LC_ / 2];
__device__ u32 g_Cwlo[(size_t)B_ * D_ * LC_ / 2];
__device__ u32 g_Cmhi[(size_t)B_ * D_ * LC_ / 2];
__device__ u32 g_Cmlo[(size_t)B_ * D_ * LC_ / 2];
__device__ u32 g_Qhi[(size_t)B_ * D_ * LQ_ / 2];
__device__ u32 g_Qlo[(size_t)B_ * D_ * LQ_ / 2];
__device__ u32 g_Thi[(size_t)B_ * LQ_ * D_ / 2];
__device__ u32 g_Tlo[(size_t)B_ * LQ_ * D_ / 2];
__device__ float g_s0[B_ * LC_];
__device__ float g_s1[B_ * LQ_];
__device__ float g_Z1p[B_ * LC_ * 4];
__device__ float g_Z2p[B_ * LQ_ * 16];

// ---------------- helpers ----------------
__device__ __forceinline__ u32 s2u(const void* p) {
    u32 a; asm("{ .reg .u64 t; cvta.to.shared.u64 t, %1; cvt.u32.u64 %0, t; }" : "=r"(a) : "l"(p));
    return a;
}
#define SWZ(x) ((u32)(x) ^ ((((u32)(x)) >> 3) & 0x70))

__device__ __forceinline__ void cpa16(u32 dst, const void* src) {
    asm volatile("cp.async.cg.shared.global [%0], [%1], 16;" :: "r"(dst), "l"(src));
}
#define CP_COMMIT() asm volatile("cp.async.commit_group;")
#define CP_WAIT0()  asm volatile("cp.async.wait_group 0;")
#define CP_WAIT1()  asm volatile("cp.async.wait_group 1;")

__device__ __forceinline__ void splt(float v, u32 &hi, u32 &lo) {
    __nv_bfloat16 h = __float2bfloat16(v);
    float hf = __bfloat162float(h);
    __nv_bfloat16 l = __float2bfloat16(v - hf);
    hi = (u32)__bfloat16_as_ushort(h);
    lo = (u32)__bfloat16_as_ushort(l);
}

__device__ __forceinline__ void ldsm4(u32 addr, u32 r[4]) {
    asm volatile("ldmatrix.sync.aligned.m8n8.x4.shared.b16 {%0,%1,%2,%3}, [%4];"
                 : "=r"(r[0]), "=r"(r[1]), "=r"(r[2]), "=r"(r[3]) : "r"(addr));
}
__device__ __forceinline__ void ldsm4t(u32 addr, u32 r[4]) {
    asm volatile("ldmatrix.sync.aligned.m8n8.x4.trans.shared.b16 {%0,%1,%2,%3}, [%4];"
                 : "=r"(r[0]), "=r"(r[1]), "=r"(r[2]), "=r"(r[3]) : "r"(addr));
}
__device__ __forceinline__ void hmma(float d[4], const u32 a[4], u32 b0, u32 b1) {
    asm volatile("mma.sync.aligned.m16n8k16.row.col.f32.bf16.bf16.f32 "
                 "{%0,%1,%2,%3}, {%4,%5,%6,%7}, {%8,%9}, {%0,%1,%2,%3};"
                 : "+f"(d[0]), "+f"(d[1]), "+f"(d[2]), "+f"(d[3])
                 : "r"(a[0]), "r"(a[1]), "r"(a[2]), "r"(a[3]), "r"(b0), "r"(b1));
}
__device__ __forceinline__ uint4 lds128(u32 a) {
    uint4 v;
    asm volatile("ld.shared.v4.b32 {%0,%1,%2,%3}, [%4];"
                 : "=r"(v.x), "=r"(v.y), "=r"(v.z), "=r"(v.w) : "r"(a));
    return v;
}
__device__ __forceinline__ void sts32(u32 a, u32 v) { asm volatile("st.shared.b32 [%0], %1;" :: "r"(a), "r"(v)); }

// ---------------- chunk copies ----------------
// k-major panel, k=64 rows x 128 cols, 2 limbs (32KB). Sub-panels 8KB, SW128.
template<int NT>
__device__ __forceinline__ void cpyT64(u32 dstBase, const __nv_bfloat16* srcHi,
                                       const __nv_bfloat16* srcLo, size_t rowStride, int tid) {
    #pragma unroll
    for (int t = 0; t < 2048 / NT; t++) {
        int u = tid + t * NT;
        int limb = u >> 10, rem = u & 1023;
        int row = rem >> 4, ucol = rem & 15;
        const __nv_bfloat16* src = (limb ? srcLo : srcHi) + (size_t)row * rowStride + ucol * 8;
        u32 dst = dstBase + limb * 16384 + (ucol >> 3) * 8192 + SWZ(row * 128 + (ucol & 7) * 16);
        cpa16(dst, src);
    }
}
// k-major panel, k=32 rows x 128 cols, 2 limbs (16KB). Sub-panels 4KB, SW128.
template<int NT>
__device__ __forceinline__ void cpyT32(u32 dstBase, const __nv_bfloat16* srcHi,
                                       const __nv_bfloat16* srcLo, size_t rowStride, int tid) {
    #pragma unroll
    for (int t = 0; t < 1024 / NT; t++) {
        int u = tid + t * NT;
        int limb = u >> 9, rem = u & 511;
        int row = rem >> 4, ucol = rem & 15;
        const __nv_bfloat16* src = (limb ? srcLo : srcHi) + (size_t)row * rowStride + ucol * 8;
        u32 dst = dstBase + limb * 8192 + (ucol >> 3) * 4096 + SWZ(row * 128 + (ucol & 7) * 16);
        cpa16(dst, src);
    }
}
// row-major panel, 128 rows x k=64 cols, 2 limbs (32KB). 128B rows, SW128.
template<int NT>
__device__ __forceinline__ void cpyN128(u32 dstBase, const __nv_bfloat16* srcHi,
                                        const __nv_bfloat16* srcLo, size_t rowStride, int tid) {
    #pragma unroll
    for (int t = 0; t < 2048 / NT; t++) {
        int u = tid + t * NT;
        int limb = u >> 10, rem = u & 1023;
        int row = rem >> 3, ucol = rem & 7;
        const __nv_bfloat16* src = (limb ? srcLo : srcHi) + (size_t)row * rowStride + ucol * 8;
        u32 dst = dstBase + limb * 16384 + SWZ(row * 128 + ucol * 16);
        cpa16(dst, src);
    }
}

// ---------------- warp MMA over one chunk (3-limb) -------------------------
// SUB: k-major sub-panel bytes (8192 for k64, 4096 for k32); lo limb at +2*SUB.
template<int MI, int AT, int BT, int KSTEPS, int SUB>
__device__ __forceinline__ void mma_chunk(float acc[MI][4][4], u32 Ab, u32 Bb,
                                          int m0w, int n0w, int lane) {
    const int LO = 2 * SUB;
    #pragma unroll
    for (int ks = 0; ks < KSTEPS; ks++) {
        int k0 = ks * 16;
        u32 ah[MI][4], al[MI][4];
        #pragma unroll
        for (int mi = 0; mi < MI; mi++) {
            int m0 = m0w + mi * 16;
            u32 ad;
            if (AT) {
                int r = k0 + (lane & 7) + ((lane & 16) ? 8 : 0);
                int c = m0 + ((lane & 8) ? 8 : 0);
                ad = Ab + ((u32)(c >> 6)) * SUB + SWZ(r * 128 + (c & 63) * 2);
                ldsm4t(ad, ah[mi]); ldsm4t(ad + LO, al[mi]);
            } else {
                int r = m0 + (lane & 15);
                int c = k0 + ((lane >> 4) << 3);
                ad = Ab + SWZ(r * 128 + c * 2);
                ldsm4(ad, ah[mi]); ldsm4(ad + LO, al[mi]);
            }
        }
        u32 bh[4][2], bl[4][2];
        #pragma unroll
        for (int nj2 = 0; nj2 < 2; nj2++) {
            int n0 = n0w + nj2 * 16;
            u32 bd;
            u32 t[4], tl[4];
            if (BT) {
                int r = k0 + (lane & 7) + ((lane & 8) ? 8 : 0);
                int c = n0 + ((lane & 16) ? 8 : 0);
                bd = Bb + ((u32)(c >> 6)) * SUB + SWZ(r * 128 + (c & 63) * 2);
                ldsm4t(bd, t); ldsm4t(bd + LO, tl);
            } else {
                int r = n0 + (lane & 7) + ((lane & 16) ? 8 : 0);
                int c = k0 + ((lane & 8) ? 8 : 0);
                bd = Bb + SWZ(r * 128 + c * 2);
                ldsm4(bd, t); ldsm4(bd + LO, tl);
            }
            bh[nj2 * 2][0] = t[0];  bh[nj2 * 2][1] = t[1];
            bh[nj2 * 2 + 1][0] = t[2]; bh[nj2 * 2 + 1][1] = t[3];
            bl[nj2 * 2][0] = tl[0]; bl[nj2 * 2][1] = tl[1];
            bl[nj2 * 2 + 1][0] = tl[2]; bl[nj2 * 2 + 1][1] = tl[3];
        }
        #pragma unroll
        for (int mi = 0; mi < MI; mi++)
            #pragma unroll
            for (int nj = 0; nj < 4; nj++) {
                hmma(acc[mi][nj], ah[mi], bh[nj][0], bh[nj][1]);
                hmma(acc[mi][nj], ah[mi], bl[nj][0], bl[nj][1]);
                hmma(acc[mi][nj], al[mi], bh[nj][0], bh[nj][1]);
            }
    }
}

// =====================================================================
// k_cvtC: C -> Cw/Cm limb planes, fused s0 = Ct.w_c + bias
//   grid (16 ctiles, 32 b), 256 threads: cp = tid&63 (c-pair), dq = tid>>6
// =====================================================================
__global__ void __launch_bounds__(256) k_cvtC(const float* __restrict__ C,
                                              const int* __restrict__ Cmask,
                                              const float* __restrict__ w_mul,
                                              const float* __restrict__ w_c,
                                              const float* __restrict__ bias) {
    __shared__ float wc[128], wm[128], zb[512];
    int tid = threadIdx.x;
    int b = blockIdx.y, cB = blockIdx.x * 128;
    if (tid < 128) { wc[tid] = w_c[tid]; wm[tid] = w_mul[tid]; }
    __syncthreads();
    int cp = tid & 63, dq = tid >> 6;
    int c0 = cB + 2 * cp;
    int m0 = Cmask[b * LC_ + c0], m1 = Cmask[b * LC_ + c0 + 1];
    float fm0 = m0 ? 1.f : 0.f, fm1 = m1 ? 1.f : 0.f;
    float s0e = 0.f, s0o = 0.f;
    #pragma unroll 4
    for (int i = 0; i < 32; i++) {
        int d = dq * 32 + i;
        size_t gi = ((size_t)(b * D_ + d)) * LC_ + c0;
        float2 v = *(const float2*)(C + gi);
        s0e += v.x * wc[d]; s0o += v.y * wc[d];
        u32 h0, l0, h1, l1;
        splt(v.x * wm[d], h0, l0); splt(v.y * wm[d], h1, l1);
        g_Cwhi[gi >> 1] = h0 | (h1 << 16);
        g_Cwlo[gi >> 1] = l0 | (l1 << 16);
        splt(v.x * fm0, h0, l0); splt(v.y * fm1, h1, l1);
        g_Cmhi[gi >> 1] = h0 | (h1 << 16);
        g_Cmlo[gi >> 1] = l0 | (l1 << 16);
    }
    zb[dq * 128 + 2 * cp] = s0e;
    zb[dq * 128 + 2 * cp + 1] = s0o;
    __syncthreads();
    if (tid < 128)
        g_s0[b * LC_ + cB + tid] = zb[tid] + zb[128 + tid] + zb[256 + tid] + zb[384 + tid] + bias[0];
}

// =====================================================================
// k_cvtQ: Q -> limb planes, fused s1 = Qt.w_q
//   grid (32 b), 512 threads: qp = tid&255 (q-pair), dh = tid>>8
// =====================================================================
__global__ void __launch_bounds__(512) k_cvtQ(const float* __restrict__ Q,
                                              const float* __restrict__ w_q) {
    __shared__ float wq[128], zb[1024];
    int tid = threadIdx.x;
    int b = blockIdx.x;
    if (tid < 128) wq[tid] = w_q[tid];
    __syncthreads();
    int qp = tid & 255, dh = tid >> 8;
    int q0 = 2 * qp;
    float s1e = 0.f, s1o = 0.f;
    #pragma unroll 4
    for (int i = 0; i < 64; i++) {
        int d = dh * 64 + i;
        size_t gi = ((size_t)(b * D_ + d)) * LQ_ + q0;
        float2 v = *(const float2*)(Q + gi);
        s1e += v.x * wq[d]; s1o += v.y * wq[d];
        u32 h0, l0, h1, l1;
        splt(v.x, h0, l0); splt(v.y, h1, l1);
        g_Qhi[gi >> 1] = h0 | (h1 << 16);
        g_Qlo[gi >> 1] = l0 | (l1 << 16);
    }
    zb[dh * 512 + q0]     = s1e;
    zb[dh * 512 + q0 + 1] = s1o;
    __syncthreads();
    g_s1[b * LQ_ + tid] = zb[tid] + zb[512 + tid];
}

// =====================================================================
// k_S: E = qmask*exp(Cw@Qt^T + s0 + s1). 256 thr, 2 CTAs/SM, m64n32 tiles.
//   exp-heavy epilogue of one CTA overlaps mainloop of the co-resident CTA.
// =====================================================================
#define KS_S0 0
#define KS_S1 512
#define KS_QM 1024
#define KS_CM 1536
#define KS_ZS 2048      // 512 f
#define KS_ZC 4096      // 256 f
#define KS_BUF 8192     // 3 stages x 32KB
#define KS_DYN (8192 + 3 * 32768)

__global__ void __launch_bounds__(256, 2) k_S(const int* __restrict__ Qmask,
                                              const int* __restrict__ Cmask) {
    extern __shared__ char sm[];
    u32 sb = s2u(sm);
    int tid = threadIdx.x, lane = tid & 31, wid = tid >> 5;
    int b = blockIdx.z, cB = blockIdx.y * 128, qB = blockIdx.x * 128, qt = blockIdx.x;
    float* s0f = (float*)(sm + KS_S0);
    float* s1f = (float*)(sm + KS_S1);
    int*   qmi = (int*)(sm + KS_QM);
    float* cmk = (float*)(sm + KS_CM);
    float* zs  = (float*)(sm + KS_ZS);
    float* zc  = (float*)(sm + KS_ZC);
    if (tid < 128) {
        s0f[tid] = g_s0[b * LC_ + cB + tid];
        s1f[tid] = g_s1[b * LQ_ + qB + tid];
        qmi[tid] = Qmask[b * LQ_ + qB + tid];
        cmk[tid] = (float)Cmask[b * LC_ + cB + tid];
    }

    const __nv_bfloat16* CwH = (const __nv_bfloat16*)g_Cwhi;
    const __nv_bfloat16* CwL = (const __nv_bfloat16*)g_Cwlo;
    const __nv_bfloat16* QH  = (const __nv_bfloat16*)g_Qhi;
    const __nv_bfloat16* QL  = (const __nv_bfloat16*)g_Qlo;
    size_t Ca = (size_t)(b * D_) * LC_ + cB;
    size_t Qa = (size_t)(b * D_) * LQ_ + qB;

    // prologue: chunks 0,1
    #pragma unroll
    for (int pc = 0; pc < 2; pc++) {
        u32 st = sb + KS_BUF + pc * 32768;
        cpyT32<256>(st,         CwH + Ca + (size_t)(pc * 32) * LC_, CwL + Ca + (size_t)(pc * 32) * LC_, LC_, tid);
        cpyT32<256>(st + 16384, QH  + Qa + (size_t)(pc * 32) * LQ_, QL  + Qa + (size_t)(pc * 32) * LQ_, LQ_, tid);
        CP_COMMIT();
    }

    int wm = wid >> 2, wn = wid & 3;
    int m0w = wm * 64, n0w = wn * 32;
    float acc[4][4][4] = {};
    #pragma unroll
    for (int ci = 0; ci < 4; ci++) {
        if (ci < 3) CP_WAIT1(); else CP_WAIT0();
        __syncthreads();
        if (ci < 2) {
            int k0 = (ci + 2) * 32;
            u32 st = sb + KS_BUF + ((ci + 2) % 3) * 32768;
            cpyT32<256>(st,         CwH + Ca + (size_t)k0 * LC_, CwL + Ca + (size_t)k0 * LC_, LC_, tid);
            cpyT32<256>(st + 16384, QH  + Qa + (size_t)k0 * LQ_, QL  + Qa + (size_t)k0 * LQ_, LQ_, tid);
            CP_COMMIT();
        }
        u32 bb = sb + KS_BUF + (ci % 3) * 32768;
        mma_chunk<4, 1, 1, 2, 4096>(acc, bb, bb + 16384, m0w, n0w, lane);
    }
    __syncthreads();   // all warps done with buffers before stage overwrite

    // epilogue: exp + split + smem staging (reuses MMA buffers)
    int r = lane >> 2, cp = (lane & 3) * 2;
    float zrow[8] = {}, zcol[8] = {};
    u32 stg = sb + KS_BUF;   // hi plane 128*272; lo at +34816
    #pragma unroll
    for (int mi = 0; mi < 4; mi++) {
        int m0 = m0w + mi * 16 + r;
        float s0a = s0f[m0], s0b = s0f[m0 + 8];
        float cma = cmk[m0], cmb = cmk[m0 + 8];
        #pragma unroll
        for (int nj = 0; nj < 4; nj++) {
            int q0 = n0w + nj * 8 + cp;
            float s1a = s1f[q0], s1b = s1f[q0 + 1];
            int qa = qmi[q0], qb = qmi[q0 + 1];
            float e00 = qa ? __expf(acc[mi][nj][0] + s0a + s1a) : 0.f;
            float e01 = qb ? __expf(acc[mi][nj][1] + s0a + s1b) : 0.f;
            float e10 = qa ? __expf(acc[mi][nj][2] + s0b + s1a) : 0.f;
            float e11 = qb ? __expf(acc[mi][nj][3] + s0b + s1b) : 0.f;
            zrow[mi * 2]     += e00 + e01;
            zrow[mi * 2 + 1] += e10 + e11;
            zcol[nj * 2]     += cma * e00 + cmb * e10;
            zcol[nj * 2 + 1] += cma * e01 + cmb * e11;
            u32 h00, l00, h01, l01, h10, l10, h11, l11;
            splt(e00, h00, l00); splt(e01, h01, l01);
            splt(e10, h10, l10); splt(e11, h11, l11);
            sts32(stg + m0 * 272 + q0 * 2,               h00 | (h01 << 16));
            sts32(stg + 34816 + m0 * 272 + q0 * 2,       l00 | (l01 << 16));
            sts32(stg + (m0 + 8) * 272 + q0 * 2,         h10 | (h11 << 16));
            sts32(stg + 34816 + (m0 + 8) * 272 + q0 * 2, l10 | (l11 << 16));
        }
    }
    #pragma unroll
    for (int h = 0; h < 8; h++) {
        float v = zrow[h];
        v += __shfl_xor_sync(0xffffffffu, v, 1);
        v += __shfl_xor_sync(0xffffffffu, v, 2);
        if ((lane & 3) == 0) {
            int m = m0w + (h >> 1) * 16 + ((h & 1) ? 8 : 0) + r;
            zs[m * 4 + wn] = v;
        }
    }
    #pragma unroll
    for (int j = 0; j < 8; j++) {
        float v = zcol[j];
        v += __shfl_xor_sync(0xffffffffu, v, 4);
        v += __shfl_xor_sync(0xffffffffu, v, 8);
        v += __shfl_xor_sync(0xffffffffu, v, 16);
        zcol[j] = v;
    }
    if (lane < 4) {
        #pragma unroll
        for (int nj = 0; nj < 4; nj++) {
            zc[wm * 128 + n0w + nj * 8 + lane * 2]     = zcol[nj * 2];
            zc[wm * 128 + n0w + nj * 8 + lane * 2 + 1] = zcol[nj * 2 + 1];
        }
    }
    __syncthreads();
    // coalesced copy stage -> global (4096 16B chunks)
    #pragma unroll
    for (int it = 0; it < 16; it++) {
        int idx = tid + it * 256;
        int chunk = idx & 15, c = (idx >> 4) & 127, plane = idx >> 11;
        uint4 v = lds128(stg + plane * 34816 + c * 272 + chunk * 16);
        uint4* dst = plane ? (uint4*)g_Elo : (uint4*)g_Ehi;
        dst[((((size_t)(b * LC_ + cB + c)) * LQ_ + qB) >> 3) + chunk] = v;
    }
    if (tid < 128) {
        g_Z1p[((size_t)b * LC_ + cB + tid) * 4 + qt] =
            zs[tid * 4] + zs[tid * 4 + 1] + zs[tid * 4 + 2] + zs[tid * 4 + 3];
        g_Z2p[((size_t)b * LQ_ + qB + tid) * 16 + blockIdx.y] = zc[tid] + zc[128 + tid];
    }
}

// =====================================================================
// k_T: T[q][d] = rZ2[q] * sum_c E[c,q]*Cm[d,c]. k64 x32, 3-stage, 1 sync.
// =====================================================================
#define KT_RZ 0
#define KT_BUF 1024
#define KT_DYN (1024 + 3 * 65536)

__global__ void __launch_bounds__(512, 1) k_T() {
    extern __shared__ char sm[];
    u32 sb = s2u(sm);
    int tid = threadIdx.x, lane = tid & 31, wid = tid >> 5;
    int b = blockIdx.y, qB = blockIdx.x * 128;
    float* rzs = (float*)(sm + KT_RZ);
    if (tid < 128) {
        const float* p = &g_Z2p[((size_t)b * LQ_ + qB + tid) * 16];
        float s = 0.f;
        #pragma unroll
        for (int t = 0; t < 16; t++) s += p[t];
        rzs[tid] = 1.f / fmaxf(s, 1e-30f);
    }
    const __nv_bfloat16* EH = (const __nv_bfloat16*)g_Ehi;
    const __nv_bfloat16* EL = (const __nv_bfloat16*)g_Elo;
    const __nv_bfloat16* CH = (const __nv_bfloat16*)g_Cmhi;
    const __nv_bfloat16* CL = (const __nv_bfloat16*)g_Cmlo;
    size_t Eoff = (size_t)(b * LC_) * LQ_ + qB;
    size_t Coff = (size_t)(b * D_) * LC_;

    #pragma unroll
    for (int pc = 0; pc < 2; pc++) {
        u32 st = sb + KT_BUF + pc * 65536;
        cpyT64<512> (st,         EH + Eoff + (size_t)(pc * 64) * LQ_, EL + Eoff + (size_t)(pc * 64) * LQ_, LQ_, tid);
        cpyN128<512>(st + 32768, CH + Coff + pc * 64,                 CL + Coff + pc * 64,                 LC_, tid);
        CP_COMMIT();
    }

    int wm = wid >> 2, wn = wid & 3;
    int m0w = wm * 32, n0w = wn * 32;
    float acc[2][4][4] = {};
    for (int ci = 0; ci < 32; ci++) {
        if (ci < 31) CP_WAIT1(); else CP_WAIT0();
        __syncthreads();
        if (ci < 30) {
            int c0 = (ci + 2) * 64;
            u32 st = sb + KT_BUF + ((ci + 2) % 3) * 65536;
            cpyT64<512> (st,         EH + Eoff + (size_t)c0 * LQ_, EL + Eoff + (size_t)c0 * LQ_, LQ_, tid);
            cpyN128<512>(st + 32768, CH + Coff + c0,               CL + Coff + c0,               LC_, tid);
            CP_COMMIT();
        }
        u32 bb = sb + KT_BUF + (ci % 3) * 65536;
        mma_chunk<2, 1, 0, 4, 8192>(acc, bb, bb + 32768, m0w, n0w, lane);
    }

    int r = lane >> 2, cp = (lane & 3) * 2;
    #pragma unroll
    for (int mi = 0; mi < 2; mi++) {
        int q0 = m0w + mi * 16 + r;
        float rza = rzs[q0], rzb = rzs[q0 + 8];
        #pragma unroll
        for (int nj = 0; nj < 4; nj++) {
            int d0 = n0w + nj * 8 + cp;
            u32 h0, l0, h1, l1;
            size_t i0 = ((size_t)(b * LQ_ + qB + q0) * D_ + d0) >> 1;
            size_t i1 = ((size_t)(b * LQ_ + qB + q0 + 8) * D_ + d0) >> 1;
            splt(acc[mi][nj][0] * rza, h0, l0); splt(acc[mi][nj][1] * rza, h1, l1);
            g_Thi[i0] = h0 | (h1 << 16); g_Tlo[i0] = l0 | (l1 << 16);
            splt(acc[mi][nj][2] * rzb, h0, l0); splt(acc[mi][nj][3] * rzb, h1, l1);
            g_Thi[i1] = h0 | (h1 << 16); g_Tlo[i1] = l0 | (l1 << 16);
        }
    }
}

// =====================================================================
// k_AB (fused): pass0 D=E@Qt -> sections 0,1,2; pass1 D=E@T -> section 3.
// =====================================================================
#define KA_RZ 0
#define KA_BUF 1024
#define KA_DYN (1024 + 3 * 65536)

__global__ void __launch_bounds__(512, 1) k_AB(const float* __restrict__ C,
                                               float* __restrict__ out) {
    extern __shared__ char sm[];
    u32 sb = s2u(sm);
    int tid = threadIdx.x, lane = tid & 31, wid = tid >> 5;
    int b = blockIdx.y, cB = blockIdx.x * 128;
    float* rzs = (float*)(sm + KA_RZ);
    if (tid < 128) {
        const float* p = &g_Z1p[((size_t)b * LC_ + cB + tid) * 4];
        rzs[tid] = 1.f / (p[0] + p[1] + p[2] + p[3]);
    }
    const __nv_bfloat16* EH = (const __nv_bfloat16*)g_Ehi;
    const __nv_bfloat16* EL = (const __nv_bfloat16*)g_Elo;
    const __nv_bfloat16* QH = (const __nv_bfloat16*)g_Qhi;
    const __nv_bfloat16* QL = (const __nv_bfloat16*)g_Qlo;
    const __nv_bfloat16* TH = (const __nv_bfloat16*)g_Thi;
    const __nv_bfloat16* TL = (const __nv_bfloat16*)g_Tlo;
    size_t Eoff = ((size_t)b * LC_ + cB) * LQ_;
    size_t Qoff = (size_t)(b * D_) * LQ_;
    size_t Toff = (size_t)(b * LQ_) * D_;
    const float* Cb = C + (size_t)b * D_ * LC_ + cB;
    float* ob = out + (size_t)b * 4 * D_ * LC_ + cB;
    float* stg = (float*)(sm + KA_BUF);
    int wm = wid >> 2, wn = wid & 3;
    int m0w = wm * 32, n0w = wn * 32;
    int r = lane >> 2, cp = (lane & 3) * 2;

    #pragma unroll 1
    for (int pass = 0; pass < 2; pass++) {
        // prologue: chunks 0,1
        #pragma unroll
        for (int pc = 0; pc < 2; pc++) {
            u32 st = sb + KA_BUF + pc * 65536;
            int q0 = pc * 64;
            cpyN128<512>(st, EH + Eoff + q0, EL + Eoff + q0, LQ_, tid);
            if (pass == 0) cpyN128<512>(st + 32768, QH + Qoff + q0, QL + Qoff + q0, LQ_, tid);
            else           cpyT64<512> (st + 32768, TH + Toff + (size_t)q0 * D_, TL + Toff + (size_t)q0 * D_, D_, tid);
            CP_COMMIT();
        }

        float acc[2][4][4] = {};
        for (int ci = 0; ci < 8; ci++) {
            if (ci < 7) CP_WAIT1(); else CP_WAIT0();
            __syncthreads();
            if (ci < 6) {
                int q0 = (ci + 2) * 64;
                u32 st = sb + KA_BUF + ((ci + 2) % 3) * 65536;
                cpyN128<512>(st, EH + Eoff + q0, EL + Eoff + q0, LQ_, tid);
                if (pass == 0) cpyN128<512>(st + 32768, QH + Qoff + q0, QL + Qoff + q0, LQ_, tid);
                else           cpyT64<512> (st + 32768, TH + Toff + (size_t)q0 * D_, TL + Toff + (size_t)q0 * D_, D_, tid);
                CP_COMMIT();
            }
            u32 bb = sb + KA_BUF + (ci % 3) * 65536;
            if (pass == 0) mma_chunk<2, 0, 0, 4, 8192>(acc, bb, bb + 32768, m0w, n0w, lane);
            else           mma_chunk<2, 0, 1, 4, 8192>(acc, bb, bb + 32768, m0w, n0w, lane);
        }
        __syncthreads();   // buffers free before stage writes

        // stage [d][c] (pitch 132) with rZ1
        #pragma unroll
        for (int mi = 0; mi < 2; mi++) {
            int m0 = m0w + mi * 16 + r;
            float rza = rzs[m0], rzb = rzs[m0 + 8];
            #pragma unroll
            for (int nj = 0; nj < 4; nj++) {
                int n0 = n0w + nj * 8 + cp;
                stg[n0 * 132 + m0]           = acc[mi][nj][0] * rza;
                stg[(n0 + 1) * 132 + m0]     = acc[mi][nj][1] * rza;
                stg[n0 * 132 + m0 + 8]       = acc[mi][nj][2] * rzb;
                stg[(n0 + 1) * 132 + m0 + 8] = acc[mi][nj][3] * rzb;
            }
        }
        __syncthreads();
        if (pass == 0) {
            for (int idx = tid; idx < 128 * 128; idx += 512) {
                int dd = idx >> 7, c = idx & 127;
                float a = stg[dd * 132 + c];
                float cv = Cb[(size_t)dd * LC_ + c];
                ob[(size_t)dd * LC_ + c]         = cv;
                ob[(size_t)(128 + dd) * LC_ + c] = a;
                ob[(size_t)(256 + dd) * LC_ + c] = cv * a;
            }
        } else {
            for (int idx = tid; idx < 128 * 128; idx += 512) {
                int dd = idx >> 7, c = idx & 127;
                float bm = stg[dd * 132 + c];
                float cv = Cb[(size_t)dd * LC_ + c];
                ob[(size_t)(384 + dd) * LC_ + c] = cv * bm;
            }
        }
        __syncthreads();
    }
}

// =====================================================================
extern "C" void kernel_launch(void* const* d_in, const int* in_sizes, int n_in,
                              void* d_out, int out_size) {
    const float* C     = (const float*)d_in[0];
    const float* Q     = (const float*)d_in[1];
    const int*   Cmask = (const int*)  d_in[2];
    const int*   Qmask = (const int*)  d_in[3];
    const float* w_c   = (const float*)d_in[4];
    const float* w_q   = (const float*)d_in[5];
    const float* w_mul = (const float*)d_in[6];
    const float* bias  = (const float*)d_in[7];
    float* out = (float*)d_out;

    cudaFuncSetAttribute(k_S,  cudaFuncAttributeMaxDynamicSharedMemorySize, KS_DYN);
    cudaFuncSetAttribute(k_T,  cudaFuncAttributeMaxDynamicSharedMemorySize, KT_DYN);
    cudaFuncSetAttribute(k_AB, cudaFuncAttributeMaxDynamicSharedMemorySize, KA_DYN);

    k_cvtC<<<dim3(16, 32), 256>>>(C, Cmask, w_mul, w_c, bias);
    k_cvtQ<<<32, 512>>>(Q, w_q);
    k_S<<<dim3(4, 16, 32), 256, KS_DYN>>>(Qmask, Cmask);
    k_T<<<dim3(4, 32), 512, KT_DYN>>>();
    k_AB<<<dim3(16, 32), 512, KA_DYN>>>(C, out);
}

// round 12
// speedup vs baseline: 1.1888x; 1.0256x over previous
#include <cuda_runtime.h>
#include <cuda_bf16.h>
#include <cstdint>

#define B_   32
#define D_   128
#define LC_  2048
#define LQ_  512

typedef unsigned int u32;

// ---------------- scratch planes (bf16 hi/lo stored as u32 pairs) ----------
__device__ u32 g_Ehi[(size_t)B_ * LC_ * LQ_ / 2];
__device__ u32 g_Elo[(size_t)B_ * LC_ * LQ_ / 2];
__device__ u32 g_Cwhi[(size_t)B_ * D_ * LC_ / 2];
__device__ u32 g_Cwlo[(size_t)B_ * D_ * LC_ / 2];
__device__ u32 g_Cmhi[(size_t)B_ * D_ * LC_ / 2];
__device__ u32 g_Cmlo[(size_t)B_ * D_ * LC_ / 2];
__device__ u32 g_Qhi[(size_t)B_ * D_ * LQ_ / 2];
__device__ u32 g_Qlo[(size_t)B_ * D_ * LQ_ / 2];
__device__ u32 g_Thi[(size_t)B_ * LQ_ * D_ / 2];
__device__ u32 g_Tlo[(size_t)B_ * LQ_ * D_ / 2];
__device__ float g_s0[B_ * LC_];
__device__ float g_s1[B_ * LQ_];
__device__ float g_Z1p[B_ * LC_ * 4];
__device__ float g_Z2p[B_ * LQ_ * 16];

// ---------------- helpers ----------------
__device__ __forceinline__ u32 s2u(const void* p) {
    u32 a; asm("{ .reg .u64 t; cvta.to.shared.u64 t, %1; cvt.u32.u64 %0, t; }" : "=r"(a) : "l"(p));
    return a;
}
#define SWZ(x) ((u32)(x) ^ ((((u32)(x)) >> 3) & 0x70))

__device__ __forceinline__ void cpa16(u32 dst, const void* src) {
    asm volatile("cp.async.cg.shared.global [%0], [%1], 16;" :: "r"(dst), "l"(src));
}
#define CP_COMMIT() asm volatile("cp.async.commit_group;")
#define CP_WAIT0()  asm volatile("cp.async.wait_group 0;")
#define CP_WAIT1()  asm volatile("cp.async.wait_group 1;")

__device__ __forceinline__ void splt(float v, u32 &hi, u32 &lo) {
    __nv_bfloat16 h = __float2bfloat16(v);
    float hf = __bfloat162float(h);
    __nv_bfloat16 l = __float2bfloat16(v - hf);
    hi = (u32)__bfloat16_as_ushort(h);
    lo = (u32)__bfloat16_as_ushort(l);
}

__device__ __forceinline__ void ldsm4(u32 addr, u32 r[4]) {
    asm volatile("ldmatrix.sync.aligned.m8n8.x4.shared.b16 {%0,%1,%2,%3}, [%4];"
                 : "=r"(r[0]), "=r"(r[1]), "=r"(r[2]), "=r"(r[3]) : "r"(addr));
}
__device__ __forceinline__ void ldsm4t(u32 addr, u32 r[4]) {
    asm volatile("ldmatrix.sync.aligned.m8n8.x4.trans.shared.b16 {%0,%1,%2,%3}, [%4];"
                 : "=r"(r[0]), "=r"(r[1]), "=r"(r[2]), "=r"(r[3]) : "r"(addr));
}
__device__ __forceinline__ void hmma(float d[4], const u32 a[4], u32 b0, u32 b1) {
    asm volatile("mma.sync.aligned.m16n8k16.row.col.f32.bf16.bf16.f32 "
                 "{%0,%1,%2,%3}, {%4,%5,%6,%7}, {%8,%9}, {%0,%1,%2,%3};"
                 : "+f"(d[0]), "+f"(d[1]), "+f"(d[2]), "+f"(d[3])
                 : "r"(a[0]), "r"(a[1]), "r"(a[2]), "r"(a[3]), "r"(b0), "r"(b1));
}
__device__ __forceinline__ uint4 lds128(u32 a) {
    uint4 v;
    asm volatile("ld.shared.v4.b32 {%0,%1,%2,%3}, [%4];"
                 : "=r"(v.x), "=r"(v.y), "=r"(v.z), "=r"(v.w) : "r"(a));
    return v;
}
__device__ __forceinline__ void sts32(u32 a, u32 v) { asm volatile("st.shared.b32 [%0], %1;" :: "r"(a), "r"(v)); }

// ---------------- chunk copies ----------------
template<int NT>
__device__ __forceinline__ void cpyT64(u32 dstBase, const __nv_bfloat16* srcHi,
                                       const __nv_bfloat16* srcLo, size_t rowStride, int tid) {
    #pragma unroll
    for (int t = 0; t < 2048 / NT; t++) {
        int u = tid + t * NT;
        int limb = u >> 10, rem = u & 1023;
        int row = rem >> 4, ucol = rem & 15;
        const __nv_bfloat16* src = (limb ? srcLo : srcHi) + (size_t)row * rowStride + ucol * 8;
        u32 dst = dstBase + limb * 16384 + (ucol >> 3) * 8192 + SWZ(row * 128 + (ucol & 7) * 16);
        cpa16(dst, src);
    }
}
template<int NT>
__device__ __forceinline__ void cpyT32(u32 dstBase, const __nv_bfloat16* srcHi,
                                       const __nv_bfloat16* srcLo, size_t rowStride, int tid) {
    #pragma unroll
    for (int t = 0; t < 1024 / NT; t++) {
        int u = tid + t * NT;
        int limb = u >> 9, rem = u & 511;
        int row = rem >> 4, ucol = rem & 15;
        const __nv_bfloat16* src = (limb ? srcLo : srcHi) + (size_t)row * rowStride + ucol * 8;
        u32 dst = dstBase + limb * 8192 + (ucol >> 3) * 4096 + SWZ(row * 128 + (ucol & 7) * 16);
        cpa16(dst, src);
    }
}
template<int NT>
__device__ __forceinline__ void cpyN128(u32 dstBase, const __nv_bfloat16* srcHi,
                                        const __nv_bfloat16* srcLo, size_t rowStride, int tid) {
    #pragma unroll
    for (int t = 0; t < 2048 / NT; t++) {
        int u = tid + t * NT;
        int limb = u >> 10, rem = u & 1023;
        int row = rem >> 3, ucol = rem & 7;
        const __nv_bfloat16* src = (limb ? srcLo : srcHi) + (size_t)row * rowStride + ucol * 8;
        u32 dst = dstBase + limb * 16384 + SWZ(row * 128 + ucol * 16);
        cpa16(dst, src);
    }
}

// ---------------- warp MMA over one chunk (3-limb) -------------------------
template<int MI, int AT, int BT, int KSTEPS, int SUB>
__device__ __forceinline__ void mma_chunk(float acc[MI][4][4], u32 Ab, u32 Bb,
                                          int m0w, int n0w, int lane) {
    const int LO = 2 * SUB;
    #pragma unroll
    for (int ks = 0; ks < KSTEPS; ks++) {
        int k0 = ks * 16;
        u32 ah[MI][4], al[MI][4];
        #pragma unroll
        for (int mi = 0; mi < MI; mi++) {
            int m0 = m0w + mi * 16;
            u32 ad;
            if (AT) {
                int r = k0 + (lane & 7) + ((lane & 16) ? 8 : 0);
                int c = m0 + ((lane & 8) ? 8 : 0);
                ad = Ab + ((u32)(c >> 6)) * SUB + SWZ(r * 128 + (c & 63) * 2);
                ldsm4t(ad, ah[mi]); ldsm4t(ad + LO, al[mi]);
            } else {
                int r = m0 + (lane & 15);
                int c = k0 + ((lane >> 4) << 3);
                ad = Ab + SWZ(r * 128 + c * 2);
                ldsm4(ad, ah[mi]); ldsm4(ad + LO, al[mi]);
            }
        }
        u32 bh[4][2], bl[4][2];
        #pragma unroll
        for (int nj2 = 0; nj2 < 2; nj2++) {
            int n0 = n0w + nj2 * 16;
            u32 bd;
            u32 t[4], tl[4];
            if (BT) {
                int r = k0 + (lane & 7) + ((lane & 8) ? 8 : 0);
                int c = n0 + ((lane & 16) ? 8 : 0);
                bd = Bb + ((u32)(c >> 6)) * SUB + SWZ(r * 128 + (c & 63) * 2);
                ldsm4t(bd, t); ldsm4t(bd + LO, tl);
            } else {
                int r = n0 + (lane & 7) + ((lane & 16) ? 8 : 0);
                int c = k0 + ((lane & 8) ? 8 : 0);
                bd = Bb + SWZ(r * 128 + c * 2);
                ldsm4(bd, t); ldsm4(bd + LO, tl);
            }
            bh[nj2 * 2][0] = t[0];  bh[nj2 * 2][1] = t[1];
            bh[nj2 * 2 + 1][0] = t[2]; bh[nj2 * 2 + 1][1] = t[3];
            bl[nj2 * 2][0] = tl[0]; bl[nj2 * 2][1] = tl[1];
            bl[nj2 * 2 + 1][0] = tl[2]; bl[nj2 * 2 + 1][1] = tl[3];
        }
        #pragma unroll
        for (int mi = 0; mi < MI; mi++)
            #pragma unroll
            for (int nj = 0; nj < 4; nj++) {
                hmma(acc[mi][nj], ah[mi], bh[nj][0], bh[nj][1]);
                hmma(acc[mi][nj], ah[mi], bl[nj][0], bl[nj][1]);
                hmma(acc[mi][nj], al[mi], bh[nj][0], bh[nj][1]);
            }
    }
}

// ---------------- dual-B warp MMA: A(E) natural, BQ natural, BT k-major -----
__device__ __forceinline__ void mma_chunk_dual(float accQ[2][4][4], float accT[2][4][4],
                                               u32 Ab, u32 Bq, u32 Bt,
                                               int m0w, int n0w, int lane) {
    #pragma unroll
    for (int ks = 0; ks < 4; ks++) {
        int k0 = ks * 16;
        u32 ah[2][4], al[2][4];
        #pragma unroll
        for (int mi = 0; mi < 2; mi++) {
            int m0 = m0w + mi * 16;
            int r = m0 + (lane & 15);
            int c = k0 + ((lane >> 4) << 3);
            u32 ad = Ab + SWZ(r * 128 + c * 2);
            ldsm4(ad, ah[mi]); ldsm4(ad + 16384, al[mi]);
        }
        // --- Q: row-major B panel ---
        {
            u32 bh[4][2], bl[4][2];
            #pragma unroll
            for (int nj2 = 0; nj2 < 2; nj2++) {
                int n0 = n0w + nj2 * 16;
                int r = n0 + (lane & 7) + ((lane & 16) ? 8 : 0);
                int c = k0 + ((lane & 8) ? 8 : 0);
                u32 bd = Bq + SWZ(r * 128 + c * 2);
                u32 t[4], tl[4];
                ldsm4(bd, t); ldsm4(bd + 16384, tl);
                bh[nj2 * 2][0] = t[0];  bh[nj2 * 2][1] = t[1];
                bh[nj2 * 2 + 1][0] = t[2]; bh[nj2 * 2 + 1][1] = t[3];
                bl[nj2 * 2][0] = tl[0]; bl[nj2 * 2][1] = tl[1];
                bl[nj2 * 2 + 1][0] = tl[2]; bl[nj2 * 2 + 1][1] = tl[3];
            }
            #pragma unroll
            for (int mi = 0; mi < 2; mi++)
                #pragma unroll
                for (int nj = 0; nj < 4; nj++) {
                    hmma(accQ[mi][nj], ah[mi], bh[nj][0], bh[nj][1]);
                    hmma(accQ[mi][nj], ah[mi], bl[nj][0], bl[nj][1]);
                    hmma(accQ[mi][nj], al[mi], bh[nj][0], bh[nj][1]);
                }
        }
        // --- T: k-major B panel (SUB=8192) ---
        {
            u32 bh[4][2], bl[4][2];
            #pragma unroll
            for (int nj2 = 0; nj2 < 2; nj2++) {
                int n0 = n0w + nj2 * 16;
                int r = k0 + (lane & 7) + ((lane & 8) ? 8 : 0);
                int c = n0 + ((lane & 16) ? 8 : 0);
                u32 bd = Bt + ((u32)(c >> 6)) * 8192 + SWZ(r * 128 + (c & 63) * 2);
                u32 t[4], tl[4];
                ldsm4t(bd, t); ldsm4t(bd + 16384, tl);
                bh[nj2 * 2][0] = t[0];  bh[nj2 * 2][1] = t[1];
                bh[nj2 * 2 + 1][0] = t[2]; bh[nj2 * 2 + 1][1] = t[3];
                bl[nj2 * 2][0] = tl[0]; bl[nj2 * 2][1] = tl[1];
                bl[nj2 * 2 + 1][0] = tl[2]; bl[nj2 * 2 + 1][1] = tl[3];
            }
            #pragma unroll
            for (int mi = 0; mi < 2; mi++)
                #pragma unroll
                for (int nj = 0; nj < 4; nj++) {
                    hmma(accT[mi][nj], ah[mi], bh[nj][0], bh[nj][1]);
                    hmma(accT[mi][nj], ah[mi], bl[nj][0], bl[nj][1]);
                    hmma(accT[mi][nj], al[mi], bh[nj][0], bh[nj][1]);
                }
        }
    }
}

// =====================================================================
// k_cvtC: C -> Cw/Cm limb planes, fused s0 = Ct.w_c + bias
// =====================================================================
__global__ void __launch_bounds__(256) k_cvtC(const float* __restrict__ C,
                                              const int* __restrict__ Cmask,
                                              const float* __restrict__ w_mul,
                                              const float* __restrict__ w_c,
                                              const float* __restrict__ bias) {
    __shared__ float wc[128], wm[128], zb[512];
    int tid = threadIdx.x;
    int b = blockIdx.y, cB = blockIdx.x * 128;
    if (tid < 128) { wc[tid] = w_c[tid]; wm[tid] = w_mul[tid]; }
    __syncthreads();
    int cp = tid & 63, dq = tid >> 6;
    int c0 = cB + 2 * cp;
    int m0 = Cmask[b * LC_ + c0], m1 = Cmask[b * LC_ + c0 + 1];
    float fm0 = m0 ? 1.f : 0.f, fm1 = m1 ? 1.f : 0.f;
    float s0e = 0.f, s0o = 0.f;
    #pragma unroll 4
    for (int i = 0; i < 32; i++) {
        int d = dq * 32 + i;
        size_t gi = ((size_t)(b * D_ + d)) * LC_ + c0;
        float2 v = *(const float2*)(C + gi);
        s0e += v.x * wc[d]; s0o += v.y * wc[d];
        u32 h0, l0, h1, l1;
        splt(v.x * wm[d], h0, l0); splt(v.y * wm[d], h1, l1);
        g_Cwhi[gi >> 1] = h0 | (h1 << 16);
        g_Cwlo[gi >> 1] = l0 | (l1 << 16);
        splt(v.x * fm0, h0, l0); splt(v.y * fm1, h1, l1);
        g_Cmhi[gi >> 1] = h0 | (h1 << 16);
        g_Cmlo[gi >> 1] = l0 | (l1 << 16);
    }
    zb[dq * 128 + 2 * cp] = s0e;
    zb[dq * 128 + 2 * cp + 1] = s0o;
    __syncthreads();
    if (tid < 128)
        g_s0[b * LC_ + cB + tid] = zb[tid] + zb[128 + tid] + zb[256 + tid] + zb[384 + tid] + bias[0];
}

// =====================================================================
// k_cvtQ: Q -> limb planes, fused s1 = Qt.w_q
// =====================================================================
__global__ void __launch_bounds__(512) k_cvtQ(const float* __restrict__ Q,
                                              const float* __restrict__ w_q) {
    __shared__ float wq[128], zb[1024];
    int tid = threadIdx.x;
    int b = blockIdx.x;
    if (tid < 128) wq[tid] = w_q[tid];
    __syncthreads();
    int qp = tid & 255, dh = tid >> 8;
    int q0 = 2 * qp;
    float s1e = 0.f, s1o = 0.f;
    #pragma unroll 4
    for (int i = 0; i < 64; i++) {
        int d = dh * 64 + i;
        size_t gi = ((size_t)(b * D_ + d)) * LQ_ + q0;
        float2 v = *(const float2*)(Q + gi);
        s1e += v.x * wq[d]; s1o += v.y * wq[d];
        u32 h0, l0, h1, l1;
        splt(v.x, h0, l0); splt(v.y, h1, l1);
        g_Qhi[gi >> 1] = h0 | (h1 << 16);
        g_Qlo[gi >> 1] = l0 | (l1 << 16);
    }
    zb[dh * 512 + q0]     = s1e;
    zb[dh * 512 + q0 + 1] = s1o;
    __syncthreads();
    g_s1[b * LQ_ + tid] = zb[tid] + zb[512 + tid];
}

// =====================================================================
// k_S: E = qmask*exp(Cw@Qt^T + s0 + s1). 256 thr, 2 CTAs/SM, m64n32 tiles.
// =====================================================================
#define KS_S0 0
#define KS_S1 512
#define KS_QM 1024
#define KS_CM 1536
#define KS_ZS 2048
#define KS_ZC 4096
#define KS_BUF 8192
#define KS_DYN (8192 + 3 * 32768)

__global__ void __launch_bounds__(256, 2) k_S(const int* __restrict__ Qmask,
                                              const int* __restrict__ Cmask) {
    extern __shared__ char sm[];
    u32 sb = s2u(sm);
    int tid = threadIdx.x, lane = tid & 31, wid = tid >> 5;
    int b = blockIdx.z, cB = blockIdx.y * 128, qB = blockIdx.x * 128, qt = blockIdx.x;
    float* s0f = (float*)(sm + KS_S0);
    float* s1f = (float*)(sm + KS_S1);
    int*   qmi = (int*)(sm + KS_QM);
    float* cmk = (float*)(sm + KS_CM);
    float* zs  = (float*)(sm + KS_ZS);
    float* zc  = (float*)(sm + KS_ZC);
    if (tid < 128) {
        s0f[tid] = g_s0[b * LC_ + cB + tid];
        s1f[tid] = g_s1[b * LQ_ + qB + tid];
        qmi[tid] = Qmask[b * LQ_ + qB + tid];
        cmk[tid] = (float)Cmask[b * LC_ + cB + tid];
    }

    const __nv_bfloat16* CwH = (const __nv_bfloat16*)g_Cwhi;
    const __nv_bfloat16* CwL = (const __nv_bfloat16*)g_Cwlo;
    const __nv_bfloat16* QH  = (const __nv_bfloat16*)g_Qhi;
    const __nv_bfloat16* QL  = (const __nv_bfloat16*)g_Qlo;
    size_t Ca = (size_t)(b * D_) * LC_ + cB;
    size_t Qa = (size_t)(b * D_) * LQ_ + qB;

    #pragma unroll
    for (int pc = 0; pc < 2; pc++) {
        u32 st = sb + KS_BUF + pc * 32768;
        cpyT32<256>(st,         CwH + Ca + (size_t)(pc * 32) * LC_, CwL + Ca + (size_t)(pc * 32) * LC_, LC_, tid);
        cpyT32<256>(st + 16384, QH  + Qa + (size_t)(pc * 32) * LQ_, QL  + Qa + (size_t)(pc * 32) * LQ_, LQ_, tid);
        CP_COMMIT();
    }

    int wm = wid >> 2, wn = wid & 3;
    int m0w = wm * 64, n0w = wn * 32;
    float acc[4][4][4] = {};
    #pragma unroll
    for (int ci = 0; ci < 4; ci++) {
        if (ci < 3) CP_WAIT1(); else CP_WAIT0();
        __syncthreads();
        if (ci < 2) {
            int k0 = (ci + 2) * 32;
            u32 st = sb + KS_BUF + ((ci + 2) % 3) * 32768;
            cpyT32<256>(st,         CwH + Ca + (size_t)k0 * LC_, CwL + Ca + (size_t)k0 * LC_, LC_, tid);
            cpyT32<256>(st + 16384, QH  + Qa + (size_t)k0 * LQ_, QL  + Qa + (size_t)k0 * LQ_, LQ_, tid);
            CP_COMMIT();
        }
        u32 bb = sb + KS_BUF + (ci % 3) * 32768;
        mma_chunk<4, 1, 1, 2, 4096>(acc, bb, bb + 16384, m0w, n0w, lane);
    }
    __syncthreads();

    int r = lane >> 2, cp = (lane & 3) * 2;
    float zrow[8] = {}, zcol[8] = {};
    u32 stg = sb + KS_BUF;
    #pragma unroll
    for (int mi = 0; mi < 4; mi++) {
        int m0 = m0w + mi * 16 + r;
        float s0a = s0f[m0], s0b = s0f[m0 + 8];
        float cma = cmk[m0], cmb = cmk[m0 + 8];
        #pragma unroll
        for (int nj = 0; nj < 4; nj++) {
            int q0 = n0w + nj * 8 + cp;
            float s1a = s1f[q0], s1b = s1f[q0 + 1];
            int qa = qmi[q0], qb = qmi[q0 + 1];
            float e00 = qa ? __expf(acc[mi][nj][0] + s0a + s1a) : 0.f;
            float e01 = qb ? __expf(acc[mi][nj][1] + s0a + s1b) : 0.f;
            float e10 = qa ? __expf(acc[mi][nj][2] + s0b + s1a) : 0.f;
            float e11 = qb ? __expf(acc[mi][nj][3] + s0b + s1b) : 0.f;
            zrow[mi * 2]     += e00 + e01;
            zrow[mi * 2 + 1] += e10 + e11;
            zcol[nj * 2]     += cma * e00 + cmb * e10;
            zcol[nj * 2 + 1] += cma * e01 + cmb * e11;
            u32 h00, l00, h01, l01, h10, l10, h11, l11;
            splt(e00, h00, l00); splt(e01, h01, l01);
            splt(e10, h10, l10); splt(e11, h11, l11);
            sts32(stg + m0 * 272 + q0 * 2,               h00 | (h01 << 16));
            sts32(stg + 34816 + m0 * 272 + q0 * 2,       l00 | (l01 << 16));
            sts32(stg + (m0 + 8) * 272 + q0 * 2,         h10 | (h11 << 16));
            sts32(stg + 34816 + (m0 + 8) * 272 + q0 * 2, l10 | (l11 << 16));
        }
    }
    #pragma unroll
    for (int h = 0; h < 8; h++) {
        float v = zrow[h];
        v += __shfl_xor_sync(0xffffffffu, v, 1);
        v += __shfl_xor_sync(0xffffffffu, v, 2);
        if ((lane & 3) == 0) {
            int m = m0w + (h >> 1) * 16 + ((h & 1) ? 8 : 0) + r;
            zs[m * 4 + wn] = v;
        }
    }
    #pragma unroll
    for (int j = 0; j < 8; j++) {
        float v = zcol[j];
        v += __shfl_xor_sync(0xffffffffu, v, 4);
        v += __shfl_xor_sync(0xffffffffu, v, 8);
        v += __shfl_xor_sync(0xffffffffu, v, 16);
        zcol[j] = v;
    }
    if (lane < 4) {
        #pragma unroll
        for (int nj = 0; nj < 4; nj++) {
            zc[wm * 128 + n0w + nj * 8 + lane * 2]     = zcol[nj * 2];
            zc[wm * 128 + n0w + nj * 8 + lane * 2 + 1] = zcol[nj * 2 + 1];
        }
    }
    __syncthreads();
    #pragma unroll
    for (int it = 0; it < 16; it++) {
        int idx = tid + it * 256;
        int chunk = idx & 15, c = (idx >> 4) & 127, plane = idx >> 11;
        uint4 v = lds128(stg + plane * 34816 + c * 272 + chunk * 16);
        uint4* dst = plane ? (uint4*)g_Elo : (uint4*)g_Ehi;
        dst[((((size_t)(b * LC_ + cB + c)) * LQ_ + qB) >> 3) + chunk] = v;
    }
    if (tid < 128) {
        g_Z1p[((size_t)b * LC_ + cB + tid) * 4 + qt] =
            zs[tid * 4] + zs[tid * 4 + 1] + zs[tid * 4 + 2] + zs[tid * 4 + 3];
        g_Z2p[((size_t)b * LQ_ + qB + tid) * 16 + blockIdx.y] = zc[tid] + zc[128 + tid];
    }
}

// =====================================================================
// k_T: T[q][d] = rZ2[q] * sum_c E[c,q]*Cm[d,c]. k64 x32, 3-stage, 1 sync.
// =====================================================================
#define KT_RZ 0
#define KT_BUF 1024
#define KT_DYN (1024 + 3 * 65536)

__global__ void __launch_bounds__(512, 1) k_T() {
    extern __shared__ char sm[];
    u32 sb = s2u(sm);
    int tid = threadIdx.x, lane = tid & 31, wid = tid >> 5;
    int b = blockIdx.y, qB = blockIdx.x * 128;
    float* rzs = (float*)(sm + KT_RZ);
    if (tid < 128) {
        const float* p = &g_Z2p[((size_t)b * LQ_ + qB + tid) * 16];
        float s = 0.f;
        #pragma unroll
        for (int t = 0; t < 16; t++) s += p[t];
        rzs[tid] = 1.f / fmaxf(s, 1e-30f);
    }
    const __nv_bfloat16* EH = (const __nv_bfloat16*)g_Ehi;
    const __nv_bfloat16* EL = (const __nv_bfloat16*)g_Elo;
    const __nv_bfloat16* CH = (const __nv_bfloat16*)g_Cmhi;
    const __nv_bfloat16* CL = (const __nv_bfloat16*)g_Cmlo;
    size_t Eoff = (size_t)(b * LC_) * LQ_ + qB;
    size_t Coff = (size_t)(b * D_) * LC_;

    #pragma unroll
    for (int pc = 0; pc < 2; pc++) {
        u32 st = sb + KT_BUF + pc * 65536;
        cpyT64<512> (st,         EH + Eoff + (size_t)(pc * 64) * LQ_, EL + Eoff + (size_t)(pc * 64) * LQ_, LQ_, tid);
        cpyN128<512>(st + 32768, CH + Coff + pc * 64,                 CL + Coff + pc * 64,                 LC_, tid);
        CP_COMMIT();
    }

    int wm = wid >> 2, wn = wid & 3;
    int m0w = wm * 32, n0w = wn * 32;
    float acc[2][4][4] = {};
    for (int ci = 0; ci < 32; ci++) {
        if (ci < 31) CP_WAIT1(); else CP_WAIT0();
        __syncthreads();
        if (ci < 30) {
            int c0 = (ci + 2) * 64;
            u32 st = sb + KT_BUF + ((ci + 2) % 3) * 65536;
            cpyT64<512> (st,         EH + Eoff + (size_t)c0 * LQ_, EL + Eoff + (size_t)c0 * LQ_, LQ_, tid);
            cpyN128<512>(st + 32768, CH + Coff + c0,               CL + Coff + c0,               LC_, tid);
            CP_COMMIT();
        }
        u32 bb = sb + KT_BUF + (ci % 3) * 65536;
        mma_chunk<2, 1, 0, 4, 8192>(acc, bb, bb + 32768, m0w, n0w, lane);
    }

    int r = lane >> 2, cp = (lane & 3) * 2;
    #pragma unroll
    for (int mi = 0; mi < 2; mi++) {
        int q0 = m0w + mi * 16 + r;
        float rza = rzs[q0], rzb = rzs[q0 + 8];
        #pragma unroll
        for (int nj = 0; nj < 4; nj++) {
            int d0 = n0w + nj * 8 + cp;
            u32 h0, l0, h1, l1;
            size_t i0 = ((size_t)(b * LQ_ + qB + q0) * D_ + d0) >> 1;
            size_t i1 = ((size_t)(b * LQ_ + qB + q0 + 8) * D_ + d0) >> 1;
            splt(acc[mi][nj][0] * rza, h0, l0); splt(acc[mi][nj][1] * rza, h1, l1);
            g_Thi[i0] = h0 | (h1 << 16); g_Tlo[i0] = l0 | (l1 << 16);
            splt(acc[mi][nj][2] * rzb, h0, l0); splt(acc[mi][nj][3] * rzb, h1, l1);
            g_Thi[i1] = h0 | (h1 << 16); g_Tlo[i1] = l0 | (l1 << 16);
        }
    }
}

// =====================================================================
// k_AB (single-pass dual-B): accQ = E@Qt, accT = E@T in one K sweep.
//   E read ONCE. Stage = {E 32K | Q 32K | T 32K}; 2 stages.
// =====================================================================
#define KA_RZ 0
#define KA_BUF 1024
#define KA_DYN (1024 + 2 * 98304)

__global__ void __launch_bounds__(512, 1) k_AB(const float* __restrict__ C,
                                               float* __restrict__ out) {
    extern __shared__ char sm[];
    u32 sb = s2u(sm);
    int tid = threadIdx.x, lane = tid & 31, wid = tid >> 5;
    int b = blockIdx.y, cB = blockIdx.x * 128;
    float* rzs = (float*)(sm + KA_RZ);
    if (tid < 128) {
        const float* p = &g_Z1p[((size_t)b * LC_ + cB + tid) * 4];
        rzs[tid] = 1.f / (p[0] + p[1] + p[2] + p[3]);
    }
    const __nv_bfloat16* EH = (const __nv_bfloat16*)g_Ehi;
    const __nv_bfloat16* EL = (const __nv_bfloat16*)g_Elo;
    const __nv_bfloat16* QH = (const __nv_bfloat16*)g_Qhi;
    const __nv_bfloat16* QL = (const __nv_bfloat16*)g_Qlo;
    const __nv_bfloat16* TH = (const __nv_bfloat16*)g_Thi;
    const __nv_bfloat16* TL = (const __nv_bfloat16*)g_Tlo;
    size_t Eoff = ((size_t)b * LC_ + cB) * LQ_;
    size_t Qoff = (size_t)(b * D_) * LQ_;
    size_t Toff = (size_t)(b * LQ_) * D_;
    const float* Cb = C + (size_t)b * D_ * LC_ + cB;
    float* ob = out + (size_t)b * 4 * D_ * LC_ + cB;
    float* stg = (float*)(sm + KA_BUF);
    int wm = wid >> 2, wn = wid & 3;
    int m0w = wm * 32, n0w = wn * 32;
    int r = lane >> 2, cp = (lane & 3) * 2;

    // prologue: chunk 0
    {
        u32 st = sb + KA_BUF;
        cpyN128<512>(st,         EH + Eoff, EL + Eoff, LQ_, tid);
        cpyN128<512>(st + 32768, QH + Qoff, QL + Qoff, LQ_, tid);
        cpyT64<512> (st + 65536, TH + Toff, TL + Toff, D_, tid);
        CP_COMMIT();
    }

    float accQ[2][4][4] = {}, accT[2][4][4] = {};
    for (int ci = 0; ci < 8; ci++) {
        CP_WAIT0();
        __syncthreads();
        if (ci + 1 < 8) {
            int q0 = (ci + 1) * 64;
            u32 st = sb + KA_BUF + ((ci + 1) & 1) * 98304;
            cpyN128<512>(st,         EH + Eoff + q0, EL + Eoff + q0, LQ_, tid);
            cpyN128<512>(st + 32768, QH + Qoff + q0, QL + Qoff + q0, LQ_, tid);
            cpyT64<512> (st + 65536, TH + Toff + (size_t)q0 * D_, TL + Toff + (size_t)q0 * D_, D_, tid);
            CP_COMMIT();
        }
        u32 bb = sb + KA_BUF + (ci & 1) * 98304;
        mma_chunk_dual(accQ, accT, bb, bb + 32768, bb + 65536, m0w, n0w, lane);
    }
    __syncthreads();   // buffers free before stage writes

    // ---- stage accQ -> sections 0,1,2
    #pragma unroll
    for (int mi = 0; mi < 2; mi++) {
        int m0 = m0w + mi * 16 + r;
        float rza = rzs[m0], rzb = rzs[m0 + 8];
        #pragma unroll
        for (int nj = 0; nj < 4; nj++) {
            int n0 = n0w + nj * 8 + cp;
            stg[n0 * 132 + m0]           = accQ[mi][nj][0] * rza;
            stg[(n0 + 1) * 132 + m0]     = accQ[mi][nj][1] * rza;
            stg[n0 * 132 + m0 + 8]       = accQ[mi][nj][2] * rzb;
            stg[(n0 + 1) * 132 + m0 + 8] = accQ[mi][nj][3] * rzb;
        }
    }
    __syncthreads();
    for (int idx = tid; idx < 128 * 128; idx += 512) {
        int dd = idx >> 7, c = idx & 127;
        float a = stg[dd * 132 + c];
        float cv = Cb[(size_t)dd * LC_ + c];
        ob[(size_t)dd * LC_ + c]         = cv;
        ob[(size_t)(128 + dd) * LC_ + c] = a;
        ob[(size_t)(256 + dd) * LC_ + c] = cv * a;
    }
    __syncthreads();
    // ---- stage accT -> section 3
    #pragma unroll
    for (int mi = 0; mi < 2; mi++) {
        int m0 = m0w + mi * 16 + r;
        float rza = rzs[m0], rzb = rzs[m0 + 8];
        #pragma unroll
        for (int nj = 0; nj < 4; nj++) {
            int n0 = n0w + nj * 8 + cp;
            stg[n0 * 132 + m0]           = accT[mi][nj][0] * rza;
            stg[(n0 + 1) * 132 + m0]     = accT[mi][nj][1] * rza;
            stg[n0 * 132 + m0 + 8]       = accT[mi][nj][2] * rzb;
            stg[(n0 + 1) * 132 + m0 + 8] = accT[mi][nj][3] * rzb;
        }
    }
    __syncthreads();
    for (int idx = tid; idx < 128 * 128; idx += 512) {
        int dd = idx >> 7, c = idx & 127;
        float bm = stg[dd * 132 + c];
        float cv = Cb[(size_t)dd * LC_ + c];
        ob[(size_t)(384 + dd) * LC_ + c] = cv * bm;
    }
}

// =====================================================================
extern "C" void kernel_launch(void* const* d_in, const int* in_sizes, int n_in,
                              void* d_out, int out_size) {
    const float* C     = (const float*)d_in[0];
    const float* Q     = (const float*)d_in[1];
    const int*   Cmask = (const int*)  d_in[2];
    const int*   Qmask = (const int*)  d_in[3];
    const float* w_c   = (const float*)d_in[4];
    const float* w_q   = (const float*)d_in[5];
    const float* w_mul = (const float*)d_in[6];
    const float* bias  = (const float*)d_in[7];
    float* out = (float*)d_out;

    cudaFuncSetAttribute(k_S,  cudaFuncAttributeMaxDynamicSharedMemorySize, KS_DYN);
    cudaFuncSetAttribute(k_T,  cudaFuncAttributeMaxDynamicSharedMemorySize, KT_DYN);
    cudaFuncSetAttribute(k_AB, cudaFuncAttributeMaxDynamicSharedMemorySize, KA_DYN);

    k_cvtC<<<dim3(16, 32), 256>>>(C, Cmask, w_mul, w_c, bias);
    k_cvtQ<<<32, 512>>>(Q, w_q);
    k_S<<<dim3(4, 16, 32), 256, KS_DYN>>>(Qmask, Cmask);
    k_T<<<dim3(4, 32), 512, KT_DYN>>>();
    k_AB<<<dim3(16, 32), 512, KA_DYN>>>(C, out);
}

// round 13
// speedup vs baseline: 1.4121x; 1.1878x over previous
#include <cuda_runtime.h>
#include <cuda_bf16.h>
#include <cuda_fp16.h>
#include <cstdint>

#define B_   32
#define D_   128
#define LC_  2048
#define LQ_  512

typedef unsigned int u32;

// ---------------- scratch planes ----------------
__device__ u32 g_E[(size_t)B_ * LC_ * LQ_ / 2];        // E'' fp16 single plane
__device__ u32 g_Cwhi[(size_t)B_ * D_ * LC_ / 2];      // C*w_mul bf16 hi (k_S)
__device__ u32 g_Cwlo[(size_t)B_ * D_ * LC_ / 2];
__device__ u32 g_Cfhi[(size_t)B_ * D_ * LC_ / 2];      // C' = C*cmask*16*exp(s0), fp16 2L (k_T)
__device__ u32 g_Cflo[(size_t)B_ * D_ * LC_ / 2];
__device__ u32 g_Qhi[(size_t)B_ * D_ * LQ_ / 2];       // Q bf16 2L (k_S)
__device__ u32 g_Qlo[(size_t)B_ * D_ * LQ_ / 2];
__device__ u32 g_Qfhi[(size_t)B_ * D_ * LQ_ / 2];      // Q fp16 2L (k_AB)
__device__ u32 g_Qflo[(size_t)B_ * D_ * LQ_ / 2];
__device__ u32 g_Thi[(size_t)B_ * LQ_ * D_ / 2];       // T fp16 2L
__device__ u32 g_Tlo[(size_t)B_ * LQ_ * D_ / 2];
__device__ float g_s0[B_ * LC_];
__device__ float g_s1[B_ * LQ_];
__device__ float g_Z1p[B_ * LC_ * 4];
__device__ float g_Z2p[B_ * LQ_ * 16];

// ---------------- helpers ----------------
__device__ __forceinline__ u32 s2u(const void* p) {
    u32 a; asm("{ .reg .u64 t; cvta.to.shared.u64 t, %1; cvt.u32.u64 %0, t; }" : "=r"(a) : "l"(p));
    return a;
}
#define SWZ(x) ((u32)(x) ^ ((((u32)(x)) >> 3) & 0x70))

__device__ __forceinline__ void cpa16(u32 dst, const void* src) {
    asm volatile("cp.async.cg.shared.global [%0], [%1], 16;" :: "r"(dst), "l"(src));
}
#define CP_COMMIT() asm volatile("cp.async.commit_group;")
#define CP_WAIT0()  asm volatile("cp.async.wait_group 0;")
#define CP_WAIT1()  asm volatile("cp.async.wait_group 1;")

__device__ __forceinline__ void splt(float v, u32 &hi, u32 &lo) {     // bf16 2-limb
    __nv_bfloat16 h = __float2bfloat16(v);
    __nv_bfloat16 l = __float2bfloat16(v - __bfloat162float(h));
    hi = (u32)__bfloat16_as_ushort(h);
    lo = (u32)__bfloat16_as_ushort(l);
}
__device__ __forceinline__ void splt16(float v, u32 &hi, u32 &lo) {   // fp16 2-limb
    __half h = __float2half(v);
    __half l = __float2half(v - __half2float(h));
    hi = (u32)__half_as_ushort(h);
    lo = (u32)__half_as_ushort(l);
}

__device__ __forceinline__ void ldsm4(u32 addr, u32 r[4]) {
    asm volatile("ldmatrix.sync.aligned.m8n8.x4.shared.b16 {%0,%1,%2,%3}, [%4];"
                 : "=r"(r[0]), "=r"(r[1]), "=r"(r[2]), "=r"(r[3]) : "r"(addr));
}
__device__ __forceinline__ void ldsm4t(u32 addr, u32 r[4]) {
    asm volatile("ldmatrix.sync.aligned.m8n8.x4.trans.shared.b16 {%0,%1,%2,%3}, [%4];"
                 : "=r"(r[0]), "=r"(r[1]), "=r"(r[2]), "=r"(r[3]) : "r"(addr));
}
template<int F16>
__device__ __forceinline__ void mmaop(float d[4], const u32 a[4], u32 b0, u32 b1) {
    if (F16)
        asm volatile("mma.sync.aligned.m16n8k16.row.col.f32.f16.f16.f32 "
                     "{%0,%1,%2,%3}, {%4,%5,%6,%7}, {%8,%9}, {%0,%1,%2,%3};"
                     : "+f"(d[0]), "+f"(d[1]), "+f"(d[2]), "+f"(d[3])
                     : "r"(a[0]), "r"(a[1]), "r"(a[2]), "r"(a[3]), "r"(b0), "r"(b1));
    else
        asm volatile("mma.sync.aligned.m16n8k16.row.col.f32.bf16.bf16.f32 "
                     "{%0,%1,%2,%3}, {%4,%5,%6,%7}, {%8,%9}, {%0,%1,%2,%3};"
                     : "+f"(d[0]), "+f"(d[1]), "+f"(d[2]), "+f"(d[3])
                     : "r"(a[0]), "r"(a[1]), "r"(a[2]), "r"(a[3]), "r"(b0), "r"(b1));
}
__device__ __forceinline__ uint4 lds128(u32 a) {
    uint4 v;
    asm volatile("ld.shared.v4.b32 {%0,%1,%2,%3}, [%4];"
                 : "=r"(v.x), "=r"(v.y), "=r"(v.z), "=r"(v.w) : "r"(a));
    return v;
}
__device__ __forceinline__ void sts32(u32 a, u32 v) { asm volatile("st.shared.b32 [%0], %1;" :: "r"(a), "r"(v)); }

// ---------------- chunk copies (L = limb count) ----------------
// k-major panel, k=64 rows x 128 cols: 16KB/limb (two 8KB col sub-panels)
template<int NT, int L, typename H>
__device__ __forceinline__ void cpyT64(u32 dstBase, const H* srcHi, const H* srcLo,
                                       size_t rowStride, int tid) {
    #pragma unroll
    for (int t = 0; t < (1024 * L) / NT; t++) {
        int u = tid + t * NT;
        int limb = u >> 10, rem = u & 1023;
        int row = rem >> 4, ucol = rem & 15;
        const H* src = (limb ? srcLo : srcHi) + (size_t)row * rowStride + ucol * 8;
        u32 dst = dstBase + limb * 16384 + (ucol >> 3) * 8192 + SWZ(row * 128 + (ucol & 7) * 16);
        cpa16(dst, src);
    }
}
// k-major panel, k=32 rows x 128 cols: 8KB/limb (two 4KB sub-panels)
template<int NT, int L, typename H>
__device__ __forceinline__ void cpyT32(u32 dstBase, const H* srcHi, const H* srcLo,
                                       size_t rowStride, int tid) {
    #pragma unroll
    for (int t = 0; t < (512 * L) / NT; t++) {
        int u = tid + t * NT;
        int limb = u >> 9, rem = u & 511;
        int row = rem >> 4, ucol = rem & 15;
        const H* src = (limb ? srcLo : srcHi) + (size_t)row * rowStride + ucol * 8;
        u32 dst = dstBase + limb * 8192 + (ucol >> 3) * 4096 + SWZ(row * 128 + (ucol & 7) * 16);
        cpa16(dst, src);
    }
}
// row-major panel, 128 rows x k=64 cols: 16KB/limb
template<int NT, int L, typename H>
__device__ __forceinline__ void cpyN128(u32 dstBase, const H* srcHi, const H* srcLo,
                                        size_t rowStride, int tid) {
    #pragma unroll
    for (int t = 0; t < (1024 * L) / NT; t++) {
        int u = tid + t * NT;
        int limb = u >> 10, rem = u & 1023;
        int row = rem >> 3, ucol = rem & 7;
        const H* src = (limb ? srcLo : srcHi) + (size_t)row * rowStride + ucol * 8;
        u32 dst = dstBase + limb * 16384 + SWZ(row * 128 + ucol * 16);
        cpa16(dst, src);
    }
}

// ---------------- warp MMA over one chunk ----------------------------------
// AL/BL = limb counts; terms: hh (+ h*bl if BL=2) (+ al*bh if AL=2)
template<int MI, int AT, int BT, int KSTEPS, int SUB, int AL, int BL, int F16>
__device__ __forceinline__ void mma_chunk(float acc[MI][4][4], u32 Ab, u32 Bb,
                                          int m0w, int n0w, int lane) {
    const int LO = 2 * SUB;
    #pragma unroll
    for (int ks = 0; ks < KSTEPS; ks++) {
        int k0 = ks * 16;
        u32 ah[MI][4], al[MI][4];
        #pragma unroll
        for (int mi = 0; mi < MI; mi++) {
            int m0 = m0w + mi * 16;
            u32 ad;
            if (AT) {
                int r = k0 + (lane & 7) + ((lane & 16) ? 8 : 0);
                int c = m0 + ((lane & 8) ? 8 : 0);
                ad = Ab + ((u32)(c >> 6)) * SUB + SWZ(r * 128 + (c & 63) * 2);
                ldsm4t(ad, ah[mi]); if (AL == 2) ldsm4t(ad + LO, al[mi]);
            } else {
                int r = m0 + (lane & 15);
                int c = k0 + ((lane >> 4) << 3);
                ad = Ab + SWZ(r * 128 + c * 2);
                ldsm4(ad, ah[mi]); if (AL == 2) ldsm4(ad + LO, al[mi]);
            }
        }
        u32 bh[4][2], bl[4][2];
        #pragma unroll
        for (int nj2 = 0; nj2 < 2; nj2++) {
            int n0 = n0w + nj2 * 16;
            u32 bd;
            u32 t[4], tl[4];
            if (BT) {
                int r = k0 + (lane & 7) + ((lane & 8) ? 8 : 0);
                int c = n0 + ((lane & 16) ? 8 : 0);
                bd = Bb + ((u32)(c >> 6)) * SUB + SWZ(r * 128 + (c & 63) * 2);
                ldsm4t(bd, t); if (BL == 2) ldsm4t(bd + LO, tl);
            } else {
                int r = n0 + (lane & 7) + ((lane & 16) ? 8 : 0);
                int c = k0 + ((lane & 8) ? 8 : 0);
                bd = Bb + SWZ(r * 128 + c * 2);
                ldsm4(bd, t); if (BL == 2) ldsm4(bd + LO, tl);
            }
            bh[nj2 * 2][0] = t[0];  bh[nj2 * 2][1] = t[1];
            bh[nj2 * 2 + 1][0] = t[2]; bh[nj2 * 2 + 1][1] = t[3];
            if (BL == 2) {
                bl[nj2 * 2][0] = tl[0]; bl[nj2 * 2][1] = tl[1];
                bl[nj2 * 2 + 1][0] = tl[2]; bl[nj2 * 2 + 1][1] = tl[3];
            }
        }
        #pragma unroll
        for (int mi = 0; mi < MI; mi++)
            #pragma unroll
            for (int nj = 0; nj < 4; nj++) {
                mmaop<F16>(acc[mi][nj], ah[mi], bh[nj][0], bh[nj][1]);
                if (BL == 2) mmaop<F16>(acc[mi][nj], ah[mi], bl[nj][0], bl[nj][1]);
                if (AL == 2) mmaop<F16>(acc[mi][nj], al[mi], bh[nj][0], bh[nj][1]);
            }
    }
}

// ---------------- dual-B warp MMA for k_AB (all fp16, A 1-limb) ------------
__device__ __forceinline__ void mma_chunk_dual(float accQ[2][4][4], float accT[2][4][4],
                                               u32 Ab, u32 Bq, u32 Bt,
                                               int m0w, int n0w, int lane) {
    #pragma unroll
    for (int ks = 0; ks < 4; ks++) {
        int k0 = ks * 16;
        u32 ah[2][4];
        #pragma unroll
        for (int mi = 0; mi < 2; mi++) {
            int m0 = m0w + mi * 16;
            int r = m0 + (lane & 15);
            int c = k0 + ((lane >> 4) << 3);
            ldsm4(Ab + SWZ(r * 128 + c * 2), ah[mi]);
        }
        // --- Q: natural 2-limb ---
        {
            u32 bh[4][2], bl[4][2];
            #pragma unroll
            for (int nj2 = 0; nj2 < 2; nj2++) {
                int n0 = n0w + nj2 * 16;
                int r = n0 + (lane & 7) + ((lane & 16) ? 8 : 0);
                int c = k0 + ((lane & 8) ? 8 : 0);
                u32 bd = Bq + SWZ(r * 128 + c * 2);
                u32 t[4], tl[4];
                ldsm4(bd, t); ldsm4(bd + 16384, tl);
                bh[nj2 * 2][0] = t[0];  bh[nj2 * 2][1] = t[1];
                bh[nj2 * 2 + 1][0] = t[2]; bh[nj2 * 2 + 1][1] = t[3];
                bl[nj2 * 2][0] = tl[0]; bl[nj2 * 2][1] = tl[1];
                bl[nj2 * 2 + 1][0] = tl[2]; bl[nj2 * 2 + 1][1] = tl[3];
            }
            #pragma unroll
            for (int mi = 0; mi < 2; mi++)
                #pragma unroll
                for (int nj = 0; nj < 4; nj++) {
                    mmaop<1>(accQ[mi][nj], ah[mi], bh[nj][0], bh[nj][1]);
                    mmaop<1>(accQ[mi][nj], ah[mi], bl[nj][0], bl[nj][1]);
                }
        }
        // --- T: k-major 2-limb (SUB=8192) ---
        {
            u32 bh[4][2], bl[4][2];
            #pragma unroll
            for (int nj2 = 0; nj2 < 2; nj2++) {
                int n0 = n0w + nj2 * 16;
                int r = k0 + (lane & 7) + ((lane & 8) ? 8 : 0);
                int c = n0 + ((lane & 16) ? 8 : 0);
                u32 bd = Bt + ((u32)(c >> 6)) * 8192 + SWZ(r * 128 + (c & 63) * 2);
                u32 t[4], tl[4];
                ldsm4t(bd, t); ldsm4t(bd + 16384, tl);
                bh[nj2 * 2][0] = t[0];  bh[nj2 * 2][1] = t[1];
                bh[nj2 * 2 + 1][0] = t[2]; bh[nj2 * 2 + 1][1] = t[3];
                bl[nj2 * 2][0] = tl[0]; bl[nj2 * 2][1] = tl[1];
                bl[nj2 * 2 + 1][0] = tl[2]; bl[nj2 * 2 + 1][1] = tl[3];
            }
            #pragma unroll
            for (int mi = 0; mi < 2; mi++)
                #pragma unroll
                for (int nj = 0; nj < 4; nj++) {
                    mmaop<1>(accT[mi][nj], ah[mi], bh[nj][0], bh[nj][1]);
                    mmaop<1>(accT[mi][nj], ah[mi], bl[nj][0], bl[nj][1]);
                }
        }
    }
}

// =====================================================================
// k_cvtC: pass1: Cw planes + s0 reduce; pass2: C' = C*cmask*16*exp(s0) fp16 2L
// =====================================================================
__global__ void __launch_bounds__(256) k_cvtC(const float* __restrict__ C,
                                              const int* __restrict__ Cmask,
                                              const float* __restrict__ w_mul,
                                              const float* __restrict__ w_c,
                                              const float* __restrict__ bias) {
    __shared__ float wc[128], wm[128], zb[512], s0s[128];
    int tid = threadIdx.x;
    int b = blockIdx.y, cB = blockIdx.x * 128;
    if (tid < 128) { wc[tid] = w_c[tid]; wm[tid] = w_mul[tid]; }
    __syncthreads();
    int cp = tid & 63, dq = tid >> 6;
    int c0 = cB + 2 * cp;
    int m0 = Cmask[b * LC_ + c0], m1 = Cmask[b * LC_ + c0 + 1];
    float s0e = 0.f, s0o = 0.f;
    float2 v[32];
    #pragma unroll
    for (int i = 0; i < 32; i++) {
        int d = dq * 32 + i;
        size_t gi = ((size_t)(b * D_ + d)) * LC_ + c0;
        v[i] = *(const float2*)(C + gi);
        s0e += v[i].x * wc[d]; s0o += v[i].y * wc[d];
        u32 h0, l0, h1, l1;
        splt(v[i].x * wm[d], h0, l0); splt(v[i].y * wm[d], h1, l1);
        g_Cwhi[gi >> 1] = h0 | (h1 << 16);
        g_Cwlo[gi >> 1] = l0 | (l1 << 16);
    }
    zb[dq * 128 + 2 * cp] = s0e;
    zb[dq * 128 + 2 * cp + 1] = s0o;
    __syncthreads();
    if (tid < 128) {
        float s0 = zb[tid] + zb[128 + tid] + zb[256 + tid] + zb[384 + tid] + bias[0];
        g_s0[b * LC_ + cB + tid] = s0;
        s0s[tid] = s0;
    }
    __syncthreads();
    float Ma0 = m0 ? 16.f * __expf(s0s[2 * cp])     : 0.f;
    float Ma1 = m1 ? 16.f * __expf(s0s[2 * cp + 1]) : 0.f;
    #pragma unroll
    for (int i = 0; i < 32; i++) {
        int d = dq * 32 + i;
        size_t gi = ((size_t)(b * D_ + d)) * LC_ + c0;
        u32 h0, l0, h1, l1;
        splt16(v[i].x * Ma0, h0, l0); splt16(v[i].y * Ma1, h1, l1);
        g_Cfhi[gi >> 1] = h0 | (h1 << 16);
        g_Cflo[gi >> 1] = l0 | (l1 << 16);
    }
}

// =====================================================================
// k_cvtQ: Q -> bf16 2L (k_S) + fp16 2L (k_AB), fused s1
// =====================================================================
__global__ void __launch_bounds__(512) k_cvtQ(const float* __restrict__ Q,
                                              const float* __restrict__ w_q) {
    __shared__ float wq[128], zb[1024];
    int tid = threadIdx.x;
    int b = blockIdx.x;
    if (tid < 128) wq[tid] = w_q[tid];
    __syncthreads();
    int qp = tid & 255, dh = tid >> 8;
    int q0 = 2 * qp;
    float s1e = 0.f, s1o = 0.f;
    #pragma unroll 4
    for (int i = 0; i < 64; i++) {
        int d = dh * 64 + i;
        size_t gi = ((size_t)(b * D_ + d)) * LQ_ + q0;
        float2 v = *(const float2*)(Q + gi);
        s1e += v.x * wq[d]; s1o += v.y * wq[d];
        u32 h0, l0, h1, l1;
        splt(v.x, h0, l0); splt(v.y, h1, l1);
        g_Qhi[gi >> 1] = h0 | (h1 << 16);
        g_Qlo[gi >> 1] = l0 | (l1 << 16);
        splt16(v.x, h0, l0); splt16(v.y, h1, l1);
        g_Qfhi[gi >> 1] = h0 | (h1 << 16);
        g_Qflo[gi >> 1] = l0 | (l1 << 16);
    }
    zb[dh * 512 + q0]     = s1e;
    zb[dh * 512 + q0 + 1] = s1o;
    __syncthreads();
    g_s1[b * LQ_ + tid] = zb[tid] + zb[512 + tid];
}

// =====================================================================
// k_S: E'' = qmask*exp(s2+s1)/16 (fp16, 1 plane); Z1 sums of E'';
//      Z2 sums of cmask*E''*16*exp(s0). bf16 3-limb GEMM unchanged.
// =====================================================================
#define KS_S0 0
#define KS_S1 512
#define KS_QM 1024
#define KS_CM 1536
#define KS_ZS 2048
#define KS_ZC 4096
#define KS_BUF 8192
#define KS_DYN (8192 + 3 * 32768)

__global__ void __launch_bounds__(256, 2) k_S(const int* __restrict__ Qmask,
                                              const int* __restrict__ Cmask) {
    extern __shared__ char sm[];
    u32 sb = s2u(sm);
    int tid = threadIdx.x, lane = tid & 31, wid = tid >> 5;
    int b = blockIdx.z, cB = blockIdx.y * 128, qB = blockIdx.x * 128, qt = blockIdx.x;
    float* s0f = (float*)(sm + KS_S0);
    float* s1f = (float*)(sm + KS_S1);
    int*   qmi = (int*)(sm + KS_QM);
    float* cmk = (float*)(sm + KS_CM);
    float* zs  = (float*)(sm + KS_ZS);
    float* zc  = (float*)(sm + KS_ZC);
    if (tid < 128) {
        s0f[tid] = g_s0[b * LC_ + cB + tid];
        s1f[tid] = g_s1[b * LQ_ + qB + tid];
        qmi[tid] = Qmask[b * LQ_ + qB + tid];
        cmk[tid] = (float)Cmask[b * LC_ + cB + tid];
    }

    const __nv_bfloat16* CwH = (const __nv_bfloat16*)g_Cwhi;
    const __nv_bfloat16* CwL = (const __nv_bfloat16*)g_Cwlo;
    const __nv_bfloat16* QH  = (const __nv_bfloat16*)g_Qhi;
    const __nv_bfloat16* QL  = (const __nv_bfloat16*)g_Qlo;
    size_t Ca = (size_t)(b * D_) * LC_ + cB;
    size_t Qa = (size_t)(b * D_) * LQ_ + qB;

    #pragma unroll
    for (int pc = 0; pc < 2; pc++) {
        u32 st = sb + KS_BUF + pc * 32768;
        cpyT32<256, 2>(st,         CwH + Ca + (size_t)(pc * 32) * LC_, CwL + Ca + (size_t)(pc * 32) * LC_, LC_, tid);
        cpyT32<256, 2>(st + 16384, QH  + Qa + (size_t)(pc * 32) * LQ_, QL  + Qa + (size_t)(pc * 32) * LQ_, LQ_, tid);
        CP_COMMIT();
    }

    int wm = wid >> 2, wn = wid & 3;
    int m0w = wm * 64, n0w = wn * 32;
    float acc[4][4][4] = {};
    #pragma unroll
    for (int ci = 0; ci < 4; ci++) {
        if (ci < 3) CP_WAIT1(); else CP_WAIT0();
        __syncthreads();
        if (ci < 2) {
            int k0 = (ci + 2) * 32;
            u32 st = sb + KS_BUF + ((ci + 2) % 3) * 32768;
            cpyT32<256, 2>(st,         CwH + Ca + (size_t)k0 * LC_, CwL + Ca + (size_t)k0 * LC_, LC_, tid);
            cpyT32<256, 2>(st + 16384, QH  + Qa + (size_t)k0 * LQ_, QL  + Qa + (size_t)k0 * LQ_, LQ_, tid);
            CP_COMMIT();
        }
        u32 bb = sb + KS_BUF + (ci % 3) * 32768;
        mma_chunk<4, 1, 1, 2, 4096, 2, 2, 0>(acc, bb, bb + 16384, m0w, n0w, lane);
    }
    __syncthreads();

    int r = lane >> 2, cp = (lane & 3) * 2;
    float zrow[8] = {}, zcol[8] = {};
    u32 stg = sb + KS_BUF;  // single fp16 plane, pitch 272
    #pragma unroll
    for (int mi = 0; mi < 4; mi++) {
        int m0 = m0w + mi * 16 + r;
        float cmaM = cmk[m0]     * 16.f * __expf(s0f[m0]);
        float cmbM = cmk[m0 + 8] * 16.f * __expf(s0f[m0 + 8]);
        #pragma unroll
        for (int nj = 0; nj < 4; nj++) {
            int q0 = n0w + nj * 8 + cp;
            float s1a = s1f[q0], s1b = s1f[q0 + 1];
            int qa = qmi[q0], qb = qmi[q0 + 1];
            float e00 = qa ? __expf(acc[mi][nj][0] + s1a) * 0.0625f : 0.f;
            float e01 = qb ? __expf(acc[mi][nj][1] + s1b) * 0.0625f : 0.f;
            float e10 = qa ? __expf(acc[mi][nj][2] + s1a) * 0.0625f : 0.f;
            float e11 = qb ? __expf(acc[mi][nj][3] + s1b) * 0.0625f : 0.f;
            zrow[mi * 2]     += e00 + e01;
            zrow[mi * 2 + 1] += e10 + e11;
            zcol[nj * 2]     += cmaM * e00 + cmbM * e10;
            zcol[nj * 2 + 1] += cmaM * e01 + cmbM * e11;
            u32 h00 = (u32)__half_as_ushort(__float2half(e00));
            u32 h01 = (u32)__half_as_ushort(__float2half(e01));
            u32 h10 = (u32)__half_as_ushort(__float2half(e10));
            u32 h11 = (u32)__half_as_ushort(__float2half(e11));
            sts32(stg + m0 * 272 + q0 * 2,       h00 | (h01 << 16));
            sts32(stg + (m0 + 8) * 272 + q0 * 2, h10 | (h11 << 16));
        }
    }
    #pragma unroll
    for (int h = 0; h < 8; h++) {
        float v = zrow[h];
        v += __shfl_xor_sync(0xffffffffu, v, 1);
        v += __shfl_xor_sync(0xffffffffu, v, 2);
        if ((lane & 3) == 0) {
            int m = m0w + (h >> 1) * 16 + ((h & 1) ? 8 : 0) + r;
            zs[m * 4 + wn] = v;
        }
    }
    #pragma unroll
    for (int j = 0; j < 8; j++) {
        float v = zcol[j];
        v += __shfl_xor_sync(0xffffffffu, v, 4);
        v += __shfl_xor_sync(0xffffffffu, v, 8);
        v += __shfl_xor_sync(0xffffffffu, v, 16);
        zcol[j] = v;
    }
    if (lane < 4) {
        #pragma unroll
        for (int nj = 0; nj < 4; nj++) {
            zc[wm * 128 + n0w + nj * 8 + lane * 2]     = zcol[nj * 2];
            zc[wm * 128 + n0w + nj * 8 + lane * 2 + 1] = zcol[nj * 2 + 1];
        }
    }
    __syncthreads();
    // copy stage -> global (2048 16B chunks, coalesced)
    #pragma unroll
    for (int it = 0; it < 8; it++) {
        int idx = tid + it * 256;
        int chunk = idx & 15, c = idx >> 4;
        uint4 v = lds128(stg + c * 272 + chunk * 16);
        ((uint4*)g_E)[((((size_t)(b * LC_ + cB + c)) * LQ_ + qB) >> 3) + chunk] = v;
    }
    if (tid < 128) {
        g_Z1p[((size_t)b * LC_ + cB + tid) * 4 + qt] =
            zs[tid * 4] + zs[tid * 4 + 1] + zs[tid * 4 + 2] + zs[tid * 4 + 3];
        g_Z2p[((size_t)b * LQ_ + qB + tid) * 16 + blockIdx.y] = zc[tid] + zc[128 + tid];
    }
}

// =====================================================================
// k_T: T[q][d] = rZ2[q] * sum_c E''[c,q]*C'[d,c]. fp16, A 1-limb, B 2-limb.
// =====================================================================
#define KT_RZ 0
#define KT_BUF 1024
#define KT_STAGE 49152
#define KT_DYN (1024 + 3 * KT_STAGE)

__global__ void __launch_bounds__(512, 1) k_T() {
    extern __shared__ char sm[];
    u32 sb = s2u(sm);
    int tid = threadIdx.x, lane = tid & 31, wid = tid >> 5;
    int b = blockIdx.y, qB = blockIdx.x * 128;
    float* rzs = (float*)(sm + KT_RZ);
    if (tid < 128) {
        const float* p = &g_Z2p[((size_t)b * LQ_ + qB + tid) * 16];
        float s = 0.f;
        #pragma unroll
        for (int t = 0; t < 16; t++) s += p[t];
        rzs[tid] = 1.f / fmaxf(s, 1e-30f);
    }
    const __half* EP = (const __half*)g_E;
    const __half* CH = (const __half*)g_Cfhi;
    const __half* CL = (const __half*)g_Cflo;
    size_t Eoff = (size_t)(b * LC_) * LQ_ + qB;
    size_t Coff = (size_t)(b * D_) * LC_;

    #pragma unroll
    for (int pc = 0; pc < 2; pc++) {
        u32 st = sb + KT_BUF + pc * KT_STAGE;
        cpyT64<512, 1>(st,         EP + Eoff + (size_t)(pc * 64) * LQ_, EP, LQ_, tid);
        cpyN128<512, 2>(st + 16384, CH + Coff + pc * 64, CL + Coff + pc * 64, LC_, tid);
        CP_COMMIT();
    }

    int wm = wid >> 2, wn = wid & 3;
    int m0w = wm * 32, n0w = wn * 32;
    float acc[2][4][4] = {};
    for (int ci = 0; ci < 32; ci++) {
        if (ci < 31) CP_WAIT1(); else CP_WAIT0();
        __syncthreads();
        if (ci < 30) {
            int c0 = (ci + 2) * 64;
            u32 st = sb + KT_BUF + ((ci + 2) % 3) * KT_STAGE;
            cpyT64<512, 1>(st,         EP + Eoff + (size_t)c0 * LQ_, EP, LQ_, tid);
            cpyN128<512, 2>(st + 16384, CH + Coff + c0, CL + Coff + c0, LC_, tid);
            CP_COMMIT();
        }
        u32 bb = sb + KT_BUF + (ci % 3) * KT_STAGE;
        mma_chunk<2, 1, 0, 4, 8192, 1, 2, 1>(acc, bb, bb + 16384, m0w, n0w, lane);
    }

    int r = lane >> 2, cp = (lane & 3) * 2;
    #pragma unroll
    for (int mi = 0; mi < 2; mi++) {
        int q0 = m0w + mi * 16 + r;
        float rza = rzs[q0], rzb = rzs[q0 + 8];
        #pragma unroll
        for (int nj = 0; nj < 4; nj++) {
            int d0 = n0w + nj * 8 + cp;
            u32 h0, l0, h1, l1;
            size_t i0 = ((size_t)(b * LQ_ + qB + q0) * D_ + d0) >> 1;
            size_t i1 = ((size_t)(b * LQ_ + qB + q0 + 8) * D_ + d0) >> 1;
            splt16(acc[mi][nj][0] * rza, h0, l0); splt16(acc[mi][nj][1] * rza, h1, l1);
            g_Thi[i0] = h0 | (h1 << 16); g_Tlo[i0] = l0 | (l1 << 16);
            splt16(acc[mi][nj][2] * rzb, h0, l0); splt16(acc[mi][nj][3] * rzb, h1, l1);
            g_Thi[i1] = h0 | (h1 << 16); g_Tlo[i1] = l0 | (l1 << 16);
        }
    }
}

// =====================================================================
// k_AB: accQ = E''@Qf, accT = E''@T in one K sweep (all fp16, E 1-limb).
//   Stage = {E 16K | Q 32K | T 32K}; 2 stages.
// =====================================================================
#define KA_RZ 0
#define KA_BUF 1024
#define KA_STAGE 81920
#define KA_DYN (1024 + 2 * KA_STAGE)

__global__ void __launch_bounds__(512, 1) k_AB(const float* __restrict__ C,
                                               float* __restrict__ out) {
    extern __shared__ char sm[];
    u32 sb = s2u(sm);
    int tid = threadIdx.x, lane = tid & 31, wid = tid >> 5;
    int b = blockIdx.y, cB = blockIdx.x * 128;
    float* rzs = (float*)(sm + KA_RZ);
    if (tid < 128) {
        const float* p = &g_Z1p[((size_t)b * LC_ + cB + tid) * 4];
        rzs[tid] = 1.f / (p[0] + p[1] + p[2] + p[3]);
    }
    const __half* EP = (const __half*)g_E;
    const __half* QH = (const __half*)g_Qfhi;
    const __half* QL = (const __half*)g_Qflo;
    const __half* TH = (const __half*)g_Thi;
    const __half* TL = (const __half*)g_Tlo;
    size_t Eoff = ((size_t)b * LC_ + cB) * LQ_;
    size_t Qoff = (size_t)(b * D_) * LQ_;
    size_t Toff = (size_t)(b * LQ_) * D_;
    const float* Cb = C + (size_t)b * D_ * LC_ + cB;
    float* ob = out + (size_t)b * 4 * D_ * LC_ + cB;
    float* stg = (float*)(sm + KA_BUF);
    int wm = wid >> 2, wn = wid & 3;
    int m0w = wm * 32, n0w = wn * 32;
    int r = lane >> 2, cp = (lane & 3) * 2;

    {
        u32 st = sb + KA_BUF;
        cpyN128<512, 1>(st,         EP + Eoff, EP, LQ_, tid);
        cpyN128<512, 2>(st + 16384, QH + Qoff, QL + Qoff, LQ_, tid);
        cpyT64<512, 2> (st + 49152, TH + Toff, TL + Toff, D_, tid);
        CP_COMMIT();
    }

    float accQ[2][4][4] = {}, accT[2][4][4] = {};
    for (int ci = 0; ci < 8; ci++) {
        CP_WAIT0();
        __syncthreads();
        if (ci + 1 < 8) {
            int q0 = (ci + 1) * 64;
            u32 st = sb + KA_BUF + ((ci + 1) & 1) * KA_STAGE;
            cpyN128<512, 1>(st,         EP + Eoff + q0, EP, LQ_, tid);
            cpyN128<512, 2>(st + 16384, QH + Qoff + q0, QL + Qoff + q0, LQ_, tid);
            cpyT64<512, 2> (st + 49152, TH + Toff + (size_t)q0 * D_, TL + Toff + (size_t)q0 * D_, D_, tid);
            CP_COMMIT();
        }
        u32 bb = sb + KA_BUF + (ci & 1) * KA_STAGE;
        mma_chunk_dual(accQ, accT, bb, bb + 16384, bb + 49152, m0w, n0w, lane);
    }
    __syncthreads();

    // ---- accQ -> sections 0,1,2
    #pragma unroll
    for (int mi = 0; mi < 2; mi++) {
        int m0 = m0w + mi * 16 + r;
        float rza = rzs[m0], rzb = rzs[m0 + 8];
        #pragma unroll
        for (int nj = 0; nj < 4; nj++) {
            int n0 = n0w + nj * 8 + cp;
            stg[n0 * 132 + m0]           = accQ[mi][nj][0] * rza;
            stg[(n0 + 1) * 132 + m0]     = accQ[mi][nj][1] * rza;
            stg[n0 * 132 + m0 + 8]       = accQ[mi][nj][2] * rzb;
            stg[(n0 + 1) * 132 + m0 + 8] = accQ[mi][nj][3] * rzb;
        }
    }
    __syncthreads();
    for (int idx = tid; idx < 128 * 128; idx += 512) {
        int dd = idx >> 7, c = idx & 127;
        float a = stg[dd * 132 + c];
        float cv = Cb[(size_t)dd * LC_ + c];
        ob[(size_t)dd * LC_ + c]         = cv;
        ob[(size_t)(128 + dd) * LC_ + c] = a;
        ob[(size_t)(256 + dd) * LC_ + c] = cv * a;
    }
    __syncthreads();
    // ---- accT -> section 3
    #pragma unroll
    for (int mi = 0; mi < 2; mi++) {
        int m0 = m0w + mi * 16 + r;
        float rza = rzs[m0], rzb = rzs[m0 + 8];
        #pragma unroll
        for (int nj = 0; nj < 4; nj++) {
            int n0 = n0w + nj * 8 + cp;
            stg[n0 * 132 + m0]           = accT[mi][nj][0] * rza;
            stg[(n0 + 1) * 132 + m0]     = accT[mi][nj][1] * rza;
            stg[n0 * 132 + m0 + 8]       = accT[mi][nj][2] * rzb;
            stg[(n0 + 1) * 132 + m0 + 8] = accT[mi][nj][3] * rzb;
        }
    }
    __syncthreads();
    for (int idx = tid; idx < 128 * 128; idx += 512) {
        int dd = idx >> 7, c = idx & 127;
        float bm = stg[dd * 132 + c];
        float cv = Cb[(size_t)dd * LC_ + c];
        ob[(size_t)(384 + dd) * LC_ + c] = cv * bm;
    }
}

// =====================================================================
extern "C" void kernel_launch(void* const* d_in, const int* in_sizes, int n_in,
                              void* d_out, int out_size) {
    const float* C     = (const float*)d_in[0];
    const float* Q     = (const float*)d_in[1];
    const int*   Cmask = (const int*)  d_in[2];
    const int*   Qmask = (const int*)  d_in[3];
    const float* w_c   = (const float*)d_in[4];
    const float* w_q   = (const float*)d_in[5];
    const float* w_mul = (const float*)d_in[6];
    const float* bias  = (const float*)d_in[7];
    float* out = (float*)d_out;

    cudaFuncSetAttribute(k_S,  cudaFuncAttributeMaxDynamicSharedMemorySize, KS_DYN);
    cudaFuncSetAttribute(k_T,  cudaFuncAttributeMaxDynamicSharedMemorySize, KT_DYN);
    cudaFuncSetAttribute(k_AB, cudaFuncAttributeMaxDynamicSharedMemorySize, KA_DYN);

    k_cvtC<<<dim3(16, 32), 256>>>(C, Cmask, w_mul, w_c, bias);
    k_cvtQ<<<32, 512>>>(Q, w_q);
    k_S<<<dim3(4, 16, 32), 256, KS_DYN>>>(Qmask, Cmask);
    k_T<<<dim3(4, 32), 512, KT_DYN>>>();
    k_AB<<<dim3(16, 32), 512, KA_DYN>>>(C, out);
}

// round 14
// speedup vs baseline: 1.5264x; 1.0810x over previous
#include <cuda_runtime.h>
#include <cuda_bf16.h>
#include <cuda_fp16.h>
#include <cstdint>

#define B_   32
#define D_   128
#define LC_  2048
#define LQ_  512

typedef unsigned int u32;

// ---------------- scratch planes ----------------
__device__ u32 g_E[(size_t)B_ * LC_ * LQ_ / 2];        // E'' fp16 single plane
__device__ u32 g_Cwhi[(size_t)B_ * D_ * LC_ / 2];      // C*w_mul bf16 2L (k_S)
__device__ u32 g_Cwlo[(size_t)B_ * D_ * LC_ / 2];
__device__ u32 g_Cfhi[(size_t)B_ * D_ * LC_ / 2];      // C' = C*cmask*16*exp(s0), fp16 2L (k_T)
__device__ u32 g_Cflo[(size_t)B_ * D_ * LC_ / 2];
__device__ u32 g_Qhi[(size_t)B_ * D_ * LQ_ / 2];       // Q bf16 2L (k_S)
__device__ u32 g_Qlo[(size_t)B_ * D_ * LQ_ / 2];
__device__ u32 g_Qfhi[(size_t)B_ * D_ * LQ_ / 2];      // Q fp16 2L (k_AB)
__device__ u32 g_Qflo[(size_t)B_ * D_ * LQ_ / 2];
__device__ u32 g_T[(size_t)B_ * LQ_ * D_ / 2];         // T fp16 single plane
__device__ float g_s0[B_ * LC_];
__device__ float g_s1[B_ * LQ_];
__device__ float g_Z1p[B_ * LC_ * 4];
__device__ float g_Z2p[B_ * LQ_ * 16];

// ---------------- helpers ----------------
__device__ __forceinline__ u32 s2u(const void* p) {
    u32 a; asm("{ .reg .u64 t; cvta.to.shared.u64 t, %1; cvt.u32.u64 %0, t; }" : "=r"(a) : "l"(p));
    return a;
}
#define SWZ(x) ((u32)(x) ^ ((((u32)(x)) >> 3) & 0x70))

__device__ __forceinline__ void cpa16(u32 dst, const void* src) {
    asm volatile("cp.async.cg.shared.global [%0], [%1], 16;" :: "r"(dst), "l"(src));
}
#define CP_COMMIT() asm volatile("cp.async.commit_group;")
#define CP_WAIT0()  asm volatile("cp.async.wait_group 0;")
#define CP_WAIT1()  asm volatile("cp.async.wait_group 1;")

__device__ __forceinline__ void splt(float v, u32 &hi, u32 &lo) {     // bf16 2-limb
    __nv_bfloat16 h = __float2bfloat16(v);
    __nv_bfloat16 l = __float2bfloat16(v - __bfloat162float(h));
    hi = (u32)__bfloat16_as_ushort(h);
    lo = (u32)__bfloat16_as_ushort(l);
}
__device__ __forceinline__ void splt16(float v, u32 &hi, u32 &lo) {   // fp16 2-limb
    __half h = __float2half(v);
    __half l = __float2half(v - __half2float(h));
    hi = (u32)__half_as_ushort(h);
    lo = (u32)__half_as_ushort(l);
}

__device__ __forceinline__ void ldsm4(u32 addr, u32 r[4]) {
    asm volatile("ldmatrix.sync.aligned.m8n8.x4.shared.b16 {%0,%1,%2,%3}, [%4];"
                 : "=r"(r[0]), "=r"(r[1]), "=r"(r[2]), "=r"(r[3]) : "r"(addr));
}
__device__ __forceinline__ void ldsm4t(u32 addr, u32 r[4]) {
    asm volatile("ldmatrix.sync.aligned.m8n8.x4.trans.shared.b16 {%0,%1,%2,%3}, [%4];"
                 : "=r"(r[0]), "=r"(r[1]), "=r"(r[2]), "=r"(r[3]) : "r"(addr));
}
template<int F16>
__device__ __forceinline__ void mmaop(float d[4], const u32 a[4], u32 b0, u32 b1) {
    if (F16)
        asm volatile("mma.sync.aligned.m16n8k16.row.col.f32.f16.f16.f32 "
                     "{%0,%1,%2,%3}, {%4,%5,%6,%7}, {%8,%9}, {%0,%1,%2,%3};"
                     : "+f"(d[0]), "+f"(d[1]), "+f"(d[2]), "+f"(d[3])
                     : "r"(a[0]), "r"(a[1]), "r"(a[2]), "r"(a[3]), "r"(b0), "r"(b1));
    else
        asm volatile("mma.sync.aligned.m16n8k16.row.col.f32.bf16.bf16.f32 "
                     "{%0,%1,%2,%3}, {%4,%5,%6,%7}, {%8,%9}, {%0,%1,%2,%3};"
                     : "+f"(d[0]), "+f"(d[1]), "+f"(d[2]), "+f"(d[3])
                     : "r"(a[0]), "r"(a[1]), "r"(a[2]), "r"(a[3]), "r"(b0), "r"(b1));
}
__device__ __forceinline__ uint4 lds128(u32 a) {
    uint4 v;
    asm volatile("ld.shared.v4.b32 {%0,%1,%2,%3}, [%4];"
                 : "=r"(v.x), "=r"(v.y), "=r"(v.z), "=r"(v.w) : "r"(a));
    return v;
}
__device__ __forceinline__ void sts32(u32 a, u32 v) { asm volatile("st.shared.b32 [%0], %1;" :: "r"(a), "r"(v)); }

// ---------------- chunk copies (L = limb count) ----------------
template<int NT, int L, typename H>
__device__ __forceinline__ void cpyT64(u32 dstBase, const H* srcHi, const H* srcLo,
                                       size_t rowStride, int tid) {
    #pragma unroll
    for (int t = 0; t < (1024 * L) / NT; t++) {
        int u = tid + t * NT;
        int limb = u >> 10, rem = u & 1023;
        int row = rem >> 4, ucol = rem & 15;
        const H* src = (limb ? srcLo : srcHi) + (size_t)row * rowStride + ucol * 8;
        u32 dst = dstBase + limb * 16384 + (ucol >> 3) * 8192 + SWZ(row * 128 + (ucol & 7) * 16);
        cpa16(dst, src);
    }
}
template<int NT, int L, typename H>
__device__ __forceinline__ void cpyT32(u32 dstBase, const H* srcHi, const H* srcLo,
                                       size_t rowStride, int tid) {
    #pragma unroll
    for (int t = 0; t < (512 * L) / NT; t++) {
        int u = tid + t * NT;
        int limb = u >> 9, rem = u & 511;
        int row = rem >> 4, ucol = rem & 15;
        const H* src = (limb ? srcLo : srcHi) + (size_t)row * rowStride + ucol * 8;
        u32 dst = dstBase + limb * 8192 + (ucol >> 3) * 4096 + SWZ(row * 128 + (ucol & 7) * 16);
        cpa16(dst, src);
    }
}
template<int NT, int L, typename H>
__device__ __forceinline__ void cpyN128(u32 dstBase, const H* srcHi, const H* srcLo,
                                        size_t rowStride, int tid) {
    #pragma unroll
    for (int t = 0; t < (1024 * L) / NT; t++) {
        int u = tid + t * NT;
        int limb = u >> 10, rem = u & 1023;
        int row = rem >> 3, ucol = rem & 7;
        const H* src = (limb ? srcLo : srcHi) + (size_t)row * rowStride + ucol * 8;
        u32 dst = dstBase + limb * 16384 + SWZ(row * 128 + ucol * 16);
        cpa16(dst, src);
    }
}

// ---------------- warp MMA over one chunk ----------------------------------
template<int MI, int AT, int BT, int KSTEPS, int SUB, int AL, int BL, int F16>
__device__ __forceinline__ void mma_chunk(float acc[MI][4][4], u32 Ab, u32 Bb,
                                          int m0w, int n0w, int lane) {
    const int LO = 2 * SUB;
    #pragma unroll
    for (int ks = 0; ks < KSTEPS; ks++) {
        int k0 = ks * 16;
        u32 ah[MI][4], al[MI][4];
        #pragma unroll
        for (int mi = 0; mi < MI; mi++) {
            int m0 = m0w + mi * 16;
            u32 ad;
            if (AT) {
                int r = k0 + (lane & 7) + ((lane & 16) ? 8 : 0);
                int c = m0 + ((lane & 8) ? 8 : 0);
                ad = Ab + ((u32)(c >> 6)) * SUB + SWZ(r * 128 + (c & 63) * 2);
                ldsm4t(ad, ah[mi]); if (AL == 2) ldsm4t(ad + LO, al[mi]);
            } else {
                int r = m0 + (lane & 15);
                int c = k0 + ((lane >> 4) << 3);
                ad = Ab + SWZ(r * 128 + c * 2);
                ldsm4(ad, ah[mi]); if (AL == 2) ldsm4(ad + LO, al[mi]);
            }
        }
        u32 bh[4][2], bl[4][2];
        #pragma unroll
        for (int nj2 = 0; nj2 < 2; nj2++) {
            int n0 = n0w + nj2 * 16;
            u32 bd;
            u32 t[4], tl[4];
            if (BT) {
                int r = k0 + (lane & 7) + ((lane & 8) ? 8 : 0);
                int c = n0 + ((lane & 16) ? 8 : 0);
                bd = Bb + ((u32)(c >> 6)) * SUB + SWZ(r * 128 + (c & 63) * 2);
                ldsm4t(bd, t); if (BL == 2) ldsm4t(bd + LO, tl);
            } else {
                int r = n0 + (lane & 7) + ((lane & 16) ? 8 : 0);
                int c = k0 + ((lane & 8) ? 8 : 0);
                bd = Bb + SWZ(r * 128 + c * 2);
                ldsm4(bd, t); if (BL == 2) ldsm4(bd + LO, tl);
            }
            bh[nj2 * 2][0] = t[0];  bh[nj2 * 2][1] = t[1];
            bh[nj2 * 2 + 1][0] = t[2]; bh[nj2 * 2 + 1][1] = t[3];
            if (BL == 2) {
                bl[nj2 * 2][0] = tl[0]; bl[nj2 * 2][1] = tl[1];
                bl[nj2 * 2 + 1][0] = tl[2]; bl[nj2 * 2 + 1][1] = tl[3];
            }
        }
        #pragma unroll
        for (int mi = 0; mi < MI; mi++)
            #pragma unroll
            for (int nj = 0; nj < 4; nj++) {
                mmaop<F16>(acc[mi][nj], ah[mi], bh[nj][0], bh[nj][1]);
                if (BL == 2) mmaop<F16>(acc[mi][nj], ah[mi], bl[nj][0], bl[nj][1]);
                if (AL == 2) mmaop<F16>(acc[mi][nj], al[mi], bh[nj][0], bh[nj][1]);
            }
    }
}

// ---------------- dual-B warp MMA for k_AB: E 1L, Q 2L, T 1L (all fp16) ----
__device__ __forceinline__ void mma_chunk_dual(float accQ[2][4][4], float accT[2][4][4],
                                               u32 Ab, u32 Bq, u32 Bt,
                                               int m0w, int n0w, int lane) {
    #pragma unroll
    for (int ks = 0; ks < 4; ks++) {
        int k0 = ks * 16;
        u32 ah[2][4];
        #pragma unroll
        for (int mi = 0; mi < 2; mi++) {
            int m0 = m0w + mi * 16;
            int r = m0 + (lane & 15);
            int c = k0 + ((lane >> 4) << 3);
            ldsm4(Ab + SWZ(r * 128 + c * 2), ah[mi]);
        }
        // --- Q: natural 2-limb ---
        {
            u32 bh[4][2], bl[4][2];
            #pragma unroll
            for (int nj2 = 0; nj2 < 2; nj2++) {
                int n0 = n0w + nj2 * 16;
                int r = n0 + (lane & 7) + ((lane & 16) ? 8 : 0);
                int c = k0 + ((lane & 8) ? 8 : 0);
                u32 bd = Bq + SWZ(r * 128 + c * 2);
                u32 t[4], tl[4];
                ldsm4(bd, t); ldsm4(bd + 16384, tl);
                bh[nj2 * 2][0] = t[0];  bh[nj2 * 2][1] = t[1];
                bh[nj2 * 2 + 1][0] = t[2]; bh[nj2 * 2 + 1][1] = t[3];
                bl[nj2 * 2][0] = tl[0]; bl[nj2 * 2][1] = tl[1];
                bl[nj2 * 2 + 1][0] = tl[2]; bl[nj2 * 2 + 1][1] = tl[3];
            }
            #pragma unroll
            for (int mi = 0; mi < 2; mi++)
                #pragma unroll
                for (int nj = 0; nj < 4; nj++) {
                    mmaop<1>(accQ[mi][nj], ah[mi], bh[nj][0], bh[nj][1]);
                    mmaop<1>(accQ[mi][nj], ah[mi], bl[nj][0], bl[nj][1]);
                }
        }
        // --- T: k-major single-limb (SUB=8192) ---
        {
            u32 bh[4][2];
            #pragma unroll
            for (int nj2 = 0; nj2 < 2; nj2++) {
                int n0 = n0w + nj2 * 16;
                int r = k0 + (lane & 7) + ((lane & 8) ? 8 : 0);
                int c = n0 + ((lane & 16) ? 8 : 0);
                u32 bd = Bt + ((u32)(c >> 6)) * 8192 + SWZ(r * 128 + (c & 63) * 2);
                u32 t[4];
                ldsm4t(bd, t);
                bh[nj2 * 2][0] = t[0];  bh[nj2 * 2][1] = t[1];
                bh[nj2 * 2 + 1][0] = t[2]; bh[nj2 * 2 + 1][1] = t[3];
            }
            #pragma unroll
            for (int mi = 0; mi < 2; mi++)
                #pragma unroll
                for (int nj = 0; nj < 4; nj++)
                    mmaop<1>(accT[mi][nj], ah[mi], bh[nj][0], bh[nj][1]);
        }
    }
}

// =====================================================================
// k_cvtC: pass1: Cw planes + s0 reduce; pass2: C' = C*cmask*16*exp(s0) fp16 2L
// =====================================================================
__global__ void __launch_bounds__(256) k_cvtC(const float* __restrict__ C,
                                              const int* __restrict__ Cmask,
                                              const float* __restrict__ w_mul,
                                              const float* __restrict__ w_c,
                                              const float* __restrict__ bias) {
    __shared__ float wc[128], wm[128], zb[512], s0s[128];
    int tid = threadIdx.x;
    int b = blockIdx.y, cB = blockIdx.x * 128;
    if (tid < 128) { wc[tid] = w_c[tid]; wm[tid] = w_mul[tid]; }
    __syncthreads();
    int cp = tid & 63, dq = tid >> 6;
    int c0 = cB + 2 * cp;
    int m0 = Cmask[b * LC_ + c0], m1 = Cmask[b * LC_ + c0 + 1];
    float s0e = 0.f, s0o = 0.f;
    float2 v[32];
    #pragma unroll
    for (int i = 0; i < 32; i++) {
        int d = dq * 32 + i;
        size_t gi = ((size_t)(b * D_ + d)) * LC_ + c0;
        v[i] = *(const float2*)(C + gi);
        s0e += v[i].x * wc[d]; s0o += v[i].y * wc[d];
        u32 h0, l0, h1, l1;
        splt(v[i].x * wm[d], h0, l0); splt(v[i].y * wm[d], h1, l1);
        g_Cwhi[gi >> 1] = h0 | (h1 << 16);
        g_Cwlo[gi >> 1] = l0 | (l1 << 16);
    }
    zb[dq * 128 + 2 * cp] = s0e;
    zb[dq * 128 + 2 * cp + 1] = s0o;
    __syncthreads();
    if (tid < 128) {
        float s0 = zb[tid] + zb[128 + tid] + zb[256 + tid] + zb[384 + tid] + bias[0];
        g_s0[b * LC_ + cB + tid] = s0;
        s0s[tid] = s0;
    }
    __syncthreads();
    float Ma0 = m0 ? 16.f * __expf(s0s[2 * cp])     : 0.f;
    float Ma1 = m1 ? 16.f * __expf(s0s[2 * cp + 1]) : 0.f;
    #pragma unroll
    for (int i = 0; i < 32; i++) {
        int d = dq * 32 + i;
        size_t gi = ((size_t)(b * D_ + d)) * LC_ + c0;
        u32 h0, l0, h1, l1;
        splt16(v[i].x * Ma0, h0, l0); splt16(v[i].y * Ma1, h1, l1);
        g_Cfhi[gi >> 1] = h0 | (h1 << 16);
        g_Cflo[gi >> 1] = l0 | (l1 << 16);
    }
}

// =====================================================================
// k_cvtQ: Q -> bf16 2L (k_S) + fp16 2L (k_AB), fused s1
// =====================================================================
__global__ void __launch_bounds__(512) k_cvtQ(const float* __restrict__ Q,
                                              const float* __restrict__ w_q) {
    __shared__ float wq[128], zb[1024];
    int tid = threadIdx.x;
    int b = blockIdx.x;
    if (tid < 128) wq[tid] = w_q[tid];
    __syncthreads();
    int qp = tid & 255, dh = tid >> 8;
    int q0 = 2 * qp;
    float s1e = 0.f, s1o = 0.f;
    #pragma unroll 4
    for (int i = 0; i < 64; i++) {
        int d = dh * 64 + i;
        size_t gi = ((size_t)(b * D_ + d)) * LQ_ + q0;
        float2 v = *(const float2*)(Q + gi);
        s1e += v.x * wq[d]; s1o += v.y * wq[d];
        u32 h0, l0, h1, l1;
        splt(v.x, h0, l0); splt(v.y, h1, l1);
        g_Qhi[gi >> 1] = h0 | (h1 << 16);
        g_Qlo[gi >> 1] = l0 | (l1 << 16);
        splt16(v.x, h0, l0); splt16(v.y, h1, l1);
        g_Qfhi[gi >> 1] = h0 | (h1 << 16);
        g_Qflo[gi >> 1] = l0 | (l1 << 16);
    }
    zb[dh * 512 + q0]     = s1e;
    zb[dh * 512 + q0 + 1] = s1o;
    __syncthreads();
    g_s1[b * LQ_ + tid] = zb[tid] + zb[512 + tid];
}

// =====================================================================
// k_S: E'' = qmask*exp(s2+s1)/16 (fp16, 1 plane); Z1/Z2 partials.
// =====================================================================
#define KS_S0 0
#define KS_S1 512
#define KS_QM 1024
#define KS_CM 1536
#define KS_ZS 2048
#define KS_ZC 4096
#define KS_BUF 8192
#define KS_DYN (8192 + 3 * 32768)

__global__ void __launch_bounds__(256, 2) k_S(const int* __restrict__ Qmask,
                                              const int* __restrict__ Cmask) {
    extern __shared__ char sm[];
    u32 sb = s2u(sm);
    int tid = threadIdx.x, lane = tid & 31, wid = tid >> 5;
    int b = blockIdx.z, cB = blockIdx.y * 128, qB = blockIdx.x * 128, qt = blockIdx.x;
    float* s0f = (float*)(sm + KS_S0);
    float* s1f = (float*)(sm + KS_S1);
    int*   qmi = (int*)(sm + KS_QM);
    float* cmk = (float*)(sm + KS_CM);
    float* zs  = (float*)(sm + KS_ZS);
    float* zc  = (float*)(sm + KS_ZC);
    if (tid < 128) {
        s0f[tid] = g_s0[b * LC_ + cB + tid];
        s1f[tid] = g_s1[b * LQ_ + qB + tid];
        qmi[tid] = Qmask[b * LQ_ + qB + tid];
        cmk[tid] = (float)Cmask[b * LC_ + cB + tid];
    }

    const __nv_bfloat16* CwH = (const __nv_bfloat16*)g_Cwhi;
    const __nv_bfloat16* CwL = (const __nv_bfloat16*)g_Cwlo;
    const __nv_bfloat16* QH  = (const __nv_bfloat16*)g_Qhi;
    const __nv_bfloat16* QL  = (const __nv_bfloat16*)g_Qlo;
    size_t Ca = (size_t)(b * D_) * LC_ + cB;
    size_t Qa = (size_t)(b * D_) * LQ_ + qB;

    #pragma unroll
    for (int pc = 0; pc < 2; pc++) {
        u32 st = sb + KS_BUF + pc * 32768;
        cpyT32<256, 2>(st,         CwH + Ca + (size_t)(pc * 32) * LC_, CwL + Ca + (size_t)(pc * 32) * LC_, LC_, tid);
        cpyT32<256, 2>(st + 16384, QH  + Qa + (size_t)(pc * 32) * LQ_, QL  + Qa + (size_t)(pc * 32) * LQ_, LQ_, tid);
        CP_COMMIT();
    }

    int wm = wid >> 2, wn = wid & 3;
    int m0w = wm * 64, n0w = wn * 32;
    float acc[4][4][4] = {};
    #pragma unroll
    for (int ci = 0; ci < 4; ci++) {
        if (ci < 3) CP_WAIT1(); else CP_WAIT0();
        __syncthreads();
        if (ci < 2) {
            int k0 = (ci + 2) * 32;
            u32 st = sb + KS_BUF + ((ci + 2) % 3) * 32768;
            cpyT32<256, 2>(st,         CwH + Ca + (size_t)k0 * LC_, CwL + Ca + (size_t)k0 * LC_, LC_, tid);
            cpyT32<256, 2>(st + 16384, QH  + Qa + (size_t)k0 * LQ_, QL  + Qa + (size_t)k0 * LQ_, LQ_, tid);
            CP_COMMIT();
        }
        u32 bb = sb + KS_BUF + (ci % 3) * 32768;
        mma_chunk<4, 1, 1, 2, 4096, 2, 2, 0>(acc, bb, bb + 16384, m0w, n0w, lane);
    }
    __syncthreads();

    int r = lane >> 2, cp = (lane & 3) * 2;
    float zrow[8] = {}, zcol[8] = {};
    u32 stg = sb + KS_BUF;
    #pragma unroll
    for (int mi = 0; mi < 4; mi++) {
        int m0 = m0w + mi * 16 + r;
        float cmaM = cmk[m0]     * 16.f * __expf(s0f[m0]);
        float cmbM = cmk[m0 + 8] * 16.f * __expf(s0f[m0 + 8]);
        #pragma unroll
        for (int nj = 0; nj < 4; nj++) {
            int q0 = n0w + nj * 8 + cp;
            float s1a = s1f[q0], s1b = s1f[q0 + 1];
            int qa = qmi[q0], qb = qmi[q0 + 1];
            float e00 = qa ? __expf(acc[mi][nj][0] + s1a) * 0.0625f : 0.f;
            float e01 = qb ? __expf(acc[mi][nj][1] + s1b) * 0.0625f : 0.f;
            float e10 = qa ? __expf(acc[mi][nj][2] + s1a) * 0.0625f : 0.f;
            float e11 = qb ? __expf(acc[mi][nj][3] + s1b) * 0.0625f : 0.f;
            zrow[mi * 2]     += e00 + e01;
            zrow[mi * 2 + 1] += e10 + e11;
            zcol[nj * 2]     += cmaM * e00 + cmbM * e10;
            zcol[nj * 2 + 1] += cmaM * e01 + cmbM * e11;
            u32 h00 = (u32)__half_as_ushort(__float2half(e00));
            u32 h01 = (u32)__half_as_ushort(__float2half(e01));
            u32 h10 = (u32)__half_as_ushort(__float2half(e10));
            u32 h11 = (u32)__half_as_ushort(__float2half(e11));
            sts32(stg + m0 * 272 + q0 * 2,       h00 | (h01 << 16));
            sts32(stg + (m0 + 8) * 272 + q0 * 2, h10 | (h11 << 16));
        }
    }
    #pragma unroll
    for (int h = 0; h < 8; h++) {
        float v = zrow[h];
        v += __shfl_xor_sync(0xffffffffu, v, 1);
        v += __shfl_xor_sync(0xffffffffu, v, 2);
        if ((lane & 3) == 0) {
            int m = m0w + (h >> 1) * 16 + ((h & 1) ? 8 : 0) + r;
            zs[m * 4 + wn] = v;
        }
    }
    #pragma unroll
    for (int j = 0; j < 8; j++) {
        float v = zcol[j];
        v += __shfl_xor_sync(0xffffffffu, v, 4);
        v += __shfl_xor_sync(0xffffffffu, v, 8);
        v += __shfl_xor_sync(0xffffffffu, v, 16);
        zcol[j] = v;
    }
    if (lane < 4) {
        #pragma unroll
        for (int nj = 0; nj < 4; nj++) {
            zc[wm * 128 + n0w + nj * 8 + lane * 2]     = zcol[nj * 2];
            zc[wm * 128 + n0w + nj * 8 + lane * 2 + 1] = zcol[nj * 2 + 1];
        }
    }
    __syncthreads();
    #pragma unroll
    for (int it = 0; it < 8; it++) {
        int idx = tid + it * 256;
        int chunk = idx & 15, c = idx >> 4;
        uint4 v = lds128(stg + c * 272 + chunk * 16);
        ((uint4*)g_E)[((((size_t)(b * LC_ + cB + c)) * LQ_ + qB) >> 3) + chunk] = v;
    }
    if (tid < 128) {
        g_Z1p[((size_t)b * LC_ + cB + tid) * 4 + qt] =
            zs[tid * 4] + zs[tid * 4 + 1] + zs[tid * 4 + 2] + zs[tid * 4 + 3];
        g_Z2p[((size_t)b * LQ_ + qB + tid) * 16 + blockIdx.y] = zc[tid] + zc[128 + tid];
    }
}

// =====================================================================
// k_T: T[q][d] = rZ2[q] * sum_c E''[c,q]*C'[d,c]; store fp16 single plane.
// =====================================================================
#define KT_RZ 0
#define KT_BUF 1024
#define KT_STAGE 49152
#define KT_DYN (1024 + 3 * KT_STAGE)

__global__ void __launch_bounds__(512, 1) k_T() {
    extern __shared__ char sm[];
    u32 sb = s2u(sm);
    int tid = threadIdx.x, lane = tid & 31, wid = tid >> 5;
    int b = blockIdx.y, qB = blockIdx.x * 128;
    float* rzs = (float*)(sm + KT_RZ);
    if (tid < 128) {
        const float* p = &g_Z2p[((size_t)b * LQ_ + qB + tid) * 16];
        float s = 0.f;
        #pragma unroll
        for (int t = 0; t < 16; t++) s += p[t];
        rzs[tid] = 1.f / fmaxf(s, 1e-30f);
    }
    const __half* EP = (const __half*)g_E;
    const __half* CH = (const __half*)g_Cfhi;
    const __half* CL = (const __half*)g_Cflo;
    size_t Eoff = (size_t)(b * LC_) * LQ_ + qB;
    size_t Coff = (size_t)(b * D_) * LC_;

    #pragma unroll
    for (int pc = 0; pc < 2; pc++) {
        u32 st = sb + KT_BUF + pc * KT_STAGE;
        cpyT64<512, 1>(st,          EP + Eoff + (size_t)(pc * 64) * LQ_, EP, LQ_, tid);
        cpyN128<512, 2>(st + 16384, CH + Coff + pc * 64, CL + Coff + pc * 64, LC_, tid);
        CP_COMMIT();
    }

    int wm = wid >> 2, wn = wid & 3;
    int m0w = wm * 32, n0w = wn * 32;
    float acc[2][4][4] = {};
    for (int ci = 0; ci < 32; ci++) {
        if (ci < 31) CP_WAIT1(); else CP_WAIT0();
        __syncthreads();
        if (ci < 30) {
            int c0 = (ci + 2) * 64;
            u32 st = sb + KT_BUF + ((ci + 2) % 3) * KT_STAGE;
            cpyT64<512, 1>(st,          EP + Eoff + (size_t)c0 * LQ_, EP, LQ_, tid);
            cpyN128<512, 2>(st + 16384, CH + Coff + c0, CL + Coff + c0, LC_, tid);
            CP_COMMIT();
        }
        u32 bb = sb + KT_BUF + (ci % 3) * KT_STAGE;
        mma_chunk<2, 1, 0, 4, 8192, 1, 2, 1>(acc, bb, bb + 16384, m0w, n0w, lane);
    }

    int r = lane >> 2, cp = (lane & 3) * 2;
    #pragma unroll
    for (int mi = 0; mi < 2; mi++) {
        int q0 = m0w + mi * 16 + r;
        float rza = rzs[q0], rzb = rzs[q0 + 8];
        #pragma unroll
        for (int nj = 0; nj < 4; nj++) {
            int d0 = n0w + nj * 8 + cp;
            size_t i0 = ((size_t)(b * LQ_ + qB + q0) * D_ + d0) >> 1;
            size_t i1 = ((size_t)(b * LQ_ + qB + q0 + 8) * D_ + d0) >> 1;
            u32 h0 = (u32)__half_as_ushort(__float2half(acc[mi][nj][0] * rza));
            u32 h1 = (u32)__half_as_ushort(__float2half(acc[mi][nj][1] * rza));
            g_T[i0] = h0 | (h1 << 16);
            h0 = (u32)__half_as_ushort(__float2half(acc[mi][nj][2] * rzb));
            h1 = (u32)__half_as_ushort(__float2half(acc[mi][nj][3] * rzb));
            g_T[i1] = h0 | (h1 << 16);
        }
    }
}

// =====================================================================
// k_AB: accQ = E''@Qf (2L), accT = E''@T (1L) in one K sweep.
//   Stage = {E 16K | Q 32K | T 16K} = 64K; 3 stages.
// =====================================================================
#define KA_RZ 0
#define KA_BUF 1024
#define KA_STAGE 65536
#define KA_DYN (1024 + 3 * KA_STAGE)

__global__ void __launch_bounds__(512, 1) k_AB(const float* __restrict__ C,
                                               float* __restrict__ out) {
    extern __shared__ char sm[];
    u32 sb = s2u(sm);
    int tid = threadIdx.x, lane = tid & 31, wid = tid >> 5;
    int b = blockIdx.y, cB = blockIdx.x * 128;
    float* rzs = (float*)(sm + KA_RZ);
    if (tid < 128) {
        const float* p = &g_Z1p[((size_t)b * LC_ + cB + tid) * 4];
        rzs[tid] = 1.f / (p[0] + p[1] + p[2] + p[3]);
    }
    const __half* EP = (const __half*)g_E;
    const __half* QH = (const __half*)g_Qfhi;
    const __half* QL = (const __half*)g_Qflo;
    const __half* TP = (const __half*)g_T;
    size_t Eoff = ((size_t)b * LC_ + cB) * LQ_;
    size_t Qoff = (size_t)(b * D_) * LQ_;
    size_t Toff = (size_t)(b * LQ_) * D_;
    const float* Cb = C + (size_t)b * D_ * LC_ + cB;
    float* ob = out + (size_t)b * 4 * D_ * LC_ + cB;
    float* stg = (float*)(sm + KA_BUF);
    int wm = wid >> 2, wn = wid & 3;
    int m0w = wm * 32, n0w = wn * 32;
    int r = lane >> 2, cp = (lane & 3) * 2;

    #pragma unroll
    for (int pc = 0; pc < 2; pc++) {
        int q0 = pc * 64;
        u32 st = sb + KA_BUF + pc * KA_STAGE;
        cpyN128<512, 1>(st,         EP + Eoff + q0, EP, LQ_, tid);
        cpyN128<512, 2>(st + 16384, QH + Qoff + q0, QL + Qoff + q0, LQ_, tid);
        cpyT64<512, 1> (st + 49152, TP + Toff + (size_t)q0 * D_, TP, D_, tid);
        CP_COMMIT();
    }

    float accQ[2][4][4] = {}, accT[2][4][4] = {};
    for (int ci = 0; ci < 8; ci++) {
        if (ci < 7) CP_WAIT1(); else CP_WAIT0();
        __syncthreads();
        if (ci < 6) {
            int q0 = (ci + 2) * 64;
            u32 st = sb + KA_BUF + ((ci + 2) % 3) * KA_STAGE;
            cpyN128<512, 1>(st,         EP + Eoff + q0, EP, LQ_, tid);
            cpyN128<512, 2>(st + 16384, QH + Qoff + q0, QL + Qoff + q0, LQ_, tid);
            cpyT64<512, 1> (st + 49152, TP + Toff + (size_t)q0 * D_, TP, D_, tid);
            CP_COMMIT();
        }
        u32 bb = sb + KA_BUF + (ci % 3) * KA_STAGE;
        mma_chunk_dual(accQ, accT, bb, bb + 16384, bb + 49152, m0w, n0w, lane);
    }
    __syncthreads();

    // ---- accQ -> sections 0,1,2
    #pragma unroll
    for (int mi = 0; mi < 2; mi++) {
        int m0 = m0w + mi * 16 + r;
        float rza = rzs[m0], rzb = rzs[m0 + 8];
        #pragma unroll
        for (int nj = 0; nj < 4; nj++) {
            int n0 = n0w + nj * 8 + cp;
            stg[n0 * 132 + m0]           = accQ[mi][nj][0] * rza;
            stg[(n0 + 1) * 132 + m0]     = accQ[mi][nj][1] * rza;
            stg[n0 * 132 + m0 + 8]       = accQ[mi][nj][2] * rzb;
            stg[(n0 + 1) * 132 + m0 + 8] = accQ[mi][nj][3] * rzb;
        }
    }
    __syncthreads();
    for (int idx = tid; idx < 128 * 128; idx += 512) {
        int dd = idx >> 7, c = idx & 127;
        float a = stg[dd * 132 + c];
        float cv = Cb[(size_t)dd * LC_ + c];
        ob[(size_t)dd * LC_ + c]         = cv;
        ob[(size_t)(128 + dd) * LC_ + c] = a;
        ob[(size_t)(256 + dd) * LC_ + c] = cv * a;
    }
    __syncthreads();
    // ---- accT -> section 3
    #pragma unroll
    for (int mi = 0; mi < 2; mi++) {
        int m0 = m0w + mi * 16 + r;
        float rza = rzs[m0], rzb = rzs[m0 + 8];
        #pragma unroll
        for (int nj = 0; nj < 4; nj++) {
            int n0 = n0w + nj * 8 + cp;
            stg[n0 * 132 + m0]           = accT[mi][nj][0] * rza;
            stg[(n0 + 1) * 132 + m0]     = accT[mi][nj][1] * rza;
            stg[n0 * 132 + m0 + 8]       = accT[mi][nj][2] * rzb;
            stg[(n0 + 1) * 132 + m0 + 8] = accT[mi][nj][3] * rzb;
        }
    }
    __syncthreads();
    for (int idx = tid; idx < 128 * 128; idx += 512) {
        int dd = idx >> 7, c = idx & 127;
        float bm = stg[dd * 132 + c];
        float cv = Cb[(size_t)dd * LC_ + c];
        ob[(size_t)(384 + dd) * LC_ + c] = cv * bm;
    }
}

// =====================================================================
extern "C" void kernel_launch(void* const* d_in, const int* in_sizes, int n_in,
                              void* d_out, int out_size) {
    const float* C     = (const float*)d_in[0];
    const float* Q     = (const float*)d_in[1];
    const int*   Cmask = (const int*)  d_in[2];
    const int*   Qmask = (const int*)  d_in[3];
    const float* w_c   = (const float*)d_in[4];
    const float* w_q   = (const float*)d_in[5];
    const float* w_mul = (const float*)d_in[6];
    const float* bias  = (const float*)d_in[7];
    float* out = (float*)d_out;

    cudaFuncSetAttribute(k_S,  cudaFuncAttributeMaxDynamicSharedMemorySize, KS_DYN);
    cudaFuncSetAttribute(k_T,  cudaFuncAttributeMaxDynamicSharedMemorySize, KT_DYN);
    cudaFuncSetAttribute(k_AB, cudaFuncAttributeMaxDynamicSharedMemorySize, KA_DYN);

    k_cvtC<<<dim3(16, 32), 256>>>(C, Cmask, w_mul, w_c, bias);
    k_cvtQ<<<32, 512>>>(Q, w_q);
    k_S<<<dim3(4, 16, 32), 256, KS_DYN>>>(Qmask, Cmask);
    k_T<<<dim3(4, 32), 512, KT_DYN>>>();
    k_AB<<<dim3(16, 32), 512, KA_DYN>>>(C, out);
}

// round 15
// speedup vs baseline: 1.5267x; 1.0002x over previous
#include <cuda_runtime.h>
#include <cuda_bf16.h>
#include <cuda_fp16.h>
#include <cstdint>

#define B_   32
#define D_   128
#define LC_  2048
#define LQ_  512

typedef unsigned int u32;

// ---------------- scratch planes ----------------
__device__ u32 g_E[(size_t)B_ * LC_ * LQ_ / 2];        // E'' fp16 single plane
__device__ u32 g_Cwhi[(size_t)B_ * D_ * LC_ / 2];      // C*w_mul bf16 2L (k_S)
__device__ u32 g_Cwlo[(size_t)B_ * D_ * LC_ / 2];
__device__ u32 g_Cfhi[(size_t)B_ * D_ * LC_ / 2];      // C' = C*cmask*16*exp(s0), fp16 2L (k_T)
__device__ u32 g_Cflo[(size_t)B_ * D_ * LC_ / 2];
__device__ u32 g_Qhi[(size_t)B_ * D_ * LQ_ / 2];       // Q bf16 2L (k_S)
__device__ u32 g_Qlo[(size_t)B_ * D_ * LQ_ / 2];
__device__ u32 g_Qfhi[(size_t)B_ * D_ * LQ_ / 2];      // Q fp16 2L (k_AB)
__device__ u32 g_Qflo[(size_t)B_ * D_ * LQ_ / 2];
__device__ u32 g_T[(size_t)B_ * LQ_ * D_ / 2];         // T fp16 single plane
__device__ float g_s0[B_ * LC_];
__device__ float g_s1[B_ * LQ_];
__device__ float g_Z1p[B_ * LC_ * 4];
__device__ float g_Z2p[B_ * LQ_ * 16];

// ---------------- helpers ----------------
__device__ __forceinline__ u32 s2u(const void* p) {
    u32 a; asm("{ .reg .u64 t; cvta.to.shared.u64 t, %1; cvt.u32.u64 %0, t; }" : "=r"(a) : "l"(p));
    return a;
}
#define SWZ(x) ((u32)(x) ^ ((((u32)(x)) >> 3) & 0x70))

__device__ __forceinline__ void cpa16(u32 dst, const void* src) {
    asm volatile("cp.async.cg.shared.global [%0], [%1], 16;" :: "r"(dst), "l"(src));
}
#define CP_COMMIT() asm volatile("cp.async.commit_group;")
#define CP_WAIT0()  asm volatile("cp.async.wait_group 0;")
#define CP_WAIT1()  asm volatile("cp.async.wait_group 1;")

__device__ __forceinline__ void splt(float v, u32 &hi, u32 &lo) {     // bf16 2-limb
    __nv_bfloat16 h = __float2bfloat16(v);
    __nv_bfloat16 l = __float2bfloat16(v - __bfloat162float(h));
    hi = (u32)__bfloat16_as_ushort(h);
    lo = (u32)__bfloat16_as_ushort(l);
}
__device__ __forceinline__ void splt16(float v, u32 &hi, u32 &lo) {   // fp16 2-limb
    __half h = __float2half(v);
    __half l = __float2half(v - __half2float(h));
    hi = (u32)__half_as_ushort(h);
    lo = (u32)__half_as_ushort(l);
}

__device__ __forceinline__ void ldsm4(u32 addr, u32 r[4]) {
    asm volatile("ldmatrix.sync.aligned.m8n8.x4.shared.b16 {%0,%1,%2,%3}, [%4];"
                 : "=r"(r[0]), "=r"(r[1]), "=r"(r[2]), "=r"(r[3]) : "r"(addr));
}
__device__ __forceinline__ void ldsm4t(u32 addr, u32 r[4]) {
    asm volatile("ldmatrix.sync.aligned.m8n8.x4.trans.shared.b16 {%0,%1,%2,%3}, [%4];"
                 : "=r"(r[0]), "=r"(r[1]), "=r"(r[2]), "=r"(r[3]) : "r"(addr));
}
template<int F16>
__device__ __forceinline__ void mmaop(float d[4], const u32 a[4], u32 b0, u32 b1) {
    if (F16)
        asm volatile("mma.sync.aligned.m16n8k16.row.col.f32.f16.f16.f32 "
                     "{%0,%1,%2,%3}, {%4,%5,%6,%7}, {%8,%9}, {%0,%1,%2,%3};"
                     : "+f"(d[0]), "+f"(d[1]), "+f"(d[2]), "+f"(d[3])
                     : "r"(a[0]), "r"(a[1]), "r"(a[2]), "r"(a[3]), "r"(b0), "r"(b1));
    else
        asm volatile("mma.sync.aligned.m16n8k16.row.col.f32.bf16.bf16.f32 "
                     "{%0,%1,%2,%3}, {%4,%5,%6,%7}, {%8,%9}, {%0,%1,%2,%3};"
                     : "+f"(d[0]), "+f"(d[1]), "+f"(d[2]), "+f"(d[3])
                     : "r"(a[0]), "r"(a[1]), "r"(a[2]), "r"(a[3]), "r"(b0), "r"(b1));
}
__device__ __forceinline__ uint4 lds128(u32 a) {
    uint4 v;
    asm volatile("ld.shared.v4.b32 {%0,%1,%2,%3}, [%4];"
                 : "=r"(v.x), "=r"(v.y), "=r"(v.z), "=r"(v.w) : "r"(a));
    return v;
}
__device__ __forceinline__ void sts32(u32 a, u32 v) { asm volatile("st.shared.b32 [%0], %1;" :: "r"(a), "r"(v)); }

// ---------------- chunk copies (L = limb count) ----------------
template<int NT, int L, typename H>
__device__ __forceinline__ void cpyT64(u32 dstBase, const H* srcHi, const H* srcLo,
                                       size_t rowStride, int tid) {
    #pragma unroll
    for (int t = 0; t < (1024 * L) / NT; t++) {
        int u = tid + t * NT;
        int limb = u >> 10, rem = u & 1023;
        int row = rem >> 4, ucol = rem & 15;
        const H* src = (limb ? srcLo : srcHi) + (size_t)row * rowStride + ucol * 8;
        u32 dst = dstBase + limb * 16384 + (ucol >> 3) * 8192 + SWZ(row * 128 + (ucol & 7) * 16);
        cpa16(dst, src);
    }
}
template<int NT, int L, typename H>
__device__ __forceinline__ void cpyT32(u32 dstBase, const H* srcHi, const H* srcLo,
                                       size_t rowStride, int tid) {
    #pragma unroll
    for (int t = 0; t < (512 * L) / NT; t++) {
        int u = tid + t * NT;
        int limb = u >> 9, rem = u & 511;
        int row = rem >> 4, ucol = rem & 15;
        const H* src = (limb ? srcLo : srcHi) + (size_t)row * rowStride + ucol * 8;
        u32 dst = dstBase + limb * 8192 + (ucol >> 3) * 4096 + SWZ(row * 128 + (ucol & 7) * 16);
        cpa16(dst, src);
    }
}
template<int NT, int L, typename H>
__device__ __forceinline__ void cpyN128(u32 dstBase, const H* srcHi, const H* srcLo,
                                        size_t rowStride, int tid) {
    #pragma unroll
    for (int t = 0; t < (1024 * L) / NT; t++) {
        int u = tid + t * NT;
        int limb = u >> 10, rem = u & 1023;
        int row = rem >> 3, ucol = rem & 7;
        const H* src = (limb ? srcLo : srcHi) + (size_t)row * rowStride + ucol * 8;
        u32 dst = dstBase + limb * 16384 + SWZ(row * 128 + ucol * 16);
        cpa16(dst, src);
    }
}

// ---------------- warp MMA over one chunk ----------------------------------
template<int MI, int AT, int BT, int KSTEPS, int SUB, int AL, int BL, int F16>
__device__ __forceinline__ void mma_chunk(float acc[MI][4][4], u32 Ab, u32 Bb,
                                          int m0w, int n0w, int lane) {
    const int LO = 2 * SUB;
    #pragma unroll
    for (int ks = 0; ks < KSTEPS; ks++) {
        int k0 = ks * 16;
        u32 ah[MI][4], al[MI][4];
        #pragma unroll
        for (int mi = 0; mi < MI; mi++) {
            int m0 = m0w + mi * 16;
            u32 ad;
            if (AT) {
                int r = k0 + (lane & 7) + ((lane & 16) ? 8 : 0);
                int c = m0 + ((lane & 8) ? 8 : 0);
                ad = Ab + ((u32)(c >> 6)) * SUB + SWZ(r * 128 + (c & 63) * 2);
                ldsm4t(ad, ah[mi]); if (AL == 2) ldsm4t(ad + LO, al[mi]);
            } else {
                int r = m0 + (lane & 15);
                int c = k0 + ((lane >> 4) << 3);
                ad = Ab + SWZ(r * 128 + c * 2);
                ldsm4(ad, ah[mi]); if (AL == 2) ldsm4(ad + LO, al[mi]);
            }
        }
        u32 bh[4][2], bl[4][2];
        #pragma unroll
        for (int nj2 = 0; nj2 < 2; nj2++) {
            int n0 = n0w + nj2 * 16;
            u32 bd;
            u32 t[4], tl[4];
            if (BT) {
                int r = k0 + (lane & 7) + ((lane & 8) ? 8 : 0);
                int c = n0 + ((lane & 16) ? 8 : 0);
                bd = Bb + ((u32)(c >> 6)) * SUB + SWZ(r * 128 + (c & 63) * 2);
                ldsm4t(bd, t); if (BL == 2) ldsm4t(bd + LO, tl);
            } else {
                int r = n0 + (lane & 7) + ((lane & 16) ? 8 : 0);
                int c = k0 + ((lane & 8) ? 8 : 0);
                bd = Bb + SWZ(r * 128 + c * 2);
                ldsm4(bd, t); if (BL == 2) ldsm4(bd + LO, tl);
            }
            bh[nj2 * 2][0] = t[0];  bh[nj2 * 2][1] = t[1];
            bh[nj2 * 2 + 1][0] = t[2]; bh[nj2 * 2 + 1][1] = t[3];
            if (BL == 2) {
                bl[nj2 * 2][0] = tl[0]; bl[nj2 * 2][1] = tl[1];
                bl[nj2 * 2 + 1][0] = tl[2]; bl[nj2 * 2 + 1][1] = tl[3];
            }
        }
        #pragma unroll
        for (int mi = 0; mi < MI; mi++)
            #pragma unroll
            for (int nj = 0; nj < 4; nj++) {
                mmaop<F16>(acc[mi][nj], ah[mi], bh[nj][0], bh[nj][1]);
                if (BL == 2) mmaop<F16>(acc[mi][nj], ah[mi], bl[nj][0], bl[nj][1]);
                if (AL == 2) mmaop<F16>(acc[mi][nj], al[mi], bh[nj][0], bh[nj][1]);
            }
    }
}

// ---------------- dual-B warp MMA for k_AB: E 1L, Q 2L, T 1L (all fp16) ----
__device__ __forceinline__ void mma_chunk_dual(float accQ[2][4][4], float accT[2][4][4],
                                               u32 Ab, u32 Bq, u32 Bt,
                                               int m0w, int n0w, int lane) {
    #pragma unroll
    for (int ks = 0; ks < 4; ks++) {
        int k0 = ks * 16;
        u32 ah[2][4];
        #pragma unroll
        for (int mi = 0; mi < 2; mi++) {
            int m0 = m0w + mi * 16;
            int r = m0 + (lane & 15);
            int c = k0 + ((lane >> 4) << 3);
            ldsm4(Ab + SWZ(r * 128 + c * 2), ah[mi]);
        }
        // --- Q: natural 2-limb ---
        {
            u32 bh[4][2], bl[4][2];
            #pragma unroll
            for (int nj2 = 0; nj2 < 2; nj2++) {
                int n0 = n0w + nj2 * 16;
                int r = n0 + (lane & 7) + ((lane & 16) ? 8 : 0);
                int c = k0 + ((lane & 8) ? 8 : 0);
                u32 bd = Bq + SWZ(r * 128 + c * 2);
                u32 t[4], tl[4];
                ldsm4(bd, t); ldsm4(bd + 16384, tl);
                bh[nj2 * 2][0] = t[0];  bh[nj2 * 2][1] = t[1];
                bh[nj2 * 2 + 1][0] = t[2]; bh[nj2 * 2 + 1][1] = t[3];
                bl[nj2 * 2][0] = tl[0]; bl[nj2 * 2][1] = tl[1];
                bl[nj2 * 2 + 1][0] = tl[2]; bl[nj2 * 2 + 1][1] = tl[3];
            }
            #pragma unroll
            for (int mi = 0; mi < 2; mi++)
                #pragma unroll
                for (int nj = 0; nj < 4; nj++) {
                    mmaop<1>(accQ[mi][nj], ah[mi], bh[nj][0], bh[nj][1]);
                    mmaop<1>(accQ[mi][nj], ah[mi], bl[nj][0], bl[nj][1]);
                }
        }
        // --- T: k-major single-limb (SUB=8192) ---
        {
            u32 bh[4][2];
            #pragma unroll
            for (int nj2 = 0; nj2 < 2; nj2++) {
                int n0 = n0w + nj2 * 16;
                int r = k0 + (lane & 7) + ((lane & 8) ? 8 : 0);
                int c = n0 + ((lane & 16) ? 8 : 0);
                u32 bd = Bt + ((u32)(c >> 6)) * 8192 + SWZ(r * 128 + (c & 63) * 2);
                u32 t[4];
                ldsm4t(bd, t);
                bh[nj2 * 2][0] = t[0];  bh[nj2 * 2][1] = t[1];
                bh[nj2 * 2 + 1][0] = t[2]; bh[nj2 * 2 + 1][1] = t[3];
            }
            #pragma unroll
            for (int mi = 0; mi < 2; mi++)
                #pragma unroll
                for (int nj = 0; nj < 4; nj++)
                    mmaop<1>(accT[mi][nj], ah[mi], bh[nj][0], bh[nj][1]);
        }
    }
}

// =====================================================================
// k_cvtC: Cw planes + s0; C' planes; AND out section 0 (out[b][0:128] = C)
// =====================================================================
__global__ void __launch_bounds__(256) k_cvtC(const float* __restrict__ C,
                                              const int* __restrict__ Cmask,
                                              const float* __restrict__ w_mul,
                                              const float* __restrict__ w_c,
                                              const float* __restrict__ bias,
                                              float* __restrict__ out) {
    __shared__ float wc[128], wm[128], zb[512], s0s[128];
    int tid = threadIdx.x;
    int b = blockIdx.y, cB = blockIdx.x * 128;
    if (tid < 128) { wc[tid] = w_c[tid]; wm[tid] = w_mul[tid]; }
    __syncthreads();
    int cp = tid & 63, dq = tid >> 6;
    int c0 = cB + 2 * cp;
    int m0 = Cmask[b * LC_ + c0], m1 = Cmask[b * LC_ + c0 + 1];
    float s0e = 0.f, s0o = 0.f;
    float2 v[32];
    float* ob0 = out + (size_t)b * 4 * D_ * LC_;
    #pragma unroll
    for (int i = 0; i < 32; i++) {
        int d = dq * 32 + i;
        size_t gi = ((size_t)(b * D_ + d)) * LC_ + c0;
        v[i] = *(const float2*)(C + gi);
        s0e += v[i].x * wc[d]; s0o += v[i].y * wc[d];
        u32 h0, l0, h1, l1;
        splt(v[i].x * wm[d], h0, l0); splt(v[i].y * wm[d], h1, l1);
        g_Cwhi[gi >> 1] = h0 | (h1 << 16);
        g_Cwlo[gi >> 1] = l0 | (l1 << 16);
        *(float2*)(ob0 + (size_t)d * LC_ + c0) = v[i];   // section 0: out = C
    }
    zb[dq * 128 + 2 * cp] = s0e;
    zb[dq * 128 + 2 * cp + 1] = s0o;
    __syncthreads();
    if (tid < 128) {
        float s0 = zb[tid] + zb[128 + tid] + zb[256 + tid] + zb[384 + tid] + bias[0];
        g_s0[b * LC_ + cB + tid] = s0;
        s0s[tid] = s0;
    }
    __syncthreads();
    float Ma0 = m0 ? 16.f * __expf(s0s[2 * cp])     : 0.f;
    float Ma1 = m1 ? 16.f * __expf(s0s[2 * cp + 1]) : 0.f;
    #pragma unroll
    for (int i = 0; i < 32; i++) {
        int d = dq * 32 + i;
        size_t gi = ((size_t)(b * D_ + d)) * LC_ + c0;
        u32 h0, l0, h1, l1;
        splt16(v[i].x * Ma0, h0, l0); splt16(v[i].y * Ma1, h1, l1);
        g_Cfhi[gi >> 1] = h0 | (h1 << 16);
        g_Cflo[gi >> 1] = l0 | (l1 << 16);
    }
}

// =====================================================================
// k_cvtQ: Q -> bf16 2L (k_S) + fp16 2L (k_AB), fused s1
// =====================================================================
__global__ void __launch_bounds__(512) k_cvtQ(const float* __restrict__ Q,
                                              const float* __restrict__ w_q) {
    __shared__ float wq[128], zb[1024];
    int tid = threadIdx.x;
    int b = blockIdx.x;
    if (tid < 128) wq[tid] = w_q[tid];
    __syncthreads();
    int qp = tid & 255, dh = tid >> 8;
    int q0 = 2 * qp;
    float s1e = 0.f, s1o = 0.f;
    #pragma unroll 4
    for (int i = 0; i < 64; i++) {
        int d = dh * 64 + i;
        size_t gi = ((size_t)(b * D_ + d)) * LQ_ + q0;
        float2 v = *(const float2*)(Q + gi);
        s1e += v.x * wq[d]; s1o += v.y * wq[d];
        u32 h0, l0, h1, l1;
        splt(v.x, h0, l0); splt(v.y, h1, l1);
        g_Qhi[gi >> 1] = h0 | (h1 << 16);
        g_Qlo[gi >> 1] = l0 | (l1 << 16);
        splt16(v.x, h0, l0); splt16(v.y, h1, l1);
        g_Qfhi[gi >> 1] = h0 | (h1 << 16);
        g_Qflo[gi >> 1] = l0 | (l1 << 16);
    }
    zb[dh * 512 + q0]     = s1e;
    zb[dh * 512 + q0 + 1] = s1o;
    __syncthreads();
    g_s1[b * LQ_ + tid] = zb[tid] + zb[512 + tid];
}

// =====================================================================
// k_S: E'' = qmask*exp(s2+s1)/16 (fp16, 1 plane); Z1/Z2 partials.
// =====================================================================
#define KS_S0 0
#define KS_S1 512
#define KS_QM 1024
#define KS_CM 1536
#define KS_ZS 2048
#define KS_ZC 4096
#define KS_BUF 8192
#define KS_DYN (8192 + 3 * 32768)

__global__ void __launch_bounds__(256, 2) k_S(const int* __restrict__ Qmask,
                                              const int* __restrict__ Cmask) {
    extern __shared__ char sm[];
    u32 sb = s2u(sm);
    int tid = threadIdx.x, lane = tid & 31, wid = tid >> 5;
    int b = blockIdx.z, cB = blockIdx.y * 128, qB = blockIdx.x * 128, qt = blockIdx.x;
    float* s0f = (float*)(sm + KS_S0);
    float* s1f = (float*)(sm + KS_S1);
    int*   qmi = (int*)(sm + KS_QM);
    float* cmk = (float*)(sm + KS_CM);
    float* zs  = (float*)(sm + KS_ZS);
    float* zc  = (float*)(sm + KS_ZC);
    if (tid < 128) {
        s0f[tid] = g_s0[b * LC_ + cB + tid];
        s1f[tid] = g_s1[b * LQ_ + qB + tid];
        qmi[tid] = Qmask[b * LQ_ + qB + tid];
        cmk[tid] = (float)Cmask[b * LC_ + cB + tid];
    }

    const __nv_bfloat16* CwH = (const __nv_bfloat16*)g_Cwhi;
    const __nv_bfloat16* CwL = (const __nv_bfloat16*)g_Cwlo;
    const __nv_bfloat16* QH  = (const __nv_bfloat16*)g_Qhi;
    const __nv_bfloat16* QL  = (const __nv_bfloat16*)g_Qlo;
    size_t Ca = (size_t)(b * D_) * LC_ + cB;
    size_t Qa = (size_t)(b * D_) * LQ_ + qB;

    #pragma unroll
    for (int pc = 0; pc < 2; pc++) {
        u32 st = sb + KS_BUF + pc * 32768;
        cpyT32<256, 2>(st,         CwH + Ca + (size_t)(pc * 32) * LC_, CwL + Ca + (size_t)(pc * 32) * LC_, LC_, tid);
        cpyT32<256, 2>(st + 16384, QH  + Qa + (size_t)(pc * 32) * LQ_, QL  + Qa + (size_t)(pc * 32) * LQ_, LQ_, tid);
        CP_COMMIT();
    }

    int wm = wid >> 2, wn = wid & 3;
    int m0w = wm * 64, n0w = wn * 32;
    float acc[4][4][4] = {};
    #pragma unroll
    for (int ci = 0; ci < 4; ci++) {
        if (ci < 3) CP_WAIT1(); else CP_WAIT0();
        __syncthreads();
        if (ci < 2) {
            int k0 = (ci + 2) * 32;
            u32 st = sb + KS_BUF + ((ci + 2) % 3) * 32768;
            cpyT32<256, 2>(st,         CwH + Ca + (size_t)k0 * LC_, CwL + Ca + (size_t)k0 * LC_, LC_, tid);
            cpyT32<256, 2>(st + 16384, QH  + Qa + (size_t)k0 * LQ_, QL  + Qa + (size_t)k0 * LQ_, LQ_, tid);
            CP_COMMIT();
        }
        u32 bb = sb + KS_BUF + (ci % 3) * 32768;
        mma_chunk<4, 1, 1, 2, 4096, 2, 2, 0>(acc, bb, bb + 16384, m0w, n0w, lane);
    }
    __syncthreads();

    int r = lane >> 2, cp = (lane & 3) * 2;
    float zrow[8] = {}, zcol[8] = {};
    u32 stg = sb + KS_BUF;
    #pragma unroll
    for (int mi = 0; mi < 4; mi++) {
        int m0 = m0w + mi * 16 + r;
        float cmaM = cmk[m0]     * 16.f * __expf(s0f[m0]);
        float cmbM = cmk[m0 + 8] * 16.f * __expf(s0f[m0 + 8]);
        #pragma unroll
        for (int nj = 0; nj < 4; nj++) {
            int q0 = n0w + nj * 8 + cp;
            float s1a = s1f[q0], s1b = s1f[q0 + 1];
            int qa = qmi[q0], qb = qmi[q0 + 1];
            float e00 = qa ? __expf(acc[mi][nj][0] + s1a) * 0.0625f : 0.f;
            float e01 = qb ? __expf(acc[mi][nj][1] + s1b) * 0.0625f : 0.f;
            float e10 = qa ? __expf(acc[mi][nj][2] + s1a) * 0.0625f : 0.f;
            float e11 = qb ? __expf(acc[mi][nj][3] + s1b) * 0.0625f : 0.f;
            zrow[mi * 2]     += e00 + e01;
            zrow[mi * 2 + 1] += e10 + e11;
            zcol[nj * 2]     += cmaM * e00 + cmbM * e10;
            zcol[nj * 2 + 1] += cmaM * e01 + cmbM * e11;
            u32 h00 = (u32)__half_as_ushort(__float2half(e00));
            u32 h01 = (u32)__half_as_ushort(__float2half(e01));
            u32 h10 = (u32)__half_as_ushort(__float2half(e10));
            u32 h11 = (u32)__half_as_ushort(__float2half(e11));
            sts32(stg + m0 * 272 + q0 * 2,       h00 | (h01 << 16));
            sts32(stg + (m0 + 8) * 272 + q0 * 2, h10 | (h11 << 16));
        }
    }
    #pragma unroll
    for (int h = 0; h < 8; h++) {
        float v = zrow[h];
        v += __shfl_xor_sync(0xffffffffu, v, 1);
        v += __shfl_xor_sync(0xffffffffu, v, 2);
        if ((lane & 3) == 0) {
            int m = m0w + (h >> 1) * 16 + ((h & 1) ? 8 : 0) + r;
            zs[m * 4 + wn] = v;
        }
    }
    #pragma unroll
    for (int j = 0; j < 8; j++) {
        float v = zcol[j];
        v += __shfl_xor_sync(0xffffffffu, v, 4);
        v += __shfl_xor_sync(0xffffffffu, v, 8);
        v += __shfl_xor_sync(0xffffffffu, v, 16);
        zcol[j] = v;
    }
    if (lane < 4) {
        #pragma unroll
        for (int nj = 0; nj < 4; nj++) {
            zc[wm * 128 + n0w + nj * 8 + lane * 2]     = zcol[nj * 2];
            zc[wm * 128 + n0w + nj * 8 + lane * 2 + 1] = zcol[nj * 2 + 1];
        }
    }
    __syncthreads();
    #pragma unroll
    for (int it = 0; it < 8; it++) {
        int idx = tid + it * 256;
        int chunk = idx & 15, c = idx >> 4;
        uint4 v = lds128(stg + c * 272 + chunk * 16);
        ((uint4*)g_E)[((((size_t)(b * LC_ + cB + c)) * LQ_ + qB) >> 3) + chunk] = v;
    }
    if (tid < 128) {
        g_Z1p[((size_t)b * LC_ + cB + tid) * 4 + qt] =
            zs[tid * 4] + zs[tid * 4 + 1] + zs[tid * 4 + 2] + zs[tid * 4 + 3];
        g_Z2p[((size_t)b * LQ_ + qB + tid) * 16 + blockIdx.y] = zc[tid] + zc[128 + tid];
    }
}

// =====================================================================
// k_T: T[q][d] = rZ2[q] * sum_c E''[c,q]*C'[d,c]; store fp16 single plane.
// =====================================================================
#define KT_RZ 0
#define KT_BUF 1024
#define KT_STAGE 49152
#define KT_DYN (1024 + 3 * KT_STAGE)

__global__ void __launch_bounds__(512, 1) k_T() {
    extern __shared__ char sm[];
    u32 sb = s2u(sm);
    int tid = threadIdx.x, lane = tid & 31, wid = tid >> 5;
    int b = blockIdx.y, qB = blockIdx.x * 128;
    float* rzs = (float*)(sm + KT_RZ);
    if (tid < 128) {
        const float* p = &g_Z2p[((size_t)b * LQ_ + qB + tid) * 16];
        float s = 0.f;
        #pragma unroll
        for (int t = 0; t < 16; t++) s += p[t];
        rzs[tid] = 1.f / fmaxf(s, 1e-30f);
    }
    const __half* EP = (const __half*)g_E;
    const __half* CH = (const __half*)g_Cfhi;
    const __half* CL = (const __half*)g_Cflo;
    size_t Eoff = (size_t)(b * LC_) * LQ_ + qB;
    size_t Coff = (size_t)(b * D_) * LC_;

    #pragma unroll
    for (int pc = 0; pc < 2; pc++) {
        u32 st = sb + KT_BUF + pc * KT_STAGE;
        cpyT64<512, 1>(st,          EP + Eoff + (size_t)(pc * 64) * LQ_, EP, LQ_, tid);
        cpyN128<512, 2>(st + 16384, CH + Coff + pc * 64, CL + Coff + pc * 64, LC_, tid);
        CP_COMMIT();
    }

    int wm = wid >> 2, wn = wid & 3;
    int m0w = wm * 32, n0w = wn * 32;
    float acc[2][4][4] = {};
    for (int ci = 0; ci < 32; ci++) {
        if (ci < 31) CP_WAIT1(); else CP_WAIT0();
        __syncthreads();
        if (ci < 30) {
            int c0 = (ci + 2) * 64;
            u32 st = sb + KT_BUF + ((ci + 2) % 3) * KT_STAGE;
            cpyT64<512, 1>(st,          EP + Eoff + (size_t)c0 * LQ_, EP, LQ_, tid);
            cpyN128<512, 2>(st + 16384, CH + Coff + c0, CL + Coff + c0, LC_, tid);
            CP_COMMIT();
        }
        u32 bb = sb + KT_BUF + (ci % 3) * KT_STAGE;
        mma_chunk<2, 1, 0, 4, 8192, 1, 2, 1>(acc, bb, bb + 16384, m0w, n0w, lane);
    }

    int r = lane >> 2, cp = (lane & 3) * 2;
    #pragma unroll
    for (int mi = 0; mi < 2; mi++) {
        int q0 = m0w + mi * 16 + r;
        float rza = rzs[q0], rzb = rzs[q0 + 8];
        #pragma unroll
        for (int nj = 0; nj < 4; nj++) {
            int d0 = n0w + nj * 8 + cp;
            size_t i0 = ((size_t)(b * LQ_ + qB + q0) * D_ + d0) >> 1;
            size_t i1 = ((size_t)(b * LQ_ + qB + q0 + 8) * D_ + d0) >> 1;
            u32 h0 = (u32)__half_as_ushort(__float2half(acc[mi][nj][0] * rza));
            u32 h1 = (u32)__half_as_ushort(__float2half(acc[mi][nj][1] * rza));
            g_T[i0] = h0 | (h1 << 16);
            h0 = (u32)__half_as_ushort(__float2half(acc[mi][nj][2] * rzb));
            h1 = (u32)__half_as_ushort(__float2half(acc[mi][nj][3] * rzb));
            g_T[i1] = h0 | (h1 << 16);
        }
    }
}

// =====================================================================
// k_AB: accQ = E''@Qf (2L), accT = E''@T (1L) in one K sweep.
//   Stage 64K x3. Fused epilogue: both acc tiles staged at once, one
//   write loop for sections 1,2,3 (section 0 written by k_cvtC).
// =====================================================================
#define KA_RZ 0
#define KA_BUF 1024
#define KA_STAGE 65536
#define KA_DYN (1024 + 3 * KA_STAGE)

__global__ void __launch_bounds__(512, 1) k_AB(const float* __restrict__ C,
                                               float* __restrict__ out) {
    extern __shared__ char sm[];
    u32 sb = s2u(sm);
    int tid = threadIdx.x, lane = tid & 31, wid = tid >> 5;
    int b = blockIdx.y, cB = blockIdx.x * 128;
    float* rzs = (float*)(sm + KA_RZ);
    if (tid < 128) {
        const float* p = &g_Z1p[((size_t)b * LC_ + cB + tid) * 4];
        rzs[tid] = 1.f / (p[0] + p[1] + p[2] + p[3]);
    }
    const __half* EP = (const __half*)g_E;
    const __half* QH = (const __half*)g_Qfhi;
    const __half* QL = (const __half*)g_Qflo;
    const __half* TP = (const __half*)g_T;
    size_t Eoff = ((size_t)b * LC_ + cB) * LQ_;
    size_t Qoff = (size_t)(b * D_) * LQ_;
    size_t Toff = (size_t)(b * LQ_) * D_;
    const float* Cb = C + (size_t)b * D_ * LC_ + cB;
    float* ob = out + (size_t)b * 4 * D_ * LC_ + cB;
    float* stgQ = (float*)(sm + KA_BUF);             // 128*132 f = 67584 B
    float* stgT = stgQ + 128 * 132;                  // next 67584 B (<192K total)
    int wm = wid >> 2, wn = wid & 3;
    int m0w = wm * 32, n0w = wn * 32;
    int r = lane >> 2, cp = (lane & 3) * 2;

    #pragma unroll
    for (int pc = 0; pc < 2; pc++) {
        int q0 = pc * 64;
        u32 st = sb + KA_BUF + pc * KA_STAGE;
        cpyN128<512, 1>(st,         EP + Eoff + q0, EP, LQ_, tid);
        cpyN128<512, 2>(st + 16384, QH + Qoff + q0, QL + Qoff + q0, LQ_, tid);
        cpyT64<512, 1> (st + 49152, TP + Toff + (size_t)q0 * D_, TP, D_, tid);
        CP_COMMIT();
    }

    float accQ[2][4][4] = {}, accT[2][4][4] = {};
    for (int ci = 0; ci < 8; ci++) {
        if (ci < 7) CP_WAIT1(); else CP_WAIT0();
        __syncthreads();
        if (ci < 6) {
            int q0 = (ci + 2) * 64;
            u32 st = sb + KA_BUF + ((ci + 2) % 3) * KA_STAGE;
            cpyN128<512, 1>(st,         EP + Eoff + q0, EP, LQ_, tid);
            cpyN128<512, 2>(st + 16384, QH + Qoff + q0, QL + Qoff + q0, LQ_, tid);
            cpyT64<512, 1> (st + 49152, TP + Toff + (size_t)q0 * D_, TP, D_, tid);
            CP_COMMIT();
        }
        u32 bb = sb + KA_BUF + (ci % 3) * KA_STAGE;
        mma_chunk_dual(accQ, accT, bb, bb + 16384, bb + 49152, m0w, n0w, lane);
    }
    __syncthreads();

    // ---- stage BOTH acc tiles, one barrier, one fused write loop ----
    #pragma unroll
    for (int mi = 0; mi < 2; mi++) {
        int m0 = m0w + mi * 16 + r;
        float rza = rzs[m0], rzb = rzs[m0 + 8];
        #pragma unroll
        for (int nj = 0; nj < 4; nj++) {
            int n0 = n0w + nj * 8 + cp;
            stgQ[n0 * 132 + m0]           = accQ[mi][nj][0] * rza;
            stgQ[(n0 + 1) * 132 + m0]     = accQ[mi][nj][1] * rza;
            stgQ[n0 * 132 + m0 + 8]       = accQ[mi][nj][2] * rzb;
            stgQ[(n0 + 1) * 132 + m0 + 8] = accQ[mi][nj][3] * rzb;
            stgT[n0 * 132 + m0]           = accT[mi][nj][0] * rza;
            stgT[(n0 + 1) * 132 + m0]     = accT[mi][nj][1] * rza;
            stgT[n0 * 132 + m0 + 8]       = accT[mi][nj][2] * rzb;
            stgT[(n0 + 1) * 132 + m0 + 8] = accT[mi][nj][3] * rzb;
        }
    }
    __syncthreads();
    for (int idx = tid; idx < 128 * 128; idx += 512) {
        int dd = idx >> 7, c = idx & 127;
        float a  = stgQ[dd * 132 + c];
        float bm = stgT[dd * 132 + c];
        float cv = Cb[(size_t)dd * LC_ + c];
        ob[(size_t)(128 + dd) * LC_ + c] = a;
        ob[(size_t)(256 + dd) * LC_ + c] = cv * a;
        ob[(size_t)(384 + dd) * LC_ + c] = cv * bm;
    }
}

// =====================================================================
extern "C" void kernel_launch(void* const* d_in, const int* in_sizes, int n_in,
                              void* d_out, int out_size) {
    const float* C     = (const float*)d_in[0];
    const float* Q     = (const float*)d_in[1];
    const int*   Cmask = (const int*)  d_in[2];
    const int*   Qmask = (const int*)  d_in[3];
    const float* w_c   = (const float*)d_in[4];
    const float* w_q   = (const float*)d_in[5];
    const float* w_mul = (const float*)d_in[6];
    const float* bias  = (const float*)d_in[7];
    float* out = (float*)d_out;

    cudaFuncSetAttribute(k_S,  cudaFuncAttributeMaxDynamicSharedMemorySize, KS_DYN);
    cudaFuncSetAttribute(k_T,  cudaFuncAttributeMaxDynamicSharedMemorySize, KT_DYN);
    cudaFuncSetAttribute(k_AB, cudaFuncAttributeMaxDynamicSharedMemorySize, KA_DYN);

    k_cvtC<<<dim3(16, 32), 256>>>(C, Cmask, w_mul, w_c, bias, out);
    k_cvtQ<<<32, 512>>>(Q, w_q);
    k_S<<<dim3(4, 16, 32), 256, KS_DYN>>>(Qmask, Cmask);
    k_T<<<dim3(4, 32), 512, KT_DYN>>>();
    k_AB<<<dim3(16, 32), 512, KA_DYN>>>(C, out);
}